// round 4
// baseline (speedup 1.0000x reference)
#include <cuda_runtime.h>
#include <cuda_bf16.h>
#include <cstddef>

// Problem constants
#define B_   8
#define T_   32
#define N_   500
#define DP_  200
#define DC_  128
#define H_   4
#define U_   64

// Scratch (device globals: allocation-free rule)
__device__ float g_S[B_*H_*N_*U_];                 // [b][h][n][u]  src proj   (4.1 MB)
__device__ float g_D[B_*H_*N_*U_];                 // [b][h][m][u]  dst proj   (4.1 MB)
__device__ float g_attn[B_*N_*H_*N_];              // [b][n][h][m]             (32 MB)
__device__ float g_msg[B_*H_*N_*T_*U_];            // [b][h][m][t][u]          (131 MB)

// ---------------------------------------------------------------------------
// Kernel A: projections.  GEMM M=4000 (b*500+n), K=200, Ncols=512
//   col c: mat = c>>8 (0=src,1=dst), h=(c>>6)&3, u=c&63
// 128x128x8 double-buffered SIMT SGEMM.
// ---------------------------------------------------------------------------
__global__ __launch_bounds__(256, 2)
void proj_gemm(const float* __restrict__ prev,
               const float* __restrict__ Wsrc,
               const float* __restrict__ Wdst)
{
    const int rowBase = blockIdx.x * 128;
    const int colBase = blockIdx.y * 128;

    __shared__ float As[2][8][132];
    __shared__ float Bs[2][8][128];

    const int tid  = threadIdx.x;
    const int aRow = tid >> 1;
    const int aK   = (tid & 1) * 4;
    const int bK   = tid >> 5;
    const int bCol = (tid & 31) * 4;
    const int tx   = tid & 15;
    const int ty   = tid >> 4;

    const int gRow  = rowBase + aRow;
    const bool rowOk = gRow < 4000;
    const float* aPtr = prev + (size_t)gRow * DP_ + aK;

    // B element (k=d, c): base + d*64
    const int cB   = colBase + bCol;
    const int matB = cB >> 8;
    const int hB   = (cB >> 6) & 3;
    const int uB   = cB & 63;
    const float* bPtr = (matB ? Wdst : Wsrc) + hB * (DP_*U_) + bK * U_ + uB;

    const int KSTEPS = DP_ / 8;  // 25

    float4 aReg = rowOk ? *(const float4*)aPtr : make_float4(0,0,0,0);
    float4 bReg = *(const float4*)bPtr;

    As[0][aK+0][aRow] = aReg.x; As[0][aK+1][aRow] = aReg.y;
    As[0][aK+2][aRow] = aReg.z; As[0][aK+3][aRow] = aReg.w;
    *(float4*)&Bs[0][bK][bCol] = bReg;
    __syncthreads();

    float acc[2][2][4][4] = {};

    for (int ks = 0; ks < KSTEPS; ks++) {
        const int cur = ks & 1;
        if (ks + 1 < KSTEPS) {
            aReg = rowOk ? *(const float4*)(aPtr + (ks+1)*8) : make_float4(0,0,0,0);
            bReg = *(const float4*)(bPtr + (ks+1)*8*U_);
        }
        #pragma unroll
        for (int kk = 0; kk < 8; kk++) {
            float ar[2][4], br[2][4];
            *(float4*)ar[0] = *(const float4*)&As[cur][kk][ty*4];
            *(float4*)ar[1] = *(const float4*)&As[cur][kk][ty*4 + 64];
            *(float4*)br[0] = *(const float4*)&Bs[cur][kk][tx*4];
            *(float4*)br[1] = *(const float4*)&Bs[cur][kk][tx*4 + 64];
            #pragma unroll
            for (int rg=0; rg<2; rg++)
              #pragma unroll
              for (int cg=0; cg<2; cg++)
                #pragma unroll
                for (int i=0;i<4;i++)
                  #pragma unroll
                  for (int j=0;j<4;j++)
                    acc[rg][cg][i][j] = fmaf(ar[rg][i], br[cg][j], acc[rg][cg][i][j]);
        }
        if (ks + 1 < KSTEPS) {
            const int nxt = cur ^ 1;
            As[nxt][aK+0][aRow] = aReg.x; As[nxt][aK+1][aRow] = aReg.y;
            As[nxt][aK+2][aRow] = aReg.z; As[nxt][aK+3][aRow] = aReg.w;
            *(float4*)&Bs[nxt][bK][bCol] = bReg;
            __syncthreads();
        }
    }

    #pragma unroll
    for (int rg=0; rg<2; rg++) {
        #pragma unroll
        for (int i=0;i<4;i++) {
            const int r = rowBase + ty*4 + rg*64 + i;
            if (r < 4000) {
                const int b = r / N_;
                const int n = r - b * N_;
                #pragma unroll
                for (int cg=0; cg<2; cg++) {
                    const int c = colBase + tx*4 + cg*64;
                    const int mat = c >> 8;
                    const int h   = (c >> 6) & 3;
                    const int u   = c & 63;
                    float* dst = (mat ? g_D : g_S) + ((size_t)(b*H_ + h)*N_ + n)*U_ + u;
                    float4 v = make_float4(acc[rg][cg][i][0], acc[rg][cg][i][1],
                                           acc[rg][cg][i][2], acc[rg][cg][i][3]);
                    *(float4*)dst = v;
                }
            }
        }
    }
}

// ---------------------------------------------------------------------------
// Kernel B: GATv2 scores + softmax.
// Block = (b,h, 16-row n-tile). Full h_dst tile (500x64, padded to 512 rows,
// stride 65 for conflict-free reads) resident in dynamic smem.
// score[n][m] = sum_u a[u] * lrelu(S[n,u] + D[m,u]),  lrelu(t)=max(t, 0.2t)
// Then per-row softmax over m, write attn[b][n][h][m].
// ---------------------------------------------------------------------------
__global__ __launch_bounds__(256)
void score_softmax_kernel(const float* __restrict__ aVec)
{
    extern __shared__ float sh[];
    float* Dsh = sh;                     // 512*65
    float* Ssh = Dsh + 512*65;           // 16*64
    float* aSh = Ssh + 16*64;            // 64 (+64 pad)
    float* sc  = aSh + 128;              // 16*500

    const int bh = blockIdx.y;           // b*4 + h
    const int b  = bh >> 2;
    const int h  = bh & 3;
    const int nBase = blockIdx.x * 16;
    const int tid = threadIdx.x;

    const float* Dg = g_D + (size_t)bh * N_ * U_;
    const float* Sg = g_S + (size_t)bh * N_ * U_;

    for (int idx = tid; idx < 512*16; idx += 256) {
        const int m = idx >> 4;
        const int u = (idx & 15) * 4;
        float4 v = (m < N_) ? *(const float4*)(Dg + m*U_ + u) : make_float4(0,0,0,0);
        float* dst = &Dsh[m*65 + u];
        dst[0]=v.x; dst[1]=v.y; dst[2]=v.z; dst[3]=v.w;
    }
    for (int idx = tid; idx < 16*16; idx += 256) {
        const int r = idx >> 4;
        const int u = (idx & 15) * 4;
        const int n = nBase + r;
        float4 v = (n < N_) ? *(const float4*)(Sg + n*U_ + u) : make_float4(0,0,0,0);
        float* dst = &Ssh[r*U_ + u];
        dst[0]=v.x; dst[1]=v.y; dst[2]=v.z; dst[3]=v.w;
    }
    if (tid < 64) aSh[tid] = aVec[h*U_ + tid];
    __syncthreads();

    // scoring: thread (tx in [0,64), tyy in [0,4)): rows tyy*4+i, cols tx+64k
    const int tx  = tid & 63;
    const int tyy = tid >> 6;

    float acc[4][8];
    #pragma unroll
    for (int i=0;i<4;i++)
        #pragma unroll
        for (int k=0;k<8;k++) acc[i][k]=0.f;

    for (int u = 0; u < U_; u++) {
        const float au = aSh[u];
        float s[4];
        #pragma unroll
        for (int i=0;i<4;i++) s[i] = Ssh[(tyy*4+i)*U_ + u];
        #pragma unroll
        for (int k=0;k<8;k++) {
            const float d = Dsh[(tx + 64*k)*65 + u];
            #pragma unroll
            for (int i=0;i<4;i++) {
                const float t  = s[i] + d;
                const float lr = fmaxf(t, 0.2f * t);
                acc[i][k] = fmaf(au, lr, acc[i][k]);
            }
        }
    }
    #pragma unroll
    for (int i=0;i<4;i++)
        #pragma unroll
        for (int k=0;k<8;k++) {
            const int m = tx + 64*k;
            if (m < N_) sc[(tyy*4+i)*N_ + m] = acc[i][k];
        }
    __syncthreads();

    // softmax: 8 warps x 2 rows
    const int warp = tid >> 5, lane = tid & 31;
    #pragma unroll
    for (int rr = 0; rr < 2; rr++) {
        const int r = warp*2 + rr;
        const int n = nBase + r;
        float mx = -1e30f;
        for (int m = lane; m < N_; m += 32) mx = fmaxf(mx, sc[r*N_+m]);
        #pragma unroll
        for (int o=16;o>0;o>>=1) mx = fmaxf(mx, __shfl_xor_sync(0xffffffffu, mx, o));
        float sum = 0.f;
        for (int m = lane; m < N_; m += 32) {
            const float e = __expf(sc[r*N_+m] - mx);
            sc[r*N_+m] = e;
            sum += e;
        }
        #pragma unroll
        for (int o=16;o>0;o>>=1) sum += __shfl_xor_sync(0xffffffffu, sum, o);
        const float inv = 1.f / sum;
        if (n < N_) {
            float* dst = g_attn + (((size_t)b*N_ + n)*H_ + h)*N_;
            for (int m = lane; m < N_; m += 32) dst[m] = sc[r*N_+m]*inv;
        }
    }
}

// ---------------------------------------------------------------------------
// Kernel C: msg GEMM. M=128000 (r = (b*32+t)*500+m), K=128, Ncols=256 (h,u).
// Output scattered to g_msg[b][h][m][t][u].
// ---------------------------------------------------------------------------
__global__ __launch_bounds__(256, 2)
void msg_gemm(const float* __restrict__ curr,
              const float* __restrict__ Wmsg)
{
    const int rowBase = blockIdx.x * 128;
    const int colBase = blockIdx.y * 128;

    __shared__ float As[2][8][132];
    __shared__ float Bs[2][8][128];

    const int tid  = threadIdx.x;
    const int aRow = tid >> 1;
    const int aK   = (tid & 1) * 4;
    const int bK   = tid >> 5;
    const int bCol = (tid & 31) * 4;
    const int tx   = tid & 15;
    const int ty   = tid >> 4;

    const float* aPtr = curr + (size_t)(rowBase + aRow) * DC_ + aK;

    const int cB = colBase + bCol;
    const int hB = cB >> 6;
    const int uB = cB & 63;
    const float* bPtr = Wmsg + hB * (DC_*U_) + bK * U_ + uB;

    const int KSTEPS = DC_ / 8;  // 16

    float4 aReg = *(const float4*)aPtr;
    float4 bReg = *(const float4*)bPtr;

    As[0][aK+0][aRow] = aReg.x; As[0][aK+1][aRow] = aReg.y;
    As[0][aK+2][aRow] = aReg.z; As[0][aK+3][aRow] = aReg.w;
    *(float4*)&Bs[0][bK][bCol] = bReg;
    __syncthreads();

    float acc[2][2][4][4] = {};

    for (int ks = 0; ks < KSTEPS; ks++) {
        const int cur = ks & 1;
        if (ks + 1 < KSTEPS) {
            aReg = *(const float4*)(aPtr + (ks+1)*8);
            bReg = *(const float4*)(bPtr + (ks+1)*8*U_);
        }
        #pragma unroll
        for (int kk = 0; kk < 8; kk++) {
            float ar[2][4], br[2][4];
            *(float4*)ar[0] = *(const float4*)&As[cur][kk][ty*4];
            *(float4*)ar[1] = *(const float4*)&As[cur][kk][ty*4 + 64];
            *(float4*)br[0] = *(const float4*)&Bs[cur][kk][tx*4];
            *(float4*)br[1] = *(const float4*)&Bs[cur][kk][tx*4 + 64];
            #pragma unroll
            for (int rg=0; rg<2; rg++)
              #pragma unroll
              for (int cg=0; cg<2; cg++)
                #pragma unroll
                for (int i=0;i<4;i++)
                  #pragma unroll
                  for (int j=0;j<4;j++)
                    acc[rg][cg][i][j] = fmaf(ar[rg][i], br[cg][j], acc[rg][cg][i][j]);
        }
        if (ks + 1 < KSTEPS) {
            const int nxt = cur ^ 1;
            As[nxt][aK+0][aRow] = aReg.x; As[nxt][aK+1][aRow] = aReg.y;
            As[nxt][aK+2][aRow] = aReg.z; As[nxt][aK+3][aRow] = aReg.w;
            *(float4*)&Bs[nxt][bK][bCol] = bReg;
            __syncthreads();
        }
    }

    #pragma unroll
    for (int rg=0; rg<2; rg++) {
        #pragma unroll
        for (int i=0;i<4;i++) {
            const int r = rowBase + ty*4 + rg*64 + i;   // always < 128000
            const int b = r / (T_*N_);
            const int rem = r - b*(T_*N_);
            const int t = rem / N_;
            const int m = rem - t*N_;
            #pragma unroll
            for (int cg=0; cg<2; cg++) {
                const int c = colBase + tx*4 + cg*64;
                const int h = c >> 6;
                const int u = c & 63;
                float* dst = g_msg + ((((size_t)(b*H_ + h)*N_ + m)*T_ + t)*U_ + u);
                float4 v = make_float4(acc[rg][cg][i][0], acc[rg][cg][i][1],
                                       acc[rg][cg][i][2], acc[rg][cg][i][3]);
                *(float4*)dst = v;
            }
        }
    }
}

// ---------------------------------------------------------------------------
// Kernel D: mix GEMM per batch b (blockIdx.z):
//   O[n][t*64+u] = sum_{h,m} attn[b][n][h*500+m] * msg[b][h*500+m][t*64+u]
//   out[b][t][n][u] = 0.25 * O[n][t*64+u]
// M=500, Ncols=2048, K=2000.
// ---------------------------------------------------------------------------
__global__ __launch_bounds__(256, 2)
void mix_gemm(float* __restrict__ out)
{
    const int b = blockIdx.z;
    const int rowBase = blockIdx.x * 128;
    const int colBase = blockIdx.y * 128;

    const float* A  = g_attn + (size_t)b * N_ * (H_*N_);       // [500 x 2000]
    const float* Bm = g_msg  + (size_t)b * (H_*N_) * (T_*U_);  // [2000 x 2048]

    __shared__ float As[2][8][132];
    __shared__ float Bs[2][8][128];

    const int tid  = threadIdx.x;
    const int aRow = tid >> 1;
    const int aK   = (tid & 1) * 4;
    const int bK   = tid >> 5;
    const int bCol = (tid & 31) * 4;
    const int tx   = tid & 15;
    const int ty   = tid >> 4;

    const int gRow  = rowBase + aRow;
    const bool rowOk = gRow < N_;
    const float* aPtr = A + (size_t)gRow * (H_*N_) + aK;
    const float* bPtr = Bm + (size_t)bK * (T_*U_) + colBase + bCol;

    const int KSTEPS = (H_*N_) / 8;  // 250

    float4 aReg = rowOk ? *(const float4*)aPtr : make_float4(0,0,0,0);
    float4 bReg = *(const float4*)bPtr;

    As[0][aK+0][aRow] = aReg.x; As[0][aK+1][aRow] = aReg.y;
    As[0][aK+2][aRow] = aReg.z; As[0][aK+3][aRow] = aReg.w;
    *(float4*)&Bs[0][bK][bCol] = bReg;
    __syncthreads();

    float acc[2][2][4][4] = {};

    for (int ks = 0; ks < KSTEPS; ks++) {
        const int cur = ks & 1;
        if (ks + 1 < KSTEPS) {
            aReg = rowOk ? *(const float4*)(aPtr + (ks+1)*8) : make_float4(0,0,0,0);
            bReg = *(const float4*)(bPtr + (size_t)(ks+1)*8*(T_*U_));
        }
        #pragma unroll
        for (int kk = 0; kk < 8; kk++) {
            float ar[2][4], br[2][4];
            *(float4*)ar[0] = *(const float4*)&As[cur][kk][ty*4];
            *(float4*)ar[1] = *(const float4*)&As[cur][kk][ty*4 + 64];
            *(float4*)br[0] = *(const float4*)&Bs[cur][kk][tx*4];
            *(float4*)br[1] = *(const float4*)&Bs[cur][kk][tx*4 + 64];
            #pragma unroll
            for (int rg=0; rg<2; rg++)
              #pragma unroll
              for (int cg=0; cg<2; cg++)
                #pragma unroll
                for (int i=0;i<4;i++)
                  #pragma unroll
                  for (int j=0;j<4;j++)
                    acc[rg][cg][i][j] = fmaf(ar[rg][i], br[cg][j], acc[rg][cg][i][j]);
        }
        if (ks + 1 < KSTEPS) {
            const int nxt = cur ^ 1;
            As[nxt][aK+0][aRow] = aReg.x; As[nxt][aK+1][aRow] = aReg.y;
            As[nxt][aK+2][aRow] = aReg.z; As[nxt][aK+3][aRow] = aReg.w;
            *(float4*)&Bs[nxt][bK][bCol] = bReg;
            __syncthreads();
        }
    }

    #pragma unroll
    for (int rg=0; rg<2; rg++) {
        #pragma unroll
        for (int i=0;i<4;i++) {
            const int n = rowBase + ty*4 + rg*64 + i;
            if (n < N_) {
                #pragma unroll
                for (int cg=0; cg<2; cg++) {
                    const int c = colBase + tx*4 + cg*64;
                    const int t = c >> 6;
                    const int u = c & 63;
                    float4 v = make_float4(acc[rg][cg][i][0]*0.25f, acc[rg][cg][i][1]*0.25f,
                                           acc[rg][cg][i][2]*0.25f, acc[rg][cg][i][3]*0.25f);
                    *(float4*)&out[(((size_t)b*T_ + t)*N_ + n)*U_ + u] = v;
                }
            }
        }
    }
}

// ---------------------------------------------------------------------------
extern "C" void kernel_launch(void* const* d_in, const int* in_sizes, int n_in,
                              void* d_out, int out_size)
{
    const float* prev = (const float*)d_in[0];   // [8,500,200]
    const float* curr = (const float*)d_in[1];   // [8,32,500,128]
    const float* Wsrc = (const float*)d_in[2];   // [4,200,64]
    const float* Wdst = (const float*)d_in[3];   // [4,200,64]
    const float* aV   = (const float*)d_in[4];   // [4,64,1]
    const float* Wmsg = (const float*)d_in[5];   // [4,128,64]
    float* out = (float*)d_out;                  // [8,32,500,64]

    // A: projections  (M=4000, N=512, K=200)
    proj_gemm<<<dim3(32, 4), 256>>>(prev, Wsrc, Wdst);

    // B: scores + softmax
    const size_t shB = (size_t)(512*65 + 16*64 + 128 + 16*500) * sizeof(float);
    cudaFuncSetAttribute(score_softmax_kernel,
                         cudaFuncAttributeMaxDynamicSharedMemorySize, (int)shB);
    score_softmax_kernel<<<dim3(32, 32), 256, shB>>>(aV);

    // C: msg GEMM  (M=128000, N=256, K=128)
    msg_gemm<<<dim3(1000, 2), 256>>>(curr, Wmsg);

    // D: mix GEMM  (per batch: M=500, N=2048, K=2000)
    mix_gemm<<<dim3(4, 16, 8), 256>>>(out);
}

// round 5
// speedup vs baseline: 1.0019x; 1.0019x over previous
#include <cuda_runtime.h>
#include <cuda_bf16.h>
#include <cstddef>

// Problem constants
#define B_   8
#define T_   32
#define N_   500
#define DP_  200
#define DC_  128
#define H_   4
#define U_   64

// Scratch (device globals: allocation-free rule)
__device__ float g_S[B_*H_*N_*U_];                 // [b][h][n][u]  src proj   (4.1 MB)
__device__ float g_D[B_*H_*N_*U_];                 // [b][h][m][u]  dst proj   (4.1 MB)
__device__ float g_attn[B_*N_*H_*N_];              // [b][n][h][m]             (32 MB)
__device__ float g_msg[B_*H_*N_*T_*U_];            // [b][h][m][t][u]          (131 MB)

// ---------------------------------------------------------------------------
// Kernel A: projections.  GEMM M=4000 (b*500+n), K=200, Ncols=512
//   col c: mat = c>>8 (0=src,1=dst), h=(c>>6)&3, u=c&63
// 128x128x8 double-buffered SIMT SGEMM.
// ---------------------------------------------------------------------------
__global__ __launch_bounds__(256, 2)
void proj_gemm(const float* __restrict__ prev,
               const float* __restrict__ Wsrc,
               const float* __restrict__ Wdst)
{
    const int rowBase = blockIdx.x * 128;
    const int colBase = blockIdx.y * 128;

    __shared__ float As[2][8][132];
    __shared__ float Bs[2][8][128];

    const int tid  = threadIdx.x;
    const int aRow = tid >> 1;
    const int aK   = (tid & 1) * 4;
    const int bK   = tid >> 5;
    const int bCol = (tid & 31) * 4;
    const int tx   = tid & 15;
    const int ty   = tid >> 4;

    const int gRow  = rowBase + aRow;
    const bool rowOk = gRow < 4000;
    const float* aPtr = prev + (size_t)gRow * DP_ + aK;

    // B element (k=d, c): base + d*64
    const int cB   = colBase + bCol;
    const int matB = cB >> 8;
    const int hB   = (cB >> 6) & 3;
    const int uB   = cB & 63;
    const float* bPtr = (matB ? Wdst : Wsrc) + hB * (DP_*U_) + bK * U_ + uB;

    const int KSTEPS = DP_ / 8;  // 25

    float4 aReg = rowOk ? *(const float4*)aPtr : make_float4(0,0,0,0);
    float4 bReg = *(const float4*)bPtr;

    As[0][aK+0][aRow] = aReg.x; As[0][aK+1][aRow] = aReg.y;
    As[0][aK+2][aRow] = aReg.z; As[0][aK+3][aRow] = aReg.w;
    *(float4*)&Bs[0][bK][bCol] = bReg;
    __syncthreads();

    float acc[2][2][4][4] = {};

    for (int ks = 0; ks < KSTEPS; ks++) {
        const int cur = ks & 1;
        if (ks + 1 < KSTEPS) {
            aReg = rowOk ? *(const float4*)(aPtr + (ks+1)*8) : make_float4(0,0,0,0);
            bReg = *(const float4*)(bPtr + (ks+1)*8*U_);
        }
        #pragma unroll
        for (int kk = 0; kk < 8; kk++) {
            float ar[2][4], br[2][4];
            *(float4*)ar[0] = *(const float4*)&As[cur][kk][ty*4];
            *(float4*)ar[1] = *(const float4*)&As[cur][kk][ty*4 + 64];
            *(float4*)br[0] = *(const float4*)&Bs[cur][kk][tx*4];
            *(float4*)br[1] = *(const float4*)&Bs[cur][kk][tx*4 + 64];
            #pragma unroll
            for (int rg=0; rg<2; rg++)
              #pragma unroll
              for (int cg=0; cg<2; cg++)
                #pragma unroll
                for (int i=0;i<4;i++)
                  #pragma unroll
                  for (int j=0;j<4;j++)
                    acc[rg][cg][i][j] = fmaf(ar[rg][i], br[cg][j], acc[rg][cg][i][j]);
        }
        if (ks + 1 < KSTEPS) {
            const int nxt = cur ^ 1;
            As[nxt][aK+0][aRow] = aReg.x; As[nxt][aK+1][aRow] = aReg.y;
            As[nxt][aK+2][aRow] = aReg.z; As[nxt][aK+3][aRow] = aReg.w;
            *(float4*)&Bs[nxt][bK][bCol] = bReg;
            __syncthreads();
        }
    }

    #pragma unroll
    for (int rg=0; rg<2; rg++) {
        #pragma unroll
        for (int i=0;i<4;i++) {
            const int r = rowBase + ty*4 + rg*64 + i;
            if (r < 4000) {
                const int b = r / N_;
                const int n = r - b * N_;
                #pragma unroll
                for (int cg=0; cg<2; cg++) {
                    const int c = colBase + tx*4 + cg*64;
                    const int mat = c >> 8;
                    const int h   = (c >> 6) & 3;
                    const int u   = c & 63;
                    float* dst = (mat ? g_D : g_S) + ((size_t)(b*H_ + h)*N_ + n)*U_ + u;
                    float4 v = make_float4(acc[rg][cg][i][0], acc[rg][cg][i][1],
                                           acc[rg][cg][i][2], acc[rg][cg][i][3]);
                    *(float4*)dst = v;
                }
            }
        }
    }
}

// ---------------------------------------------------------------------------
// Kernel B: GATv2 scores + softmax.
// Block = (b,h, 16-row n-tile). Full h_dst tile (500x64, padded to 512 rows,
// stride 65 for conflict-free reads) resident in dynamic smem.
// score[n][m] = sum_u a[u] * lrelu(S[n,u] + D[m,u]),  lrelu(t)=max(t, 0.2t)
// Then per-row softmax over m, write attn[b][n][h][m].
// ---------------------------------------------------------------------------
__global__ __launch_bounds__(256)
void score_softmax_kernel(const float* __restrict__ aVec)
{
    extern __shared__ float sh[];
    float* Dsh = sh;                     // 512*65
    float* Ssh = Dsh + 512*65;           // 16*64
    float* aSh = Ssh + 16*64;            // 64 (+64 pad)
    float* sc  = aSh + 128;              // 16*500

    const int bh = blockIdx.y;           // b*4 + h
    const int b  = bh >> 2;
    const int h  = bh & 3;
    const int nBase = blockIdx.x * 16;
    const int tid = threadIdx.x;

    const float* Dg = g_D + (size_t)bh * N_ * U_;
    const float* Sg = g_S + (size_t)bh * N_ * U_;

    for (int idx = tid; idx < 512*16; idx += 256) {
        const int m = idx >> 4;
        const int u = (idx & 15) * 4;
        float4 v = (m < N_) ? *(const float4*)(Dg + m*U_ + u) : make_float4(0,0,0,0);
        float* dst = &Dsh[m*65 + u];
        dst[0]=v.x; dst[1]=v.y; dst[2]=v.z; dst[3]=v.w;
    }
    for (int idx = tid; idx < 16*16; idx += 256) {
        const int r = idx >> 4;
        const int u = (idx & 15) * 4;
        const int n = nBase + r;
        float4 v = (n < N_) ? *(const float4*)(Sg + n*U_ + u) : make_float4(0,0,0,0);
        float* dst = &Ssh[r*U_ + u];
        dst[0]=v.x; dst[1]=v.y; dst[2]=v.z; dst[3]=v.w;
    }
    if (tid < 64) aSh[tid] = aVec[h*U_ + tid];
    __syncthreads();

    // scoring: thread (tx in [0,64), tyy in [0,4)): rows tyy*4+i, cols tx+64k
    const int tx  = tid & 63;
    const int tyy = tid >> 6;

    float acc[4][8];
    #pragma unroll
    for (int i=0;i<4;i++)
        #pragma unroll
        for (int k=0;k<8;k++) acc[i][k]=0.f;

    for (int u = 0; u < U_; u++) {
        const float au = aSh[u];
        float s[4];
        #pragma unroll
        for (int i=0;i<4;i++) s[i] = Ssh[(tyy*4+i)*U_ + u];
        #pragma unroll
        for (int k=0;k<8;k++) {
            const float d = Dsh[(tx + 64*k)*65 + u];
            #pragma unroll
            for (int i=0;i<4;i++) {
                const float t  = s[i] + d;
                const float lr = fmaxf(t, 0.2f * t);
                acc[i][k] = fmaf(au, lr, acc[i][k]);
            }
        }
    }
    #pragma unroll
    for (int i=0;i<4;i++)
        #pragma unroll
        for (int k=0;k<8;k++) {
            const int m = tx + 64*k;
            if (m < N_) sc[(tyy*4+i)*N_ + m] = acc[i][k];
        }
    __syncthreads();

    // softmax: 8 warps x 2 rows
    const int warp = tid >> 5, lane = tid & 31;
    #pragma unroll
    for (int rr = 0; rr < 2; rr++) {
        const int r = warp*2 + rr;
        const int n = nBase + r;
        float mx = -1e30f;
        for (int m = lane; m < N_; m += 32) mx = fmaxf(mx, sc[r*N_+m]);
        #pragma unroll
        for (int o=16;o>0;o>>=1) mx = fmaxf(mx, __shfl_xor_sync(0xffffffffu, mx, o));
        float sum = 0.f;
        for (int m = lane; m < N_; m += 32) {
            const float e = __expf(sc[r*N_+m] - mx);
            sc[r*N_+m] = e;
            sum += e;
        }
        #pragma unroll
        for (int o=16;o>0;o>>=1) sum += __shfl_xor_sync(0xffffffffu, sum, o);
        const float inv = 1.f / sum;
        if (n < N_) {
            float* dst = g_attn + (((size_t)b*N_ + n)*H_ + h)*N_;
            for (int m = lane; m < N_; m += 32) dst[m] = sc[r*N_+m]*inv;
        }
    }
}

// ---------------------------------------------------------------------------
// Kernel C: msg GEMM. M=128000 (r = (b*32+t)*500+m), K=128, Ncols=256 (h,u).
// Output scattered to g_msg[b][h][m][t][u].
// ---------------------------------------------------------------------------
__global__ __launch_bounds__(256, 2)
void msg_gemm(const float* __restrict__ curr,
              const float* __restrict__ Wmsg)
{
    const int rowBase = blockIdx.x * 128;
    const int colBase = blockIdx.y * 128;

    __shared__ float As[2][8][132];
    __shared__ float Bs[2][8][128];

    const int tid  = threadIdx.x;
    const int aRow = tid >> 1;
    const int aK   = (tid & 1) * 4;
    const int bK   = tid >> 5;
    const int bCol = (tid & 31) * 4;
    const int tx   = tid & 15;
    const int ty   = tid >> 4;

    const float* aPtr = curr + (size_t)(rowBase + aRow) * DC_ + aK;

    const int cB = colBase + bCol;
    const int hB = cB >> 6;
    const int uB = cB & 63;
    const float* bPtr = Wmsg + hB * (DC_*U_) + bK * U_ + uB;

    const int KSTEPS = DC_ / 8;  // 16

    float4 aReg = *(const float4*)aPtr;
    float4 bReg = *(const float4*)bPtr;

    As[0][aK+0][aRow] = aReg.x; As[0][aK+1][aRow] = aReg.y;
    As[0][aK+2][aRow] = aReg.z; As[0][aK+3][aRow] = aReg.w;
    *(float4*)&Bs[0][bK][bCol] = bReg;
    __syncthreads();

    float acc[2][2][4][4] = {};

    for (int ks = 0; ks < KSTEPS; ks++) {
        const int cur = ks & 1;
        if (ks + 1 < KSTEPS) {
            aReg = *(const float4*)(aPtr + (ks+1)*8);
            bReg = *(const float4*)(bPtr + (ks+1)*8*U_);
        }
        #pragma unroll
        for (int kk = 0; kk < 8; kk++) {
            float ar[2][4], br[2][4];
            *(float4*)ar[0] = *(const float4*)&As[cur][kk][ty*4];
            *(float4*)ar[1] = *(const float4*)&As[cur][kk][ty*4 + 64];
            *(float4*)br[0] = *(const float4*)&Bs[cur][kk][tx*4];
            *(float4*)br[1] = *(const float4*)&Bs[cur][kk][tx*4 + 64];
            #pragma unroll
            for (int rg=0; rg<2; rg++)
              #pragma unroll
              for (int cg=0; cg<2; cg++)
                #pragma unroll
                for (int i=0;i<4;i++)
                  #pragma unroll
                  for (int j=0;j<4;j++)
                    acc[rg][cg][i][j] = fmaf(ar[rg][i], br[cg][j], acc[rg][cg][i][j]);
        }
        if (ks + 1 < KSTEPS) {
            const int nxt = cur ^ 1;
            As[nxt][aK+0][aRow] = aReg.x; As[nxt][aK+1][aRow] = aReg.y;
            As[nxt][aK+2][aRow] = aReg.z; As[nxt][aK+3][aRow] = aReg.w;
            *(float4*)&Bs[nxt][bK][bCol] = bReg;
            __syncthreads();
        }
    }

    #pragma unroll
    for (int rg=0; rg<2; rg++) {
        #pragma unroll
        for (int i=0;i<4;i++) {
            const int r = rowBase + ty*4 + rg*64 + i;   // always < 128000
            const int b = r / (T_*N_);
            const int rem = r - b*(T_*N_);
            const int t = rem / N_;
            const int m = rem - t*N_;
            #pragma unroll
            for (int cg=0; cg<2; cg++) {
                const int c = colBase + tx*4 + cg*64;
                const int h = c >> 6;
                const int u = c & 63;
                float* dst = g_msg + ((((size_t)(b*H_ + h)*N_ + m)*T_ + t)*U_ + u);
                float4 v = make_float4(acc[rg][cg][i][0], acc[rg][cg][i][1],
                                       acc[rg][cg][i][2], acc[rg][cg][i][3]);
                *(float4*)dst = v;
            }
        }
    }
}

// ---------------------------------------------------------------------------
// Kernel D: mix GEMM per batch b (blockIdx.z):
//   O[n][t*64+u] = sum_{h,m} attn[b][n][h*500+m] * msg[b][h*500+m][t*64+u]
//   out[b][t][n][u] = 0.25 * O[n][t*64+u]
// M=500, Ncols=2048, K=2000.
// ---------------------------------------------------------------------------
__global__ __launch_bounds__(256, 2)
void mix_gemm(float* __restrict__ out)
{
    const int b = blockIdx.z;
    const int rowBase = blockIdx.x * 128;
    const int colBase = blockIdx.y * 128;

    const float* A  = g_attn + (size_t)b * N_ * (H_*N_);       // [500 x 2000]
    const float* Bm = g_msg  + (size_t)b * (H_*N_) * (T_*U_);  // [2000 x 2048]

    __shared__ float As[2][8][132];
    __shared__ float Bs[2][8][128];

    const int tid  = threadIdx.x;
    const int aRow = tid >> 1;
    const int aK   = (tid & 1) * 4;
    const int bK   = tid >> 5;
    const int bCol = (tid & 31) * 4;
    const int tx   = tid & 15;
    const int ty   = tid >> 4;

    const int gRow  = rowBase + aRow;
    const bool rowOk = gRow < N_;
    const float* aPtr = A + (size_t)gRow * (H_*N_) + aK;
    const float* bPtr = Bm + (size_t)bK * (T_*U_) + colBase + bCol;

    const int KSTEPS = (H_*N_) / 8;  // 250

    float4 aReg = rowOk ? *(const float4*)aPtr : make_float4(0,0,0,0);
    float4 bReg = *(const float4*)bPtr;

    As[0][aK+0][aRow] = aReg.x; As[0][aK+1][aRow] = aReg.y;
    As[0][aK+2][aRow] = aReg.z; As[0][aK+3][aRow] = aReg.w;
    *(float4*)&Bs[0][bK][bCol] = bReg;
    __syncthreads();

    float acc[2][2][4][4] = {};

    for (int ks = 0; ks < KSTEPS; ks++) {
        const int cur = ks & 1;
        if (ks + 1 < KSTEPS) {
            aReg = rowOk ? *(const float4*)(aPtr + (ks+1)*8) : make_float4(0,0,0,0);
            bReg = *(const float4*)(bPtr + (size_t)(ks+1)*8*(T_*U_));
        }
        #pragma unroll
        for (int kk = 0; kk < 8; kk++) {
            float ar[2][4], br[2][4];
            *(float4*)ar[0] = *(const float4*)&As[cur][kk][ty*4];
            *(float4*)ar[1] = *(const float4*)&As[cur][kk][ty*4 + 64];
            *(float4*)br[0] = *(const float4*)&Bs[cur][kk][tx*4];
            *(float4*)br[1] = *(const float4*)&Bs[cur][kk][tx*4 + 64];
            #pragma unroll
            for (int rg=0; rg<2; rg++)
              #pragma unroll
              for (int cg=0; cg<2; cg++)
                #pragma unroll
                for (int i=0;i<4;i++)
                  #pragma unroll
                  for (int j=0;j<4;j++)
                    acc[rg][cg][i][j] = fmaf(ar[rg][i], br[cg][j], acc[rg][cg][i][j]);
        }
        if (ks + 1 < KSTEPS) {
            const int nxt = cur ^ 1;
            As[nxt][aK+0][aRow] = aReg.x; As[nxt][aK+1][aRow] = aReg.y;
            As[nxt][aK+2][aRow] = aReg.z; As[nxt][aK+3][aRow] = aReg.w;
            *(float4*)&Bs[nxt][bK][bCol] = bReg;
            __syncthreads();
        }
    }

    #pragma unroll
    for (int rg=0; rg<2; rg++) {
        #pragma unroll
        for (int i=0;i<4;i++) {
            const int n = rowBase + ty*4 + rg*64 + i;
            if (n < N_) {
                #pragma unroll
                for (int cg=0; cg<2; cg++) {
                    const int c = colBase + tx*4 + cg*64;
                    const int t = c >> 6;
                    const int u = c & 63;
                    float4 v = make_float4(acc[rg][cg][i][0]*0.25f, acc[rg][cg][i][1]*0.25f,
                                           acc[rg][cg][i][2]*0.25f, acc[rg][cg][i][3]*0.25f);
                    *(float4*)&out[(((size_t)b*T_ + t)*N_ + n)*U_ + u] = v;
                }
            }
        }
    }
}

// ---------------------------------------------------------------------------
extern "C" void kernel_launch(void* const* d_in, const int* in_sizes, int n_in,
                              void* d_out, int out_size)
{
    const float* prev = (const float*)d_in[0];   // [8,500,200]
    const float* curr = (const float*)d_in[1];   // [8,32,500,128]
    const float* Wsrc = (const float*)d_in[2];   // [4,200,64]
    const float* Wdst = (const float*)d_in[3];   // [4,200,64]
    const float* aV   = (const float*)d_in[4];   // [4,64,1]
    const float* Wmsg = (const float*)d_in[5];   // [4,128,64]
    float* out = (float*)d_out;                  // [8,32,500,64]

    // A: projections  (M=4000, N=512, K=200)
    proj_gemm<<<dim3(32, 4), 256>>>(prev, Wsrc, Wdst);

    // B: scores + softmax
    const size_t shB = (size_t)(512*65 + 16*64 + 128 + 16*500) * sizeof(float);
    cudaFuncSetAttribute(score_softmax_kernel,
                         cudaFuncAttributeMaxDynamicSharedMemorySize, (int)shB);
    score_softmax_kernel<<<dim3(32, 32), 256, shB>>>(aV);

    // C: msg GEMM  (M=128000, N=256, K=128)
    msg_gemm<<<dim3(1000, 2), 256>>>(curr, Wmsg);

    // D: mix GEMM  (per batch: M=500, N=2048, K=2000)
    mix_gemm<<<dim3(4, 16, 8), 256>>>(out);
}

// round 7
// speedup vs baseline: 1.4128x; 1.4100x over previous
#include <cuda_runtime.h>
#include <cuda_bf16.h>
#include <cstdint>
#include <cstddef>

// Problem constants
#define B_   8
#define T_   32
#define N_   500
#define DP_  200
#define DC_  128
#define H_   4
#define U_   64
#define HM_  2000   // H_*N_  (K dim of mix GEMM)
#define TU_  2048   // T_*U_  (N dim of mix GEMM)

// Scratch (device globals: allocation-free rule)
__device__ float g_S[B_*H_*N_*U_];                         // [b][h][n][u]
__device__ float g_D[B_*H_*N_*U_];                         // [b][h][m][u]
__device__ __nv_bfloat16 g_attn_hi[(size_t)B_*N_*HM_];     // [b][n][hm]
__device__ __nv_bfloat16 g_attn_lo[(size_t)B_*N_*HM_];     // [b][n][hm]
__device__ __nv_bfloat16 g_msgT_hi[(size_t)B_*TU_*HM_];    // [b][tu][hm]
__device__ __nv_bfloat16 g_msgT_lo[(size_t)B_*TU_*HM_];    // [b][tu][hm]

// ---------------------------------------------------------------------------
// Helpers (baseline PTX only — compute_103-safe: cp.async / ldmatrix / mma.sync)
// ---------------------------------------------------------------------------
__device__ __forceinline__ uint32_t smem_u32(const void* p) {
    uint32_t a;
    asm("{ .reg .u64 t; cvta.to.shared.u64 t, %1; cvt.u32.u64 %0, t; }" : "=r"(a) : "l"(p));
    return a;
}
__device__ __forceinline__ void cp16(uint32_t dst, const void* src, bool ok) {
    int sz = ok ? 16 : 0;   // src-size 0 => zero-fill 16B
    asm volatile("cp.async.cg.shared.global [%0], [%1], 16, %2;" :: "r"(dst), "l"(src), "r"(sz) : "memory");
}
__device__ __forceinline__ void cp_commit() {
    asm volatile("cp.async.commit_group;" ::: "memory");
}
template <int NW>
__device__ __forceinline__ void cp_wait() {
    asm volatile("cp.async.wait_group %0;" :: "n"(NW) : "memory");
}
__device__ __forceinline__ void ldsm_x4(uint32_t* r, uint32_t addr) {
    asm volatile("ldmatrix.sync.aligned.m8n8.x4.shared.b16 {%0,%1,%2,%3}, [%4];"
                 : "=r"(r[0]), "=r"(r[1]), "=r"(r[2]), "=r"(r[3]) : "r"(addr));
}
__device__ __forceinline__ void mma16816(float* c, const uint32_t* a, const uint32_t* b) {
    asm volatile(
        "mma.sync.aligned.m16n8k16.row.col.f32.bf16.bf16.f32 "
        "{%0,%1,%2,%3}, {%4,%5,%6,%7}, {%8,%9}, {%0,%1,%2,%3};"
        : "+f"(c[0]), "+f"(c[1]), "+f"(c[2]), "+f"(c[3])
        : "r"(a[0]), "r"(a[1]), "r"(a[2]), "r"(a[3]), "r"(b[0]), "r"(b[1]));
}
__device__ __forceinline__ void bf16_split(float v, __nv_bfloat16& hi, __nv_bfloat16& lo) {
    hi = __float2bfloat16(v);
    lo = __float2bfloat16(v - __bfloat162float(hi));
}

// ---------------------------------------------------------------------------
// Kernel A: projections.  GEMM M=4000 (b*500+n), K=200, Ncols=512
// ---------------------------------------------------------------------------
__global__ __launch_bounds__(256, 2)
void proj_gemm(const float* __restrict__ prev,
               const float* __restrict__ Wsrc,
               const float* __restrict__ Wdst)
{
    const int rowBase = blockIdx.x * 128;
    const int colBase = blockIdx.y * 128;

    __shared__ float As[2][8][132];
    __shared__ float Bs[2][8][128];

    const int tid  = threadIdx.x;
    const int aRow = tid >> 1;
    const int aK   = (tid & 1) * 4;
    const int bK   = tid >> 5;
    const int bCol = (tid & 31) * 4;
    const int tx   = tid & 15;
    const int ty   = tid >> 4;

    const int gRow  = rowBase + aRow;
    const bool rowOk = gRow < 4000;
    const float* aPtr = prev + (size_t)gRow * DP_ + aK;

    const int cB   = colBase + bCol;
    const int matB = cB >> 8;
    const int hB   = (cB >> 6) & 3;
    const int uB   = cB & 63;
    const float* bPtr = (matB ? Wdst : Wsrc) + hB * (DP_*U_) + bK * U_ + uB;

    const int KSTEPS = DP_ / 8;  // 25

    float4 aReg = rowOk ? *(const float4*)aPtr : make_float4(0,0,0,0);
    float4 bReg = *(const float4*)bPtr;

    As[0][aK+0][aRow] = aReg.x; As[0][aK+1][aRow] = aReg.y;
    As[0][aK+2][aRow] = aReg.z; As[0][aK+3][aRow] = aReg.w;
    *(float4*)&Bs[0][bK][bCol] = bReg;
    __syncthreads();

    float acc[2][2][4][4] = {};

    for (int ks = 0; ks < KSTEPS; ks++) {
        const int cur = ks & 1;
        if (ks + 1 < KSTEPS) {
            aReg = rowOk ? *(const float4*)(aPtr + (ks+1)*8) : make_float4(0,0,0,0);
            bReg = *(const float4*)(bPtr + (ks+1)*8*U_);
        }
        #pragma unroll
        for (int kk = 0; kk < 8; kk++) {
            float ar[2][4], br[2][4];
            *(float4*)ar[0] = *(const float4*)&As[cur][kk][ty*4];
            *(float4*)ar[1] = *(const float4*)&As[cur][kk][ty*4 + 64];
            *(float4*)br[0] = *(const float4*)&Bs[cur][kk][tx*4];
            *(float4*)br[1] = *(const float4*)&Bs[cur][kk][tx*4 + 64];
            #pragma unroll
            for (int rg=0; rg<2; rg++)
              #pragma unroll
              for (int cg=0; cg<2; cg++)
                #pragma unroll
                for (int i=0;i<4;i++)
                  #pragma unroll
                  for (int j=0;j<4;j++)
                    acc[rg][cg][i][j] = fmaf(ar[rg][i], br[cg][j], acc[rg][cg][i][j]);
        }
        if (ks + 1 < KSTEPS) {
            const int nxt = cur ^ 1;
            As[nxt][aK+0][aRow] = aReg.x; As[nxt][aK+1][aRow] = aReg.y;
            As[nxt][aK+2][aRow] = aReg.z; As[nxt][aK+3][aRow] = aReg.w;
            *(float4*)&Bs[nxt][bK][bCol] = bReg;
            __syncthreads();
        }
    }

    #pragma unroll
    for (int rg=0; rg<2; rg++) {
        #pragma unroll
        for (int i=0;i<4;i++) {
            const int r = rowBase + ty*4 + rg*64 + i;
            if (r < 4000) {
                const int b = r / N_;
                const int n = r - b * N_;
                #pragma unroll
                for (int cg=0; cg<2; cg++) {
                    const int c = colBase + tx*4 + cg*64;
                    const int mat = c >> 8;
                    const int h   = (c >> 6) & 3;
                    const int u   = c & 63;
                    float* dst = (mat ? g_D : g_S) + ((size_t)(b*H_ + h)*N_ + n)*U_ + u;
                    float4 v = make_float4(acc[rg][cg][i][0], acc[rg][cg][i][1],
                                           acc[rg][cg][i][2], acc[rg][cg][i][3]);
                    *(float4*)dst = v;
                }
            }
        }
    }
}

// ---------------------------------------------------------------------------
// Kernel B: GATv2 scores + softmax -> attn written as bf16 hi/lo [b][n][hm]
// ---------------------------------------------------------------------------
__global__ __launch_bounds__(256)
void score_softmax_kernel(const float* __restrict__ aVec)
{
    extern __shared__ float sh[];
    float* Dsh = sh;                     // 512*65
    float* Ssh = Dsh + 512*65;           // 16*64
    float* aSh = Ssh + 16*64;            // 64 (+64 pad)
    float* sc  = aSh + 128;              // 16*500

    const int bh = blockIdx.y;           // b*4 + h
    const int b  = bh >> 2;
    const int h  = bh & 3;
    const int nBase = blockIdx.x * 16;
    const int tid = threadIdx.x;

    const float* Dg = g_D + (size_t)bh * N_ * U_;
    const float* Sg = g_S + (size_t)bh * N_ * U_;

    for (int idx = tid; idx < 512*16; idx += 256) {
        const int m = idx >> 4;
        const int u = (idx & 15) * 4;
        float4 v = (m < N_) ? *(const float4*)(Dg + m*U_ + u) : make_float4(0,0,0,0);
        float* dst = &Dsh[m*65 + u];
        dst[0]=v.x; dst[1]=v.y; dst[2]=v.z; dst[3]=v.w;
    }
    for (int idx = tid; idx < 16*16; idx += 256) {
        const int r = idx >> 4;
        const int u = (idx & 15) * 4;
        const int n = nBase + r;
        float4 v = (n < N_) ? *(const float4*)(Sg + n*U_ + u) : make_float4(0,0,0,0);
        float* dst = &Ssh[r*U_ + u];
        dst[0]=v.x; dst[1]=v.y; dst[2]=v.z; dst[3]=v.w;
    }
    if (tid < 64) aSh[tid] = aVec[h*U_ + tid];
    __syncthreads();

    const int tx  = tid & 63;
    const int tyy = tid >> 6;

    float acc[4][8];
    #pragma unroll
    for (int i=0;i<4;i++)
        #pragma unroll
        for (int k=0;k<8;k++) acc[i][k]=0.f;

    for (int u = 0; u < U_; u++) {
        const float au = aSh[u];
        float s[4];
        #pragma unroll
        for (int i=0;i<4;i++) s[i] = Ssh[(tyy*4+i)*U_ + u];
        #pragma unroll
        for (int k=0;k<8;k++) {
            const float d = Dsh[(tx + 64*k)*65 + u];
            #pragma unroll
            for (int i=0;i<4;i++) {
                const float t  = s[i] + d;
                const float lr = fmaxf(t, 0.2f * t);
                acc[i][k] = fmaf(au, lr, acc[i][k]);
            }
        }
    }
    #pragma unroll
    for (int i=0;i<4;i++)
        #pragma unroll
        for (int k=0;k<8;k++) {
            const int m = tx + 64*k;
            if (m < N_) sc[(tyy*4+i)*N_ + m] = acc[i][k];
        }
    __syncthreads();

    const int warp = tid >> 5, lane = tid & 31;
    #pragma unroll
    for (int rr = 0; rr < 2; rr++) {
        const int r = warp*2 + rr;
        const int n = nBase + r;
        float mx = -1e30f;
        for (int m = lane; m < N_; m += 32) mx = fmaxf(mx, sc[r*N_+m]);
        #pragma unroll
        for (int o=16;o>0;o>>=1) mx = fmaxf(mx, __shfl_xor_sync(0xffffffffu, mx, o));
        float sum = 0.f;
        for (int m = lane; m < N_; m += 32) {
            const float e = __expf(sc[r*N_+m] - mx);
            sc[r*N_+m] = e;
            sum += e;
        }
        #pragma unroll
        for (int o=16;o>0;o>>=1) sum += __shfl_xor_sync(0xffffffffu, sum, o);
        const float inv = 1.f / sum;
        if (n < N_) {
            __nv_bfloat16* dH = g_attn_hi + ((size_t)b*N_ + n)*HM_ + (size_t)h*N_;
            __nv_bfloat16* dL = g_attn_lo + ((size_t)b*N_ + n)*HM_ + (size_t)h*N_;
            for (int m = lane; m < N_; m += 32) {
                const float v = sc[r*N_+m]*inv;
                __nv_bfloat16 hi, lo;
                bf16_split(v, hi, lo);
                dH[m] = hi; dL[m] = lo;
            }
        }
    }
}

// ---------------------------------------------------------------------------
// Kernel C: msg GEMM. M=128000 (r=(b*32+t)*500+m), K=128, Ncols=256 (h,u).
// Epilogue: bf16 hi/lo TRANSPOSED: msgT[b][t*64+u][h*500+m]
// ---------------------------------------------------------------------------
__global__ __launch_bounds__(256, 2)
void msg_gemm(const float* __restrict__ curr,
              const float* __restrict__ Wmsg)
{
    const int rowBase = blockIdx.x * 128;
    const int colBase = blockIdx.y * 128;

    __shared__ float As[2][8][132];
    __shared__ float Bs[2][8][128];

    const int tid  = threadIdx.x;
    const int aRow = tid >> 1;
    const int aK   = (tid & 1) * 4;
    const int bK   = tid >> 5;
    const int bCol = (tid & 31) * 4;
    const int tx   = tid & 15;
    const int ty   = tid >> 4;

    const float* aPtr = curr + (size_t)(rowBase + aRow) * DC_ + aK;

    const int cB = colBase + bCol;
    const int hB = cB >> 6;
    const int uB = cB & 63;
    const float* bPtr = Wmsg + hB * (DC_*U_) + bK * U_ + uB;

    const int KSTEPS = DC_ / 8;  // 16

    float4 aReg = *(const float4*)aPtr;
    float4 bReg = *(const float4*)bPtr;

    As[0][aK+0][aRow] = aReg.x; As[0][aK+1][aRow] = aReg.y;
    As[0][aK+2][aRow] = aReg.z; As[0][aK+3][aRow] = aReg.w;
    *(float4*)&Bs[0][bK][bCol] = bReg;
    __syncthreads();

    float acc[2][2][4][4] = {};

    for (int ks = 0; ks < KSTEPS; ks++) {
        const int cur = ks & 1;
        if (ks + 1 < KSTEPS) {
            aReg = *(const float4*)(aPtr + (ks+1)*8);
            bReg = *(const float4*)(bPtr + (ks+1)*8*U_);
        }
        #pragma unroll
        for (int kk = 0; kk < 8; kk++) {
            float ar[2][4], br[2][4];
            *(float4*)ar[0] = *(const float4*)&As[cur][kk][ty*4];
            *(float4*)ar[1] = *(const float4*)&As[cur][kk][ty*4 + 64];
            *(float4*)br[0] = *(const float4*)&Bs[cur][kk][tx*4];
            *(float4*)br[1] = *(const float4*)&Bs[cur][kk][tx*4 + 64];
            #pragma unroll
            for (int rg=0; rg<2; rg++)
              #pragma unroll
              for (int cg=0; cg<2; cg++)
                #pragma unroll
                for (int i=0;i<4;i++)
                  #pragma unroll
                  for (int j=0;j<4;j++)
                    acc[rg][cg][i][j] = fmaf(ar[rg][i], br[cg][j], acc[rg][cg][i][j]);
        }
        if (ks + 1 < KSTEPS) {
            const int nxt = cur ^ 1;
            As[nxt][aK+0][aRow] = aReg.x; As[nxt][aK+1][aRow] = aReg.y;
            As[nxt][aK+2][aRow] = aReg.z; As[nxt][aK+3][aRow] = aReg.w;
            *(float4*)&Bs[nxt][bK][bCol] = bReg;
            __syncthreads();
        }
    }

    // Transposed bf16 hi/lo epilogue (4 consecutive m per thread quad; 500%4==0)
    #pragma unroll
    for (int rg=0; rg<2; rg++) {
        const int r0 = rowBase + ty*4 + rg*64;
        const int bb  = r0 / (T_*N_);
        const int rem = r0 - bb*(T_*N_);
        const int t   = rem / N_;
        const int m   = rem - t*N_;
        #pragma unroll
        for (int cg=0; cg<2; cg++) {
            #pragma unroll
            for (int j=0;j<4;j++) {
                const int c = colBase + tx*4 + cg*64 + j;
                const int h = c >> 6;
                const int u = c & 63;
                const size_t off = ((size_t)bb*TU_ + t*U_ + u)*HM_ + (size_t)h*N_ + m;
                union { __nv_bfloat16 x[4]; uint2 v; } ph, pl;
                #pragma unroll
                for (int i=0;i<4;i++) {
                    __nv_bfloat16 hi, lo;
                    bf16_split(acc[rg][cg][i][j], hi, lo);
                    ph.x[i] = hi; pl.x[i] = lo;
                }
                *(uint2*)&g_msgT_hi[off] = ph.v;
                *(uint2*)&g_msgT_lo[off] = pl.v;
            }
        }
    }
}

// ---------------------------------------------------------------------------
// Kernel D: mix GEMM via mma.sync (HMMA bf16, split precision).
// Per (Mtile 128, Ntile 128, b): C[n][tu] = Ah*Bh + Ah*Bl + Al*Bh  (fp32 acc)
//   A = attn[b][n][k] (K-major), B = msgT[b][tu][k] (K-major), K zero-pad 2016.
// cp.async double buffer, KC=32; ldmatrix from 80B-strided smem rows.
// ---------------------------------------------------------------------------
#define MIX_KC    32
#define MIX_NCH   63          // ceil(2000/32) -> covers k<2016, zero-filled
#define MRS       80          // smem row stride bytes (64B data + 16B pad)
#define MTILE     10240       // 128 rows * 80B
#define MSTAGE    (4*MTILE)   // Ah, Al, Bh, Bl
#define MSM_TOTAL (2*MSTAGE)  // 81920

__device__ __forceinline__ void mix_load_chunk(
    uint32_t sstage, int kc, int tid, int b, int mBase, int nBase)
{
    const __nv_bfloat16* Ah = g_attn_hi + (size_t)b * N_ * HM_;
    const __nv_bfloat16* Al = g_attn_lo + (size_t)b * N_ * HM_;
    const __nv_bfloat16* Bh = g_msgT_hi + (size_t)b * TU_ * HM_;
    const __nv_bfloat16* Bl = g_msgT_lo + (size_t)b * TU_ * HM_;
    #pragma unroll
    for (int i = 0; i < 8; i++) {
        const int g    = tid + i*256;       // 0..2047
        const int tile = g >> 9;            // 0:Ah 1:Al 2:Bh 3:Bl
        const int rem  = g & 511;
        const int row  = rem >> 2;
        const int seg  = rem & 3;
        const int k    = kc + seg*8;
        const uint32_t dst = sstage + tile*MTILE + row*MRS + seg*16;
        if (tile < 2) {
            const int n = mBase + row;
            const bool ok = (n < N_) && (k < HM_);
            const __nv_bfloat16* base = tile ? Al : Ah;
            cp16(dst, base + (ok ? ((size_t)n*HM_ + k) : 0), ok);
        } else {
            const bool ok = (k < HM_);
            const __nv_bfloat16* base = (tile == 3) ? Bl : Bh;
            cp16(dst, base + (ok ? ((size_t)(nBase + row)*HM_ + k) : 0), ok);
        }
    }
    cp_commit();
}

__global__ __launch_bounds__(256, 1)
void mix_mma(float* __restrict__ out)
{
    extern __shared__ __align__(128) char smx[];
    const uint32_t sbase = smem_u32(smx);
    const int tid  = threadIdx.x;
    const int wid  = tid >> 5;
    const int lane = tid & 31;
    const int b     = blockIdx.z;
    const int mBase = blockIdx.x * 128;
    const int nBase = blockIdx.y * 128;

    const int wm = wid & 1;       // m band (2 x 64)
    const int wn = wid >> 1;      // n band (4 x 32)

    // ldmatrix lane address components
    const uint32_t aRowOff = (lane & 7) + ((lane >> 3) & 1) * 8;   // A: x4 = (r0-7,k0-7)(r8-15,k0-7)(r0-7,k8-15)(r8-15,k8-15)
    const uint32_t aSegOff = (lane >> 4) * 16;
    const uint32_t bRowOff = (lane & 7) + (lane >> 4) * 8;         // B: x4 = (n0-7,k0-7)(n0-7,k8-15)(n8-15,k0-7)(n8-15,k8-15)
    const uint32_t bSegOff = ((lane >> 3) & 1) * 16;

    float acc[4][4][4] = {};   // [mt][nt][4]

    mix_load_chunk(sbase, 0, tid, b, mBase, nBase);

    for (int c = 0; c < MIX_NCH; c++) {
        if (c + 1 < MIX_NCH) {
            mix_load_chunk(sbase + ((c+1) & 1)*MSTAGE, (c+1)*MIX_KC, tid, b, mBase, nBase);
            cp_wait<1>();
        } else {
            cp_wait<0>();
        }
        __syncthreads();

        const uint32_t sA = sbase + (c & 1)*MSTAGE;
        const uint32_t sB = sA + 2*MTILE;

        #pragma unroll
        for (int k16 = 0; k16 < 2; k16++) {
            const uint32_t kb = k16*32;
            uint32_t ah[4][4], al[4][4];
            #pragma unroll
            for (int mt = 0; mt < 4; mt++) {
                const uint32_t addr = sA + (wm*64 + mt*16 + aRowOff)*MRS + kb + aSegOff;
                ldsm_x4(ah[mt], addr);
                ldsm_x4(al[mt], addr + MTILE);
            }
            uint32_t bh[2][4], bl[2][4];
            #pragma unroll
            for (int p = 0; p < 2; p++) {
                const uint32_t addr = sB + (wn*32 + p*16 + bRowOff)*MRS + kb + bSegOff;
                ldsm_x4(bh[p], addr);
                ldsm_x4(bl[p], addr + MTILE);
            }
            #pragma unroll
            for (int mt = 0; mt < 4; mt++) {
                #pragma unroll
                for (int nt = 0; nt < 4; nt++) {
                    const uint32_t* ph = &bh[nt >> 1][(nt & 1)*2];
                    const uint32_t* pl = &bl[nt >> 1][(nt & 1)*2];
                    mma16816(acc[mt][nt], ah[mt], ph);
                    mma16816(acc[mt][nt], ah[mt], pl);
                    mma16816(acc[mt][nt], al[mt], ph);
                }
            }
        }
        __syncthreads();
    }

    // Epilogue: thread (mt,nt): rows mBase+wm*64+mt*16+lane/4 (+8), cols nBase+wn*32+nt*8+(lane%4)*2
    const int r0 = mBase + wm*64 + (lane >> 2);
    const int c0 = nBase + wn*32 + (lane & 3)*2;
    #pragma unroll
    for (int mt = 0; mt < 4; mt++) {
        #pragma unroll
        for (int half = 0; half < 2; half++) {
            const int n = r0 + mt*16 + half*8;
            if (n < N_) {
                #pragma unroll
                for (int nt = 0; nt < 4; nt++) {
                    const int cc = c0 + nt*8;
                    const int t  = cc >> 6;
                    const int u  = cc & 63;
                    float2 v = make_float2(acc[mt][nt][half*2+0]*0.25f,
                                           acc[mt][nt][half*2+1]*0.25f);
                    *(float2*)&out[(((size_t)b*T_ + t)*N_ + n)*U_ + u] = v;
                }
            }
        }
    }
}

// ---------------------------------------------------------------------------
extern "C" void kernel_launch(void* const* d_in, const int* in_sizes, int n_in,
                              void* d_out, int out_size)
{
    const float* prev = (const float*)d_in[0];   // [8,500,200]
    const float* curr = (const float*)d_in[1];   // [8,32,500,128]
    const float* Wsrc = (const float*)d_in[2];   // [4,200,64]
    const float* Wdst = (const float*)d_in[3];   // [4,200,64]
    const float* aV   = (const float*)d_in[4];   // [4,64,1]
    const float* Wmsg = (const float*)d_in[5];   // [4,128,64]
    float* out = (float*)d_out;                  // [8,32,500,64]

    // A: projections  (M=4000, N=512, K=200)
    proj_gemm<<<dim3(32, 4), 256>>>(prev, Wsrc, Wdst);

    // B: scores + softmax -> bf16 hi/lo attn
    const size_t shB = (size_t)(512*65 + 16*64 + 128 + 16*500) * sizeof(float);
    cudaFuncSetAttribute(score_softmax_kernel,
                         cudaFuncAttributeMaxDynamicSharedMemorySize, (int)shB);
    score_softmax_kernel<<<dim3(32, 32), 256, shB>>>(aV);

    // C: msg GEMM -> transposed bf16 hi/lo msgT
    msg_gemm<<<dim3(1000, 2), 256>>>(curr, Wmsg);

    // D: mix GEMM on tensor cores via mma.sync (per batch: M=500, N=2048, K=2000)
    cudaFuncSetAttribute(mix_mma,
                         cudaFuncAttributeMaxDynamicSharedMemorySize, MSM_TOTAL);
    mix_mma<<<dim3(4, 16, 8), 256, MSM_TOTAL>>>(out);
}

// round 9
// speedup vs baseline: 1.4691x; 1.0399x over previous
#include <cuda_runtime.h>
#include <cuda_bf16.h>
#include <cstdint>
#include <cstddef>

// Problem constants
#define B_   8
#define T_   32
#define N_   500
#define DP_  200
#define DC_  128
#define H_   4
#define U_   64
#define HM_  2000   // H_*N_  (K dim of mix GEMM)
#define TU_  2048   // T_*U_  (N dim of mix GEMM)

// Scratch (device globals: allocation-free rule)
__device__ float g_S[B_*H_*N_*U_];                         // [b][h][n][u]
__device__ float g_D[B_*H_*N_*U_];                         // [b][h][m][u]
__device__ __nv_bfloat16 g_attn_hi[(size_t)B_*N_*HM_];     // [b][n][hm]
__device__ __nv_bfloat16 g_attn_lo[(size_t)B_*N_*HM_];     // [b][n][hm]
__device__ __nv_bfloat16 g_msgT_hi[(size_t)B_*TU_*HM_];    // [b][tu][hm]
__device__ __nv_bfloat16 g_msgT_lo[(size_t)B_*TU_*HM_];    // [b][tu][hm]

// ---------------------------------------------------------------------------
// Helpers (compute_103-safe: cp.async / ldmatrix / mma.sync)
// ---------------------------------------------------------------------------
__device__ __forceinline__ uint32_t smem_u32(const void* p) {
    uint32_t a;
    asm("{ .reg .u64 t; cvta.to.shared.u64 t, %1; cvt.u32.u64 %0, t; }" : "=r"(a) : "l"(p));
    return a;
}
__device__ __forceinline__ void cp16(uint32_t dst, const void* src, bool ok) {
    int sz = ok ? 16 : 0;   // src-size 0 => zero-fill 16B
    asm volatile("cp.async.cg.shared.global [%0], [%1], 16, %2;" :: "r"(dst), "l"(src), "r"(sz) : "memory");
}
__device__ __forceinline__ void cp_commit() {
    asm volatile("cp.async.commit_group;" ::: "memory");
}
template <int NW>
__device__ __forceinline__ void cp_wait() {
    asm volatile("cp.async.wait_group %0;" :: "n"(NW) : "memory");
}
__device__ __forceinline__ void ldsm_x4(uint32_t* r, uint32_t addr) {
    asm volatile("ldmatrix.sync.aligned.m8n8.x4.shared.b16 {%0,%1,%2,%3}, [%4];"
                 : "=r"(r[0]), "=r"(r[1]), "=r"(r[2]), "=r"(r[3]) : "r"(addr));
}
__device__ __forceinline__ void mma16816(float* c, const uint32_t* a, const uint32_t* b) {
    asm volatile(
        "mma.sync.aligned.m16n8k16.row.col.f32.bf16.bf16.f32 "
        "{%0,%1,%2,%3}, {%4,%5,%6,%7}, {%8,%9}, {%0,%1,%2,%3};"
        : "+f"(c[0]), "+f"(c[1]), "+f"(c[2]), "+f"(c[3])
        : "r"(a[0]), "r"(a[1]), "r"(a[2]), "r"(a[3]), "r"(b[0]), "r"(b[1]));
}
__device__ __forceinline__ void bf16_split(float v, __nv_bfloat16& hi, __nv_bfloat16& lo) {
    hi = __float2bfloat16(v);
    lo = __float2bfloat16(v - __bfloat162float(hi));
}

// ---------------------------------------------------------------------------
// Kernel A: projections.  GEMM M=4000 (b*500+n), K=200, Ncols=512
// ---------------------------------------------------------------------------
__global__ __launch_bounds__(256, 2)
void proj_gemm(const float* __restrict__ prev,
               const float* __restrict__ Wsrc,
               const float* __restrict__ Wdst)
{
    const int rowBase = blockIdx.x * 128;
    const int colBase = blockIdx.y * 128;

    __shared__ float As[2][8][132];
    __shared__ float Bs[2][8][128];

    const int tid  = threadIdx.x;
    const int aRow = tid >> 1;
    const int aK   = (tid & 1) * 4;
    const int bK   = tid >> 5;
    const int bCol = (tid & 31) * 4;
    const int tx   = tid & 15;
    const int ty   = tid >> 4;

    const int gRow  = rowBase + aRow;
    const bool rowOk = gRow < 4000;
    const float* aPtr = prev + (size_t)gRow * DP_ + aK;

    const int cB   = colBase + bCol;
    const int matB = cB >> 8;
    const int hB   = (cB >> 6) & 3;
    const int uB   = cB & 63;
    const float* bPtr = (matB ? Wdst : Wsrc) + hB * (DP_*U_) + bK * U_ + uB;

    const int KSTEPS = DP_ / 8;  // 25

    float4 aReg = rowOk ? *(const float4*)aPtr : make_float4(0,0,0,0);
    float4 bReg = *(const float4*)bPtr;

    As[0][aK+0][aRow] = aReg.x; As[0][aK+1][aRow] = aReg.y;
    As[0][aK+2][aRow] = aReg.z; As[0][aK+3][aRow] = aReg.w;
    *(float4*)&Bs[0][bK][bCol] = bReg;
    __syncthreads();

    float acc[2][2][4][4] = {};

    for (int ks = 0; ks < KSTEPS; ks++) {
        const int cur = ks & 1;
        if (ks + 1 < KSTEPS) {
            aReg = rowOk ? *(const float4*)(aPtr + (ks+1)*8) : make_float4(0,0,0,0);
            bReg = *(const float4*)(bPtr + (ks+1)*8*U_);
        }
        #pragma unroll
        for (int kk = 0; kk < 8; kk++) {
            float ar[2][4], br[2][4];
            *(float4*)ar[0] = *(const float4*)&As[cur][kk][ty*4];
            *(float4*)ar[1] = *(const float4*)&As[cur][kk][ty*4 + 64];
            *(float4*)br[0] = *(const float4*)&Bs[cur][kk][tx*4];
            *(float4*)br[1] = *(const float4*)&Bs[cur][kk][tx*4 + 64];
            #pragma unroll
            for (int rg=0; rg<2; rg++)
              #pragma unroll
              for (int cg=0; cg<2; cg++)
                #pragma unroll
                for (int i=0;i<4;i++)
                  #pragma unroll
                  for (int j=0;j<4;j++)
                    acc[rg][cg][i][j] = fmaf(ar[rg][i], br[cg][j], acc[rg][cg][i][j]);
        }
        if (ks + 1 < KSTEPS) {
            const int nxt = cur ^ 1;
            As[nxt][aK+0][aRow] = aReg.x; As[nxt][aK+1][aRow] = aReg.y;
            As[nxt][aK+2][aRow] = aReg.z; As[nxt][aK+3][aRow] = aReg.w;
            *(float4*)&Bs[nxt][bK][bCol] = bReg;
            __syncthreads();
        }
    }

    #pragma unroll
    for (int rg=0; rg<2; rg++) {
        #pragma unroll
        for (int i=0;i<4;i++) {
            const int r = rowBase + ty*4 + rg*64 + i;
            if (r < 4000) {
                const int b = r / N_;
                const int n = r - b * N_;
                #pragma unroll
                for (int cg=0; cg<2; cg++) {
                    const int c = colBase + tx*4 + cg*64;
                    const int mat = c >> 8;
                    const int h   = (c >> 6) & 3;
                    const int u   = c & 63;
                    float* dst = (mat ? g_D : g_S) + ((size_t)(b*H_ + h)*N_ + n)*U_ + u;
                    float4 v = make_float4(acc[rg][cg][i][0], acc[rg][cg][i][1],
                                           acc[rg][cg][i][2], acc[rg][cg][i][3]);
                    *(float4*)dst = v;
                }
            }
        }
    }
}

// ---------------------------------------------------------------------------
// Kernel B: GATv2 scores + softmax -> attn written as bf16 hi/lo [b][n][hm]
// ---------------------------------------------------------------------------
__global__ __launch_bounds__(256)
void score_softmax_kernel(const float* __restrict__ aVec)
{
    extern __shared__ float sh[];
    float* Dsh = sh;                     // 512*65
    float* Ssh = Dsh + 512*65;           // 16*64
    float* aSh = Ssh + 16*64;            // 64 (+64 pad)
    float* sc  = aSh + 128;              // 16*500

    const int bh = blockIdx.y;           // b*4 + h
    const int b  = bh >> 2;
    const int h  = bh & 3;
    const int nBase = blockIdx.x * 16;
    const int tid = threadIdx.x;

    const float* Dg = g_D + (size_t)bh * N_ * U_;
    const float* Sg = g_S + (size_t)bh * N_ * U_;

    for (int idx = tid; idx < 512*16; idx += 256) {
        const int m = idx >> 4;
        const int u = (idx & 15) * 4;
        float4 v = (m < N_) ? *(const float4*)(Dg + m*U_ + u) : make_float4(0,0,0,0);
        float* dst = &Dsh[m*65 + u];
        dst[0]=v.x; dst[1]=v.y; dst[2]=v.z; dst[3]=v.w;
    }
    for (int idx = tid; idx < 16*16; idx += 256) {
        const int r = idx >> 4;
        const int u = (idx & 15) * 4;
        const int n = nBase + r;
        float4 v = (n < N_) ? *(const float4*)(Sg + n*U_ + u) : make_float4(0,0,0,0);
        float* dst = &Ssh[r*U_ + u];
        dst[0]=v.x; dst[1]=v.y; dst[2]=v.z; dst[3]=v.w;
    }
    if (tid < 64) aSh[tid] = aVec[h*U_ + tid];
    __syncthreads();

    const int tx  = tid & 63;
    const int tyy = tid >> 6;

    float acc[4][8];
    #pragma unroll
    for (int i=0;i<4;i++)
        #pragma unroll
        for (int k=0;k<8;k++) acc[i][k]=0.f;

    for (int u = 0; u < U_; u++) {
        const float au = aSh[u];
        float s[4];
        #pragma unroll
        for (int i=0;i<4;i++) s[i] = Ssh[(tyy*4+i)*U_ + u];
        #pragma unroll
        for (int k=0;k<8;k++) {
            const float d = Dsh[(tx + 64*k)*65 + u];
            #pragma unroll
            for (int i=0;i<4;i++) {
                const float t  = s[i] + d;
                const float lr = fmaxf(t, 0.2f * t);
                acc[i][k] = fmaf(au, lr, acc[i][k]);
            }
        }
    }
    #pragma unroll
    for (int i=0;i<4;i++)
        #pragma unroll
        for (int k=0;k<8;k++) {
            const int m = tx + 64*k;
            if (m < N_) sc[(tyy*4+i)*N_ + m] = acc[i][k];
        }
    __syncthreads();

    const int warp = tid >> 5, lane = tid & 31;
    #pragma unroll
    for (int rr = 0; rr < 2; rr++) {
        const int r = warp*2 + rr;
        const int n = nBase + r;
        float mx = -1e30f;
        for (int m = lane; m < N_; m += 32) mx = fmaxf(mx, sc[r*N_+m]);
        #pragma unroll
        for (int o=16;o>0;o>>=1) mx = fmaxf(mx, __shfl_xor_sync(0xffffffffu, mx, o));
        float sum = 0.f;
        for (int m = lane; m < N_; m += 32) {
            const float e = __expf(sc[r*N_+m] - mx);
            sc[r*N_+m] = e;
            sum += e;
        }
        #pragma unroll
        for (int o=16;o>0;o>>=1) sum += __shfl_xor_sync(0xffffffffu, sum, o);
        const float inv = 1.f / sum;
        if (n < N_) {
            __nv_bfloat16* dH = g_attn_hi + ((size_t)b*N_ + n)*HM_ + (size_t)h*N_;
            __nv_bfloat16* dL = g_attn_lo + ((size_t)b*N_ + n)*HM_ + (size_t)h*N_;
            for (int m = lane; m < N_; m += 32) {
                const float v = sc[r*N_+m]*inv;
                __nv_bfloat16 hi, lo;
                bf16_split(v, hi, lo);
                dH[m] = hi; dL[m] = lo;
            }
        }
    }
}

// ---------------------------------------------------------------------------
// Kernel C: msg GEMM (SIMT, proven). M=128000 (r=(b*32+t)*500+m), K=128,
// Ncols=256 (h,u). Epilogue: bf16 hi/lo TRANSPOSED msgT[b][t*64+u][h*500+m]
// ---------------------------------------------------------------------------
__global__ __launch_bounds__(256, 2)
void msg_gemm(const float* __restrict__ curr,
              const float* __restrict__ Wmsg)
{
    const int rowBase = blockIdx.x * 128;
    const int colBase = blockIdx.y * 128;

    __shared__ float As[2][8][132];
    __shared__ float Bs[2][8][128];

    const int tid  = threadIdx.x;
    const int aRow = tid >> 1;
    const int aK   = (tid & 1) * 4;
    const int bK   = tid >> 5;
    const int bCol = (tid & 31) * 4;
    const int tx   = tid & 15;
    const int ty   = tid >> 4;

    const float* aPtr = curr + (size_t)(rowBase + aRow) * DC_ + aK;

    const int cB = colBase + bCol;
    const int hB = cB >> 6;
    const int uB = cB & 63;
    const float* bPtr = Wmsg + hB * (DC_*U_) + bK * U_ + uB;

    const int KSTEPS = DC_ / 8;  // 16

    float4 aReg = *(const float4*)aPtr;
    float4 bReg = *(const float4*)bPtr;

    As[0][aK+0][aRow] = aReg.x; As[0][aK+1][aRow] = aReg.y;
    As[0][aK+2][aRow] = aReg.z; As[0][aK+3][aRow] = aReg.w;
    *(float4*)&Bs[0][bK][bCol] = bReg;
    __syncthreads();

    float acc[2][2][4][4] = {};

    for (int ks = 0; ks < KSTEPS; ks++) {
        const int cur = ks & 1;
        if (ks + 1 < KSTEPS) {
            aReg = *(const float4*)(aPtr + (ks+1)*8);
            bReg = *(const float4*)(bPtr + (ks+1)*8*U_);
        }
        #pragma unroll
        for (int kk = 0; kk < 8; kk++) {
            float ar[2][4], br[2][4];
            *(float4*)ar[0] = *(const float4*)&As[cur][kk][ty*4];
            *(float4*)ar[1] = *(const float4*)&As[cur][kk][ty*4 + 64];
            *(float4*)br[0] = *(const float4*)&Bs[cur][kk][tx*4];
            *(float4*)br[1] = *(const float4*)&Bs[cur][kk][tx*4 + 64];
            #pragma unroll
            for (int rg=0; rg<2; rg++)
              #pragma unroll
              for (int cg=0; cg<2; cg++)
                #pragma unroll
                for (int i=0;i<4;i++)
                  #pragma unroll
                  for (int j=0;j<4;j++)
                    acc[rg][cg][i][j] = fmaf(ar[rg][i], br[cg][j], acc[rg][cg][i][j]);
        }
        if (ks + 1 < KSTEPS) {
            const int nxt = cur ^ 1;
            As[nxt][aK+0][aRow] = aReg.x; As[nxt][aK+1][aRow] = aReg.y;
            As[nxt][aK+2][aRow] = aReg.z; As[nxt][aK+3][aRow] = aReg.w;
            *(float4*)&Bs[nxt][bK][bCol] = bReg;
            __syncthreads();
        }
    }

    // Transposed bf16 hi/lo epilogue (4 consecutive m per thread quad; 500%4==0)
    #pragma unroll
    for (int rg=0; rg<2; rg++) {
        const int r0 = rowBase + ty*4 + rg*64;
        const int bb  = r0 / (T_*N_);
        const int rem = r0 - bb*(T_*N_);
        const int t   = rem / N_;
        const int m   = rem - t*N_;
        #pragma unroll
        for (int cg=0; cg<2; cg++) {
            #pragma unroll
            for (int j=0;j<4;j++) {
                const int c = colBase + tx*4 + cg*64 + j;
                const int h = c >> 6;
                const int u = c & 63;
                const size_t off = ((size_t)bb*TU_ + t*U_ + u)*HM_ + (size_t)h*N_ + m;
                union { __nv_bfloat16 x[4]; uint2 v; } ph, pl;
                #pragma unroll
                for (int i=0;i<4;i++) {
                    __nv_bfloat16 hi, lo;
                    bf16_split(acc[rg][cg][i][j], hi, lo);
                    ph.x[i] = hi; pl.x[i] = lo;
                }
                *(uint2*)&g_msgT_hi[off] = ph.v;
                *(uint2*)&g_msgT_lo[off] = pl.v;
            }
        }
    }
}

// ---------------------------------------------------------------------------
// Kernel D: mix GEMM via mma.sync (HMMA bf16, split precision), 2 CTAs/SM.
// Per (Mtile 128, Ntile 128, b): C = Ah*Bh + Ah*Bl + Al*Bh  (fp32 acc)
// cp.async double buffer, KC=32; ldmatrix from 80B-strided smem rows.
// ---------------------------------------------------------------------------
#define MIX_KC    32
#define MIX_NCH   63          // ceil(2000/32), zero-filled to 2016
#define MRS       80          // smem row stride bytes
#define MTILE     10240       // 128 rows * 80B
#define MSTAGE    (4*MTILE)   // Ah, Al, Bh, Bl
#define MSM_TOTAL (2*MSTAGE)  // 81920

__device__ __forceinline__ void mix_load_chunk(
    uint32_t sstage, int kc, int tid, int b, int mBase, int nBase)
{
    const __nv_bfloat16* Ah = g_attn_hi + (size_t)b * N_ * HM_;
    const __nv_bfloat16* Al = g_attn_lo + (size_t)b * N_ * HM_;
    const __nv_bfloat16* Bh = g_msgT_hi + (size_t)b * TU_ * HM_;
    const __nv_bfloat16* Bl = g_msgT_lo + (size_t)b * TU_ * HM_;
    #pragma unroll
    for (int i = 0; i < 8; i++) {
        const int g    = tid + i*256;       // 0..2047
        const int tile = g >> 9;            // 0:Ah 1:Al 2:Bh 3:Bl
        const int rem  = g & 511;
        const int row  = rem >> 2;
        const int seg  = rem & 3;
        const int k    = kc + seg*8;
        const uint32_t dst = sstage + tile*MTILE + row*MRS + seg*16;
        if (tile < 2) {
            const int n = mBase + row;
            const bool ok = (n < N_) && (k < HM_);
            const __nv_bfloat16* base = tile ? Al : Ah;
            cp16(dst, base + (ok ? ((size_t)n*HM_ + k) : 0), ok);
        } else {
            const bool ok = (k < HM_);
            const __nv_bfloat16* base = (tile == 3) ? Bl : Bh;
            cp16(dst, base + (ok ? ((size_t)(nBase + row)*HM_ + k) : 0), ok);
        }
    }
    cp_commit();
}

__global__ __launch_bounds__(256, 2)
void mix_mma(float* __restrict__ out)
{
    extern __shared__ __align__(128) char smx[];
    const uint32_t sbase = smem_u32(smx);
    const int tid  = threadIdx.x;
    const int wid  = tid >> 5;
    const int lane = tid & 31;
    const int b     = blockIdx.z;
    const int mBase = blockIdx.x * 128;
    const int nBase = blockIdx.y * 128;

    const int wm = wid & 1;       // m band (2 x 64)
    const int wn = wid >> 1;      // n band (4 x 32)

    const uint32_t aRowOff = (lane & 7) + ((lane >> 3) & 1) * 8;
    const uint32_t aSegOff = (lane >> 4) * 16;
    const uint32_t bRowOff = (lane & 7) + (lane >> 4) * 8;
    const uint32_t bSegOff = ((lane >> 3) & 1) * 16;

    float acc[4][4][4] = {};   // [mt][nt][4]

    mix_load_chunk(sbase, 0, tid, b, mBase, nBase);

    for (int c = 0; c < MIX_NCH; c++) {
        if (c + 1 < MIX_NCH) {
            mix_load_chunk(sbase + ((c+1) & 1)*MSTAGE, (c+1)*MIX_KC, tid, b, mBase, nBase);
            cp_wait<1>();
        } else {
            cp_wait<0>();
        }
        __syncthreads();

        const uint32_t sA = sbase + (c & 1)*MSTAGE;
        const uint32_t sB = sA + 2*MTILE;

        #pragma unroll
        for (int k16 = 0; k16 < 2; k16++) {
            const uint32_t kb = k16*32;
            uint32_t bh[2][4], bl[2][4];
            #pragma unroll
            for (int p = 0; p < 2; p++) {
                const uint32_t addr = sB + (wn*32 + p*16 + bRowOff)*MRS + kb + bSegOff;
                ldsm_x4(bh[p], addr);
                ldsm_x4(bl[p], addr + MTILE);
            }
            #pragma unroll
            for (int mt = 0; mt < 4; mt++) {
                const uint32_t aaddr = sA + (wm*64 + mt*16 + aRowOff)*MRS + kb + aSegOff;
                uint32_t a[4], a2[4];
                ldsm_x4(a, aaddr);
                ldsm_x4(a2, aaddr + MTILE);
                #pragma unroll
                for (int nt = 0; nt < 4; nt++) {
                    const uint32_t* ph = &bh[nt >> 1][(nt & 1)*2];
                    const uint32_t* pl = &bl[nt >> 1][(nt & 1)*2];
                    mma16816(acc[mt][nt], a,  ph);
                    mma16816(acc[mt][nt], a,  pl);
                    mma16816(acc[mt][nt], a2, ph);
                }
            }
        }
        __syncthreads();
    }

    // Epilogue
    const int r0 = mBase + wm*64 + (lane >> 2);
    const int c0 = nBase + wn*32 + (lane & 3)*2;
    #pragma unroll
    for (int mt = 0; mt < 4; mt++) {
        #pragma unroll
        for (int half = 0; half < 2; half++) {
            const int n = r0 + mt*16 + half*8;
            if (n < N_) {
                #pragma unroll
                for (int nt = 0; nt < 4; nt++) {
                    const int cc = c0 + nt*8;
                    const int t  = cc >> 6;
                    const int u  = cc & 63;
                    float2 v = make_float2(acc[mt][nt][half*2+0]*0.25f,
                                           acc[mt][nt][half*2+1]*0.25f);
                    *(float2*)&out[(((size_t)b*T_ + t)*N_ + n)*U_ + u] = v;
                }
            }
        }
    }
}

// ---------------------------------------------------------------------------
extern "C" void kernel_launch(void* const* d_in, const int* in_sizes, int n_in,
                              void* d_out, int out_size)
{
    const float* prev = (const float*)d_in[0];   // [8,500,200]
    const float* curr = (const float*)d_in[1];   // [8,32,500,128]
    const float* Wsrc = (const float*)d_in[2];   // [4,200,64]
    const float* Wdst = (const float*)d_in[3];   // [4,200,64]
    const float* aV   = (const float*)d_in[4];   // [4,64,1]
    const float* Wmsg = (const float*)d_in[5];   // [4,128,64]
    float* out = (float*)d_out;                  // [8,32,500,64]

    // A: projections  (M=4000, N=512, K=200)
    proj_gemm<<<dim3(32, 4), 256>>>(prev, Wsrc, Wdst);

    // B: scores + softmax -> bf16 hi/lo attn
    const size_t shB = (size_t)(512*65 + 16*64 + 128 + 16*500) * sizeof(float);
    cudaFuncSetAttribute(score_softmax_kernel,
                         cudaFuncAttributeMaxDynamicSharedMemorySize, (int)shB);
    score_softmax_kernel<<<dim3(32, 32), 256, shB>>>(aV);

    // C: msg GEMM (SIMT) -> transposed bf16 hi/lo msgT
    msg_gemm<<<dim3(1000, 2), 256>>>(curr, Wmsg);

    // D: mix GEMM on tensor cores (per batch: M=500, N=2048, K=2000), 2 CTAs/SM
    cudaFuncSetAttribute(mix_mma,
                         cudaFuncAttributeMaxDynamicSharedMemorySize, MSM_TOTAL);
    mix_mma<<<dim3(4, 16, 8), 256, MSM_TOTAL>>>(out);
}

// round 10
// speedup vs baseline: 1.7753x; 1.2085x over previous
#include <cuda_runtime.h>
#include <cuda_bf16.h>
#include <cuda_fp16.h>
#include <cstdint>
#include <cstddef>

// Problem constants
#define B_   8
#define T_   32
#define N_   500
#define DP_  200
#define DC_  128
#define H_   4
#define U_   64
#define HM_  2000   // H_*N_  (K dim of mix GEMM)
#define TU_  2048   // T_*U_  (N dim of mix GEMM)

// Scratch (device globals: allocation-free rule)
__device__ float g_S[B_*H_*N_*U_];                    // [b][h][n][u]
__device__ float g_D[B_*H_*N_*U_];                    // [b][h][m][u]
__device__ __half g_attn_hi[(size_t)B_*N_*HM_];       // [b][n][hm]
__device__ __half g_attn_lo[(size_t)B_*N_*HM_];       // [b][n][hm]
__device__ __half g_msgT[(size_t)B_*TU_*HM_];         // [b][tu][hm] single fp16

// ---------------------------------------------------------------------------
// Helpers (compute_103-safe: cp.async / ldmatrix / mma.sync)
// ---------------------------------------------------------------------------
__device__ __forceinline__ uint32_t smem_u32(const void* p) {
    uint32_t a;
    asm("{ .reg .u64 t; cvta.to.shared.u64 t, %1; cvt.u32.u64 %0, t; }" : "=r"(a) : "l"(p));
    return a;
}
__device__ __forceinline__ void cp16(uint32_t dst, const void* src, bool ok) {
    int sz = ok ? 16 : 0;   // src-size 0 => zero-fill 16B
    asm volatile("cp.async.cg.shared.global [%0], [%1], 16, %2;" :: "r"(dst), "l"(src), "r"(sz) : "memory");
}
__device__ __forceinline__ void cp_commit() {
    asm volatile("cp.async.commit_group;" ::: "memory");
}
template <int NW>
__device__ __forceinline__ void cp_wait() {
    asm volatile("cp.async.wait_group %0;" :: "n"(NW) : "memory");
}
__device__ __forceinline__ void ldsm_x4(uint32_t* r, uint32_t addr) {
    asm volatile("ldmatrix.sync.aligned.m8n8.x4.shared.b16 {%0,%1,%2,%3}, [%4];"
                 : "=r"(r[0]), "=r"(r[1]), "=r"(r[2]), "=r"(r[3]) : "r"(addr));
}
// fp16 MMA, fp32 accumulate
__device__ __forceinline__ void mma16816h(float* c, const uint32_t* a, const uint32_t* b) {
    asm volatile(
        "mma.sync.aligned.m16n8k16.row.col.f32.f16.f16.f32 "
        "{%0,%1,%2,%3}, {%4,%5,%6,%7}, {%8,%9}, {%0,%1,%2,%3};"
        : "+f"(c[0]), "+f"(c[1]), "+f"(c[2]), "+f"(c[3])
        : "r"(a[0]), "r"(a[1]), "r"(a[2]), "r"(a[3]), "r"(b[0]), "r"(b[1]));
}
__device__ __forceinline__ void f16_split(float v, __half& hi, __half& lo) {
    hi = __float2half_rn(v);
    lo = __float2half_rn(v - __half2float(hi));
}

// ---------------------------------------------------------------------------
// Kernel A: projections.  GEMM M=4000 (b*500+n), K=200, Ncols=512
// ---------------------------------------------------------------------------
__global__ __launch_bounds__(256, 2)
void proj_gemm(const float* __restrict__ prev,
               const float* __restrict__ Wsrc,
               const float* __restrict__ Wdst)
{
    const int rowBase = blockIdx.x * 128;
    const int colBase = blockIdx.y * 128;

    __shared__ float As[2][8][132];
    __shared__ float Bs[2][8][128];

    const int tid  = threadIdx.x;
    const int aRow = tid >> 1;
    const int aK   = (tid & 1) * 4;
    const int bK   = tid >> 5;
    const int bCol = (tid & 31) * 4;
    const int tx   = tid & 15;
    const int ty   = tid >> 4;

    const int gRow  = rowBase + aRow;
    const bool rowOk = gRow < 4000;
    const float* aPtr = prev + (size_t)gRow * DP_ + aK;

    const int cB   = colBase + bCol;
    const int matB = cB >> 8;
    const int hB   = (cB >> 6) & 3;
    const int uB   = cB & 63;
    const float* bPtr = (matB ? Wdst : Wsrc) + hB * (DP_*U_) + bK * U_ + uB;

    const int KSTEPS = DP_ / 8;  // 25

    float4 aReg = rowOk ? *(const float4*)aPtr : make_float4(0,0,0,0);
    float4 bReg = *(const float4*)bPtr;

    As[0][aK+0][aRow] = aReg.x; As[0][aK+1][aRow] = aReg.y;
    As[0][aK+2][aRow] = aReg.z; As[0][aK+3][aRow] = aReg.w;
    *(float4*)&Bs[0][bK][bCol] = bReg;
    __syncthreads();

    float acc[2][2][4][4] = {};

    for (int ks = 0; ks < KSTEPS; ks++) {
        const int cur = ks & 1;
        if (ks + 1 < KSTEPS) {
            aReg = rowOk ? *(const float4*)(aPtr + (ks+1)*8) : make_float4(0,0,0,0);
            bReg = *(const float4*)(bPtr + (ks+1)*8*U_);
        }
        #pragma unroll
        for (int kk = 0; kk < 8; kk++) {
            float ar[2][4], br[2][4];
            *(float4*)ar[0] = *(const float4*)&As[cur][kk][ty*4];
            *(float4*)ar[1] = *(const float4*)&As[cur][kk][ty*4 + 64];
            *(float4*)br[0] = *(const float4*)&Bs[cur][kk][tx*4];
            *(float4*)br[1] = *(const float4*)&Bs[cur][kk][tx*4 + 64];
            #pragma unroll
            for (int rg=0; rg<2; rg++)
              #pragma unroll
              for (int cg=0; cg<2; cg++)
                #pragma unroll
                for (int i=0;i<4;i++)
                  #pragma unroll
                  for (int j=0;j<4;j++)
                    acc[rg][cg][i][j] = fmaf(ar[rg][i], br[cg][j], acc[rg][cg][i][j]);
        }
        if (ks + 1 < KSTEPS) {
            const int nxt = cur ^ 1;
            As[nxt][aK+0][aRow] = aReg.x; As[nxt][aK+1][aRow] = aReg.y;
            As[nxt][aK+2][aRow] = aReg.z; As[nxt][aK+3][aRow] = aReg.w;
            *(float4*)&Bs[nxt][bK][bCol] = bReg;
            __syncthreads();
        }
    }

    #pragma unroll
    for (int rg=0; rg<2; rg++) {
        #pragma unroll
        for (int i=0;i<4;i++) {
            const int r = rowBase + ty*4 + rg*64 + i;
            if (r < 4000) {
                const int b = r / N_;
                const int n = r - b * N_;
                #pragma unroll
                for (int cg=0; cg<2; cg++) {
                    const int c = colBase + tx*4 + cg*64;
                    const int mat = c >> 8;
                    const int h   = (c >> 6) & 3;
                    const int u   = c & 63;
                    float* dst = (mat ? g_D : g_S) + ((size_t)(b*H_ + h)*N_ + n)*U_ + u;
                    float4 v = make_float4(acc[rg][cg][i][0], acc[rg][cg][i][1],
                                           acc[rg][cg][i][2], acc[rg][cg][i][3]);
                    *(float4*)dst = v;
                }
            }
        }
    }
}

// ---------------------------------------------------------------------------
// Kernel B: GATv2 scores + softmax -> attn written as fp16 hi/lo [b][n][hm]
// ---------------------------------------------------------------------------
__global__ __launch_bounds__(256)
void score_softmax_kernel(const float* __restrict__ aVec)
{
    extern __shared__ float sh[];
    float* Dsh = sh;                     // 512*65
    float* Ssh = Dsh + 512*65;           // 16*64
    float* aSh = Ssh + 16*64;            // 64 (+64 pad)
    float* sc  = aSh + 128;              // 16*500

    const int bh = blockIdx.y;           // b*4 + h
    const int b  = bh >> 2;
    const int h  = bh & 3;
    const int nBase = blockIdx.x * 16;
    const int tid = threadIdx.x;

    const float* Dg = g_D + (size_t)bh * N_ * U_;
    const float* Sg = g_S + (size_t)bh * N_ * U_;

    for (int idx = tid; idx < 512*16; idx += 256) {
        const int m = idx >> 4;
        const int u = (idx & 15) * 4;
        float4 v = (m < N_) ? *(const float4*)(Dg + m*U_ + u) : make_float4(0,0,0,0);
        float* dst = &Dsh[m*65 + u];
        dst[0]=v.x; dst[1]=v.y; dst[2]=v.z; dst[3]=v.w;
    }
    for (int idx = tid; idx < 16*16; idx += 256) {
        const int r = idx >> 4;
        const int u = (idx & 15) * 4;
        const int n = nBase + r;
        float4 v = (n < N_) ? *(const float4*)(Sg + n*U_ + u) : make_float4(0,0,0,0);
        float* dst = &Ssh[r*U_ + u];
        dst[0]=v.x; dst[1]=v.y; dst[2]=v.z; dst[3]=v.w;
    }
    if (tid < 64) aSh[tid] = aVec[h*U_ + tid];
    __syncthreads();

    const int tx  = tid & 63;
    const int tyy = tid >> 6;

    float acc[4][8];
    #pragma unroll
    for (int i=0;i<4;i++)
        #pragma unroll
        for (int k=0;k<8;k++) acc[i][k]=0.f;

    for (int u = 0; u < U_; u++) {
        const float au = aSh[u];
        float s[4];
        #pragma unroll
        for (int i=0;i<4;i++) s[i] = Ssh[(tyy*4+i)*U_ + u];
        #pragma unroll
        for (int k=0;k<8;k++) {
            const float d = Dsh[(tx + 64*k)*65 + u];
            #pragma unroll
            for (int i=0;i<4;i++) {
                const float t  = s[i] + d;
                const float lr = fmaxf(t, 0.2f * t);
                acc[i][k] = fmaf(au, lr, acc[i][k]);
            }
        }
    }
    #pragma unroll
    for (int i=0;i<4;i++)
        #pragma unroll
        for (int k=0;k<8;k++) {
            const int m = tx + 64*k;
            if (m < N_) sc[(tyy*4+i)*N_ + m] = acc[i][k];
        }
    __syncthreads();

    const int warp = tid >> 5, lane = tid & 31;
    #pragma unroll
    for (int rr = 0; rr < 2; rr++) {
        const int r = warp*2 + rr;
        const int n = nBase + r;
        float mx = -1e30f;
        for (int m = lane; m < N_; m += 32) mx = fmaxf(mx, sc[r*N_+m]);
        #pragma unroll
        for (int o=16;o>0;o>>=1) mx = fmaxf(mx, __shfl_xor_sync(0xffffffffu, mx, o));
        float sum = 0.f;
        for (int m = lane; m < N_; m += 32) {
            const float e = __expf(sc[r*N_+m] - mx);
            sc[r*N_+m] = e;
            sum += e;
        }
        #pragma unroll
        for (int o=16;o>0;o>>=1) sum += __shfl_xor_sync(0xffffffffu, sum, o);
        const float inv = 1.f / sum;
        if (n < N_) {
            __half* dH = g_attn_hi + ((size_t)b*N_ + n)*HM_ + (size_t)h*N_;
            __half* dL = g_attn_lo + ((size_t)b*N_ + n)*HM_ + (size_t)h*N_;
            for (int m = lane; m < N_; m += 32) {
                const float v = sc[r*N_+m]*inv;
                __half hi, lo;
                f16_split(v, hi, lo);
                dH[m] = hi; dL[m] = lo;
            }
        }
    }
}

// ---------------------------------------------------------------------------
// Kernel C: msg GEMM (SIMT). M=128000 (r=(b*32+t)*500+m), K=128,
// Ncols=256 (h,u). Epilogue: single fp16 TRANSPOSED msgT[b][t*64+u][h*500+m]
// ---------------------------------------------------------------------------
__global__ __launch_bounds__(256, 2)
void msg_gemm(const float* __restrict__ curr,
              const float* __restrict__ Wmsg)
{
    const int rowBase = blockIdx.x * 128;
    const int colBase = blockIdx.y * 128;

    __shared__ float As[2][8][132];
    __shared__ float Bs[2][8][128];

    const int tid  = threadIdx.x;
    const int aRow = tid >> 1;
    const int aK   = (tid & 1) * 4;
    const int bK   = tid >> 5;
    const int bCol = (tid & 31) * 4;
    const int tx   = tid & 15;
    const int ty   = tid >> 4;

    const float* aPtr = curr + (size_t)(rowBase + aRow) * DC_ + aK;

    const int cB = colBase + bCol;
    const int hB = cB >> 6;
    const int uB = cB & 63;
    const float* bPtr = Wmsg + hB * (DC_*U_) + bK * U_ + uB;

    const int KSTEPS = DC_ / 8;  // 16

    float4 aReg = *(const float4*)aPtr;
    float4 bReg = *(const float4*)bPtr;

    As[0][aK+0][aRow] = aReg.x; As[0][aK+1][aRow] = aReg.y;
    As[0][aK+2][aRow] = aReg.z; As[0][aK+3][aRow] = aReg.w;
    *(float4*)&Bs[0][bK][bCol] = bReg;
    __syncthreads();

    float acc[2][2][4][4] = {};

    for (int ks = 0; ks < KSTEPS; ks++) {
        const int cur = ks & 1;
        if (ks + 1 < KSTEPS) {
            aReg = *(const float4*)(aPtr + (ks+1)*8);
            bReg = *(const float4*)(bPtr + (ks+1)*8*U_);
        }
        #pragma unroll
        for (int kk = 0; kk < 8; kk++) {
            float ar[2][4], br[2][4];
            *(float4*)ar[0] = *(const float4*)&As[cur][kk][ty*4];
            *(float4*)ar[1] = *(const float4*)&As[cur][kk][ty*4 + 64];
            *(float4*)br[0] = *(const float4*)&Bs[cur][kk][tx*4];
            *(float4*)br[1] = *(const float4*)&Bs[cur][kk][tx*4 + 64];
            #pragma unroll
            for (int rg=0; rg<2; rg++)
              #pragma unroll
              for (int cg=0; cg<2; cg++)
                #pragma unroll
                for (int i=0;i<4;i++)
                  #pragma unroll
                  for (int j=0;j<4;j++)
                    acc[rg][cg][i][j] = fmaf(ar[rg][i], br[cg][j], acc[rg][cg][i][j]);
        }
        if (ks + 1 < KSTEPS) {
            const int nxt = cur ^ 1;
            As[nxt][aK+0][aRow] = aReg.x; As[nxt][aK+1][aRow] = aReg.y;
            As[nxt][aK+2][aRow] = aReg.z; As[nxt][aK+3][aRow] = aReg.w;
            *(float4*)&Bs[nxt][bK][bCol] = bReg;
            __syncthreads();
        }
    }

    // Transposed fp16 epilogue (4 consecutive m per thread quad; 500%4==0)
    #pragma unroll
    for (int rg=0; rg<2; rg++) {
        const int r0 = rowBase + ty*4 + rg*64;
        const int bb  = r0 / (T_*N_);
        const int rem = r0 - bb*(T_*N_);
        const int t   = rem / N_;
        const int m   = rem - t*N_;
        #pragma unroll
        for (int cg=0; cg<2; cg++) {
            #pragma unroll
            for (int j=0;j<4;j++) {
                const int c = colBase + tx*4 + cg*64 + j;
                const int h = c >> 6;
                const int u = c & 63;
                const size_t off = ((size_t)bb*TU_ + t*U_ + u)*HM_ + (size_t)h*N_ + m;
                union { __half x[4]; uint2 v; } p;
                #pragma unroll
                for (int i=0;i<4;i++) p.x[i] = __float2half_rn(acc[rg][cg][i][j]);
                *(uint2*)&g_msgT[off] = p.v;
            }
        }
    }
}

// ---------------------------------------------------------------------------
// Kernel D: mix GEMM via mma.sync (fp16, A split / B single), 2 CTAs/SM,
// 3-stage cp.async pipeline.
// Per (Mtile 128, Ntile 128, b): C = Ah*B + Al*B  (fp32 acc)
// ---------------------------------------------------------------------------
#define MIX_KC    32
#define MIX_NCH   63          // ceil(2000/32), zero-filled to 2016
#define MRS       80          // smem row stride bytes (64B data + 16B pad)
#define MTILE     10240       // 128 rows * 80B
#define MSTAGE    (3*MTILE)   // Ah, Al, B  = 30720
#define MNSTG     3
#define MSM_TOTAL (MNSTG*MSTAGE)  // 92160

__device__ __forceinline__ void mix_load_chunk(
    uint32_t sstage, int kc, int tid, int b, int mBase, int nBase)
{
    const __half* Ah = g_attn_hi + (size_t)b * N_ * HM_;
    const __half* Al = g_attn_lo + (size_t)b * N_ * HM_;
    const __half* Bm = g_msgT   + (size_t)b * TU_ * HM_;
    #pragma unroll
    for (int i = 0; i < 6; i++) {
        const int g    = tid + i*256;       // 0..1535
        const int tile = g >> 9;            // 0:Ah 1:Al 2:B
        const int rem  = g & 511;
        const int row  = rem >> 2;
        const int seg  = rem & 3;
        const int k    = kc + seg*8;
        const uint32_t dst = sstage + tile*MTILE + row*MRS + seg*16;
        if (tile < 2) {
            const int n = mBase + row;
            const bool ok = (n < N_) && (k < HM_);
            const __half* base = tile ? Al : Ah;
            cp16(dst, base + (ok ? ((size_t)n*HM_ + k) : 0), ok);
        } else {
            const bool ok = (k < HM_);
            cp16(dst, Bm + (ok ? ((size_t)(nBase + row)*HM_ + k) : 0), ok);
        }
    }
    cp_commit();
}

__global__ __launch_bounds__(256, 2)
void mix_mma(float* __restrict__ out)
{
    extern __shared__ __align__(128) char smx[];
    const uint32_t sbase = smem_u32(smx);
    const int tid  = threadIdx.x;
    const int wid  = tid >> 5;
    const int lane = tid & 31;
    const int b     = blockIdx.z;
    const int mBase = blockIdx.x * 128;
    const int nBase = blockIdx.y * 128;

    const int wm = wid & 1;       // m band (2 x 64)
    const int wn = wid >> 1;      // n band (4 x 32)

    const uint32_t aRowOff = (lane & 7) + ((lane >> 3) & 1) * 8;
    const uint32_t aSegOff = (lane >> 4) * 16;
    const uint32_t bRowOff = (lane & 7) + (lane >> 4) * 8;
    const uint32_t bSegOff = ((lane >> 3) & 1) * 16;

    float acc[4][4][4] = {};   // [mt][nt][4]

    mix_load_chunk(sbase + 0*MSTAGE, 0*MIX_KC, tid, b, mBase, nBase);
    mix_load_chunk(sbase + 1*MSTAGE, 1*MIX_KC, tid, b, mBase, nBase);

    int sc = 0;
    for (int c = 0; c < MIX_NCH; c++) {
        if (c + 2 < MIX_NCH) {
            const int ns = (sc + 2 >= MNSTG) ? sc + 2 - MNSTG : sc + 2;
            mix_load_chunk(sbase + ns*MSTAGE, (c+2)*MIX_KC, tid, b, mBase, nBase);
            cp_wait<2>();
        } else if (c + 1 < MIX_NCH) {
            cp_wait<1>();
        } else {
            cp_wait<0>();
        }
        __syncthreads();

        const uint32_t sA = sbase + sc*MSTAGE;
        const uint32_t sB = sA + 2*MTILE;

        #pragma unroll
        for (int k16 = 0; k16 < 2; k16++) {
            const uint32_t kb = k16*32;
            uint32_t bb[2][4];
            #pragma unroll
            for (int p = 0; p < 2; p++) {
                ldsm_x4(bb[p], sB + (wn*32 + p*16 + bRowOff)*MRS + kb + bSegOff);
            }
            #pragma unroll
            for (int mt = 0; mt < 4; mt++) {
                const uint32_t aaddr = sA + (wm*64 + mt*16 + aRowOff)*MRS + kb + aSegOff;
                uint32_t a[4], a2[4];
                ldsm_x4(a, aaddr);
                ldsm_x4(a2, aaddr + MTILE);
                #pragma unroll
                for (int nt = 0; nt < 4; nt++) {
                    const uint32_t* pb = &bb[nt >> 1][(nt & 1)*2];
                    mma16816h(acc[mt][nt], a,  pb);
                    mma16816h(acc[mt][nt], a2, pb);
                }
            }
        }
        __syncthreads();
        sc = (sc + 1 >= MNSTG) ? 0 : sc + 1;
    }

    // Epilogue
    const int r0 = mBase + wm*64 + (lane >> 2);
    const int c0 = nBase + wn*32 + (lane & 3)*2;
    #pragma unroll
    for (int mt = 0; mt < 4; mt++) {
        #pragma unroll
        for (int half = 0; half < 2; half++) {
            const int n = r0 + mt*16 + half*8;
            if (n < N_) {
                #pragma unroll
                for (int nt = 0; nt < 4; nt++) {
                    const int cc = c0 + nt*8;
                    const int t  = cc >> 6;
                    const int u  = cc & 63;
                    float2 v = make_float2(acc[mt][nt][half*2+0]*0.25f,
                                           acc[mt][nt][half*2+1]*0.25f);
                    *(float2*)&out[(((size_t)b*T_ + t)*N_ + n)*U_ + u] = v;
                }
            }
        }
    }
}

// ---------------------------------------------------------------------------
extern "C" void kernel_launch(void* const* d_in, const int* in_sizes, int n_in,
                              void* d_out, int out_size)
{
    const float* prev = (const float*)d_in[0];   // [8,500,200]
    const float* curr = (const float*)d_in[1];   // [8,32,500,128]
    const float* Wsrc = (const float*)d_in[2];   // [4,200,64]
    const float* Wdst = (const float*)d_in[3];   // [4,200,64]
    const float* aV   = (const float*)d_in[4];   // [4,64,1]
    const float* Wmsg = (const float*)d_in[5];   // [4,128,64]
    float* out = (float*)d_out;                  // [8,32,500,64]

    // A: projections  (M=4000, N=512, K=200)
    proj_gemm<<<dim3(32, 4), 256>>>(prev, Wsrc, Wdst);

    // B: scores + softmax -> fp16 hi/lo attn
    const size_t shB = (size_t)(512*65 + 16*64 + 128 + 16*500) * sizeof(float);
    cudaFuncSetAttribute(score_softmax_kernel,
                         cudaFuncAttributeMaxDynamicSharedMemorySize, (int)shB);
    score_softmax_kernel<<<dim3(32, 32), 256, shB>>>(aV);

    // C: msg GEMM (SIMT) -> transposed single-fp16 msgT
    msg_gemm<<<dim3(1000, 2), 256>>>(curr, Wmsg);

    // D: mix GEMM on tensor cores (per batch: M=500, N=2048, K=2000), 2 CTAs/SM
    cudaFuncSetAttribute(mix_mma,
                         cudaFuncAttributeMaxDynamicSharedMemorySize, MSM_TOTAL);
    mix_mma<<<dim3(4, 16, 8), 256, MSM_TOTAL>>>(out);
}

// round 11
// speedup vs baseline: 1.8133x; 1.0214x over previous
#include <cuda_runtime.h>
#include <cuda_bf16.h>
#include <cuda_fp16.h>
#include <cstdint>
#include <cstddef>

// Problem constants
#define B_   8
#define T_   32
#define N_   500
#define DP_  200
#define DC_  128
#define H_   4
#define U_   64
#define HM_  2000   // H_*N_  (K dim of mix GEMM)
#define TU_  2048   // T_*U_  (N dim of mix GEMM)

// Scratch (device globals: allocation-free rule)
__device__ float g_S[B_*H_*N_*U_];                    // [b][h][n][u]
__device__ float g_D[B_*H_*N_*U_];                    // [b][h][m][u]
__device__ __half g_attn_hi[(size_t)B_*N_*HM_];       // [b][n][hm]
__device__ __half g_attn_lo[(size_t)B_*N_*HM_];       // [b][n][hm]
__device__ __half g_msgT[(size_t)B_*TU_*HM_];         // [b][tu][hm] single fp16

// ---------------------------------------------------------------------------
// Helpers (compute_103-safe: cp.async / ldmatrix / mma.sync)
// ---------------------------------------------------------------------------
__device__ __forceinline__ uint32_t smem_u32(const void* p) {
    uint32_t a;
    asm("{ .reg .u64 t; cvta.to.shared.u64 t, %1; cvt.u32.u64 %0, t; }" : "=r"(a) : "l"(p));
    return a;
}
__device__ __forceinline__ void cp16(uint32_t dst, const void* src, bool ok) {
    int sz = ok ? 16 : 0;   // src-size 0 => zero-fill 16B
    asm volatile("cp.async.cg.shared.global [%0], [%1], 16, %2;" :: "r"(dst), "l"(src), "r"(sz) : "memory");
}
__device__ __forceinline__ void cp_commit() {
    asm volatile("cp.async.commit_group;" ::: "memory");
}
template <int NW>
__device__ __forceinline__ void cp_wait() {
    asm volatile("cp.async.wait_group %0;" :: "n"(NW) : "memory");
}
__device__ __forceinline__ void ldsm_x4(uint32_t* r, uint32_t addr) {
    asm volatile("ldmatrix.sync.aligned.m8n8.x4.shared.b16 {%0,%1,%2,%3}, [%4];"
                 : "=r"(r[0]), "=r"(r[1]), "=r"(r[2]), "=r"(r[3]) : "r"(addr));
}
// fp16 MMA, fp32 accumulate
__device__ __forceinline__ void mma16816h(float* c, const uint32_t* a, const uint32_t* b) {
    asm volatile(
        "mma.sync.aligned.m16n8k16.row.col.f32.f16.f16.f32 "
        "{%0,%1,%2,%3}, {%4,%5,%6,%7}, {%8,%9}, {%0,%1,%2,%3};"
        : "+f"(c[0]), "+f"(c[1]), "+f"(c[2]), "+f"(c[3])
        : "r"(a[0]), "r"(a[1]), "r"(a[2]), "r"(a[3]), "r"(b[0]), "r"(b[1]));
}
__device__ __forceinline__ void f16_split(float v, __half& hi, __half& lo) {
    hi = __float2half_rn(v);
    lo = __float2half_rn(v - __half2float(hi));
}

// ---------------------------------------------------------------------------
// Kernel A: projections.  GEMM M=4000 (b*500+n), K=200, Ncols=512
// ---------------------------------------------------------------------------
__global__ __launch_bounds__(256, 2)
void proj_gemm(const float* __restrict__ prev,
               const float* __restrict__ Wsrc,
               const float* __restrict__ Wdst)
{
    const int rowBase = blockIdx.x * 128;
    const int colBase = blockIdx.y * 128;

    __shared__ float As[2][8][132];
    __shared__ float Bs[2][8][128];

    const int tid  = threadIdx.x;
    const int aRow = tid >> 1;
    const int aK   = (tid & 1) * 4;
    const int bK   = tid >> 5;
    const int bCol = (tid & 31) * 4;
    const int tx   = tid & 15;
    const int ty   = tid >> 4;

    const int gRow  = rowBase + aRow;
    const bool rowOk = gRow < 4000;
    const float* aPtr = prev + (size_t)gRow * DP_ + aK;

    const int cB   = colBase + bCol;
    const int matB = cB >> 8;
    const int hB   = (cB >> 6) & 3;
    const int uB   = cB & 63;
    const float* bPtr = (matB ? Wdst : Wsrc) + hB * (DP_*U_) + bK * U_ + uB;

    const int KSTEPS = DP_ / 8;  // 25

    float4 aReg = rowOk ? *(const float4*)aPtr : make_float4(0,0,0,0);
    float4 bReg = *(const float4*)bPtr;

    As[0][aK+0][aRow] = aReg.x; As[0][aK+1][aRow] = aReg.y;
    As[0][aK+2][aRow] = aReg.z; As[0][aK+3][aRow] = aReg.w;
    *(float4*)&Bs[0][bK][bCol] = bReg;
    __syncthreads();

    float acc[2][2][4][4] = {};

    for (int ks = 0; ks < KSTEPS; ks++) {
        const int cur = ks & 1;
        if (ks + 1 < KSTEPS) {
            aReg = rowOk ? *(const float4*)(aPtr + (ks+1)*8) : make_float4(0,0,0,0);
            bReg = *(const float4*)(bPtr + (ks+1)*8*U_);
        }
        #pragma unroll
        for (int kk = 0; kk < 8; kk++) {
            float ar[2][4], br[2][4];
            *(float4*)ar[0] = *(const float4*)&As[cur][kk][ty*4];
            *(float4*)ar[1] = *(const float4*)&As[cur][kk][ty*4 + 64];
            *(float4*)br[0] = *(const float4*)&Bs[cur][kk][tx*4];
            *(float4*)br[1] = *(const float4*)&Bs[cur][kk][tx*4 + 64];
            #pragma unroll
            for (int rg=0; rg<2; rg++)
              #pragma unroll
              for (int cg=0; cg<2; cg++)
                #pragma unroll
                for (int i=0;i<4;i++)
                  #pragma unroll
                  for (int j=0;j<4;j++)
                    acc[rg][cg][i][j] = fmaf(ar[rg][i], br[cg][j], acc[rg][cg][i][j]);
        }
        if (ks + 1 < KSTEPS) {
            const int nxt = cur ^ 1;
            As[nxt][aK+0][aRow] = aReg.x; As[nxt][aK+1][aRow] = aReg.y;
            As[nxt][aK+2][aRow] = aReg.z; As[nxt][aK+3][aRow] = aReg.w;
            *(float4*)&Bs[nxt][bK][bCol] = bReg;
            __syncthreads();
        }
    }

    #pragma unroll
    for (int rg=0; rg<2; rg++) {
        #pragma unroll
        for (int i=0;i<4;i++) {
            const int r = rowBase + ty*4 + rg*64 + i;
            if (r < 4000) {
                const int b = r / N_;
                const int n = r - b * N_;
                #pragma unroll
                for (int cg=0; cg<2; cg++) {
                    const int c = colBase + tx*4 + cg*64;
                    const int mat = c >> 8;
                    const int h   = (c >> 6) & 3;
                    const int u   = c & 63;
                    float* dst = (mat ? g_D : g_S) + ((size_t)(b*H_ + h)*N_ + n)*U_ + u;
                    float4 v = make_float4(acc[rg][cg][i][0], acc[rg][cg][i][1],
                                           acc[rg][cg][i][2], acc[rg][cg][i][3]);
                    *(float4*)dst = v;
                }
            }
        }
    }
}

// ---------------------------------------------------------------------------
// Kernel B: GATv2 scores + softmax -> attn written as fp16 hi/lo [b][n][hm]
// ---------------------------------------------------------------------------
__global__ __launch_bounds__(256)
void score_softmax_kernel(const float* __restrict__ aVec)
{
    extern __shared__ float sh[];
    float* Dsh = sh;                     // 512*65
    float* Ssh = Dsh + 512*65;           // 16*64
    float* aSh = Ssh + 16*64;            // 64 (+64 pad)
    float* sc  = aSh + 128;              // 16*500

    const int bh = blockIdx.y;           // b*4 + h
    const int b  = bh >> 2;
    const int h  = bh & 3;
    const int nBase = blockIdx.x * 16;
    const int tid = threadIdx.x;

    const float* Dg = g_D + (size_t)bh * N_ * U_;
    const float* Sg = g_S + (size_t)bh * N_ * U_;

    for (int idx = tid; idx < 512*16; idx += 256) {
        const int m = idx >> 4;
        const int u = (idx & 15) * 4;
        float4 v = (m < N_) ? *(const float4*)(Dg + m*U_ + u) : make_float4(0,0,0,0);
        float* dst = &Dsh[m*65 + u];
        dst[0]=v.x; dst[1]=v.y; dst[2]=v.z; dst[3]=v.w;
    }
    for (int idx = tid; idx < 16*16; idx += 256) {
        const int r = idx >> 4;
        const int u = (idx & 15) * 4;
        const int n = nBase + r;
        float4 v = (n < N_) ? *(const float4*)(Sg + n*U_ + u) : make_float4(0,0,0,0);
        float* dst = &Ssh[r*U_ + u];
        dst[0]=v.x; dst[1]=v.y; dst[2]=v.z; dst[3]=v.w;
    }
    if (tid < 64) aSh[tid] = aVec[h*U_ + tid];
    __syncthreads();

    const int tx  = tid & 63;
    const int tyy = tid >> 6;

    float acc[4][8];
    #pragma unroll
    for (int i=0;i<4;i++)
        #pragma unroll
        for (int k=0;k<8;k++) acc[i][k]=0.f;

    for (int u = 0; u < U_; u++) {
        const float au = aSh[u];
        float s[4];
        #pragma unroll
        for (int i=0;i<4;i++) s[i] = Ssh[(tyy*4+i)*U_ + u];
        #pragma unroll
        for (int k=0;k<8;k++) {
            const float d = Dsh[(tx + 64*k)*65 + u];
            #pragma unroll
            for (int i=0;i<4;i++) {
                const float t  = s[i] + d;
                const float lr = fmaxf(t, 0.2f * t);
                acc[i][k] = fmaf(au, lr, acc[i][k]);
            }
        }
    }
    #pragma unroll
    for (int i=0;i<4;i++)
        #pragma unroll
        for (int k=0;k<8;k++) {
            const int m = tx + 64*k;
            if (m < N_) sc[(tyy*4+i)*N_ + m] = acc[i][k];
        }
    __syncthreads();

    const int warp = tid >> 5, lane = tid & 31;
    #pragma unroll
    for (int rr = 0; rr < 2; rr++) {
        const int r = warp*2 + rr;
        const int n = nBase + r;
        float mx = -1e30f;
        for (int m = lane; m < N_; m += 32) mx = fmaxf(mx, sc[r*N_+m]);
        #pragma unroll
        for (int o=16;o>0;o>>=1) mx = fmaxf(mx, __shfl_xor_sync(0xffffffffu, mx, o));
        float sum = 0.f;
        for (int m = lane; m < N_; m += 32) {
            const float e = __expf(sc[r*N_+m] - mx);
            sc[r*N_+m] = e;
            sum += e;
        }
        #pragma unroll
        for (int o=16;o>0;o>>=1) sum += __shfl_xor_sync(0xffffffffu, sum, o);
        const float inv = 1.f / sum;
        if (n < N_) {
            __half* dH = g_attn_hi + ((size_t)b*N_ + n)*HM_ + (size_t)h*N_;
            __half* dL = g_attn_lo + ((size_t)b*N_ + n)*HM_ + (size_t)h*N_;
            for (int m = lane; m < N_; m += 32) {
                const float v = sc[r*N_+m]*inv;
                __half hi, lo;
                f16_split(v, hi, lo);
                dH[m] = hi; dL[m] = lo;
            }
        }
    }
}

// ---------------------------------------------------------------------------
// Kernel C: msg GEMM on tensor cores (3-term fp16 split, K=128 resident).
// CTA: 128 rows (r=(b*32+t)*500+m) x 256 cols (h,u), K=128 (d).
// A = curr (fp32 -> hi/lo fp16), B = Wmsg gathered as [(h,u)][d] hi/lo fp16.
// C = Ah*Wh + Ah*Wl + Al*Wh (fp32). Epilogue: smem-staged transpose ->
// single fp16 msgT[b][t*64+u][h*500+m], packed aligned 8B stores.
// ---------------------------------------------------------------------------
#define QRS    272                        // smem row stride (17 x 16B, odd units)
#define QAHI   0
#define QALO   (128*QRS)                  // 34816
#define QWHI   (2*128*QRS)                // 69632
#define QWLO   (QWHI + 256*QRS)           // 139264
#define QSMEM  (QWLO + 256*QRS)           // 208896
#define QCS    260                        // C staging stride (fp32 words)

__global__ __launch_bounds__(512, 1)
void msg_mma(const float* __restrict__ curr,
             const float* __restrict__ Wmsg)
{
    extern __shared__ __align__(128) char smq[];
    const uint32_t sbase = smem_u32(smq);
    const int tid  = threadIdx.x;
    const int wid  = tid >> 5;
    const int lane = tid & 31;
    const int r0   = blockIdx.x * 128;

    // ---- A: curr rows -> split fp16 smem.  128 rows x 16 segs (8 d each) ----
    #pragma unroll
    for (int i = 0; i < 4; i++) {
        const int g   = tid + i*512;            // 0..2047
        const int row = g >> 4;
        const int s   = g & 15;
        const float* src = curr + (size_t)(r0 + row)*DC_ + s*8;
        float4 v0 = *(const float4*)(src);
        float4 v1 = *(const float4*)(src + 4);
        union { __half x[8]; uint4 v; } ph, pl;
        f16_split(v0.x, ph.x[0], pl.x[0]);
        f16_split(v0.y, ph.x[1], pl.x[1]);
        f16_split(v0.z, ph.x[2], pl.x[2]);
        f16_split(v0.w, ph.x[3], pl.x[3]);
        f16_split(v1.x, ph.x[4], pl.x[4]);
        f16_split(v1.y, ph.x[5], pl.x[5]);
        f16_split(v1.z, ph.x[6], pl.x[6]);
        f16_split(v1.w, ph.x[7], pl.x[7]);
        *(uint4*)(smq + QAHI + row*QRS + s*16) = ph.v;
        *(uint4*)(smq + QALO + row*QRS + s*16) = pl.v;
    }
    // ---- B: Wmsg[h][d][u] -> Wsm[(h,u)][d] split fp16.  256 rows x 16 segs ----
    #pragma unroll
    for (int i = 0; i < 8; i++) {
        const int g = tid + i*512;              // 0..4095
        const int n = g >> 4;                   // (h,u)
        const int s = g & 15;
        const int h = n >> 6;
        const int u = n & 63;
        const int d0 = s * 8;
        union { __half x[8]; uint4 v; } ph, pl;
        #pragma unroll
        for (int j = 0; j < 8; j++) {
            const float w = __ldg(Wmsg + h*(DC_*U_) + (d0 + j)*U_ + u);
            f16_split(w, ph.x[j], pl.x[j]);
        }
        *(uint4*)(smq + QWHI + n*QRS + s*16) = ph.v;
        *(uint4*)(smq + QWLO + n*QRS + s*16) = pl.v;
    }
    __syncthreads();

    // ---- MMA: 16 warps, warp tile 64(m) x 32(n); 8 k16 steps, no syncs ----
    const int wm = wid & 1;        // 2 m-bands of 64
    const int wn = wid >> 1;       // 8 n-bands of 32
    const uint32_t aRowOff = (lane & 7) + ((lane >> 3) & 1) * 8;
    const uint32_t aSegOff = (lane >> 4) * 16;
    const uint32_t bRowOff = (lane & 7) + (lane >> 4) * 8;
    const uint32_t bSegOff = ((lane >> 3) & 1) * 16;

    float acc[4][4][4] = {};       // [mt][nt][4]
    const uint32_t sAh = sbase + QAHI;
    const uint32_t sWh = sbase + QWHI;

    #pragma unroll
    for (int k16 = 0; k16 < 8; k16++) {
        const uint32_t kb = k16*32;
        uint32_t bh[2][4], bl[2][4];
        #pragma unroll
        for (int p = 0; p < 2; p++) {
            const uint32_t addr = sWh + (wn*32 + p*16 + bRowOff)*QRS + kb + bSegOff;
            ldsm_x4(bh[p], addr);
            ldsm_x4(bl[p], addr + (QWLO - QWHI));
        }
        #pragma unroll
        for (int mt = 0; mt < 4; mt++) {
            const uint32_t aaddr = sAh + (wm*64 + mt*16 + aRowOff)*QRS + kb + aSegOff;
            uint32_t a[4], a2[4];
            ldsm_x4(a, aaddr);
            ldsm_x4(a2, aaddr + (QALO - QAHI));
            #pragma unroll
            for (int nt = 0; nt < 4; nt++) {
                const uint32_t* ph = &bh[nt >> 1][(nt & 1)*2];
                const uint32_t* pl = &bl[nt >> 1][(nt & 1)*2];
                mma16816h(acc[mt][nt], a,  ph);
                mma16816h(acc[mt][nt], a,  pl);
                mma16816h(acc[mt][nt], a2, ph);
            }
        }
    }

    // ---- Stage C (fp32) in smem (operands dead; 128*260*4 = 133120 <= QSMEM) ----
    __syncthreads();
    float* Cs = (float*)smq;
    const int cr0 = wm*64 + (lane >> 2);
    const int cc0 = wn*32 + (lane & 3)*2;
    #pragma unroll
    for (int mt = 0; mt < 4; mt++) {
        #pragma unroll
        for (int half = 0; half < 2; half++) {
            const int r = cr0 + mt*16 + half*8;
            #pragma unroll
            for (int nt = 0; nt < 4; nt++) {
                *(float2*)&Cs[r*QCS + cc0 + nt*8] =
                    make_float2(acc[mt][nt][half*2+0], acc[mt][nt][half*2+1]);
            }
        }
    }
    __syncthreads();

    // ---- Transposed fp16 store: msgT[b][t*64+u][h*500+m], 4 m per store ----
    #pragma unroll
    for (int i = 0; i < 16; i++) {
        const int g  = tid + i*512;      // 0..8191 (256 c x 32 mq)
        const int c  = g & 255;
        const int mq = g >> 8;
        const int rloc = mq*4;
        const int rg = r0 + rloc;
        const int bb  = rg / (T_*N_);
        const int rem = rg - bb*(T_*N_);
        const int t   = rem / N_;
        const int m   = rem - t*N_;      // 4-aligned; quad never crosses t (500%4==0)
        const int h   = c >> 6;
        const int u   = c & 63;
        union { __half x[4]; uint2 v; } p;
        #pragma unroll
        for (int j = 0; j < 4; j++)
            p.x[j] = __float2half_rn(Cs[(rloc + j)*QCS + c]);
        const size_t off = ((size_t)bb*TU_ + t*U_ + u)*HM_ + (size_t)h*N_ + m;
        *(uint2*)&g_msgT[off] = p.v;
    }
}

// ---------------------------------------------------------------------------
// Kernel D: mix GEMM via mma.sync (fp16, A split / B single), 2 CTAs/SM,
// 3-stage cp.async pipeline.  (unchanged from R10)
// ---------------------------------------------------------------------------
#define MIX_KC    32
#define MIX_NCH   63          // ceil(2000/32), zero-filled to 2016
#define MRS       80          // smem row stride bytes (64B data + 16B pad)
#define MTILE     10240       // 128 rows * 80B
#define MSTAGE    (3*MTILE)   // Ah, Al, B  = 30720
#define MNSTG     3
#define MSM_TOTAL (MNSTG*MSTAGE)  // 92160

__device__ __forceinline__ void mix_load_chunk(
    uint32_t sstage, int kc, int tid, int b, int mBase, int nBase)
{
    const __half* Ah = g_attn_hi + (size_t)b * N_ * HM_;
    const __half* Al = g_attn_lo + (size_t)b * N_ * HM_;
    const __half* Bm = g_msgT   + (size_t)b * TU_ * HM_;
    #pragma unroll
    for (int i = 0; i < 6; i++) {
        const int g    = tid + i*256;       // 0..1535
        const int tile = g >> 9;            // 0:Ah 1:Al 2:B
        const int rem  = g & 511;
        const int row  = rem >> 2;
        const int seg  = rem & 3;
        const int k    = kc + seg*8;
        const uint32_t dst = sstage + tile*MTILE + row*MRS + seg*16;
        if (tile < 2) {
            const int n = mBase + row;
            const bool ok = (n < N_) && (k < HM_);
            const __half* base = tile ? Al : Ah;
            cp16(dst, base + (ok ? ((size_t)n*HM_ + k) : 0), ok);
        } else {
            const bool ok = (k < HM_);
            cp16(dst, Bm + (ok ? ((size_t)(nBase + row)*HM_ + k) : 0), ok);
        }
    }
    cp_commit();
}

__global__ __launch_bounds__(256, 2)
void mix_mma(float* __restrict__ out)
{
    extern __shared__ __align__(128) char smx[];
    const uint32_t sbase = smem_u32(smx);
    const int tid  = threadIdx.x;
    const int wid  = tid >> 5;
    const int lane = tid & 31;
    const int b     = blockIdx.z;
    const int mBase = blockIdx.x * 128;
    const int nBase = blockIdx.y * 128;

    const int wm = wid & 1;       // m band (2 x 64)
    const int wn = wid >> 1;      // n band (4 x 32)

    const uint32_t aRowOff = (lane & 7) + ((lane >> 3) & 1) * 8;
    const uint32_t aSegOff = (lane >> 4) * 16;
    const uint32_t bRowOff = (lane & 7) + (lane >> 4) * 8;
    const uint32_t bSegOff = ((lane >> 3) & 1) * 16;

    float acc[4][4][4] = {};   // [mt][nt][4]

    mix_load_chunk(sbase + 0*MSTAGE, 0*MIX_KC, tid, b, mBase, nBase);
    mix_load_chunk(sbase + 1*MSTAGE, 1*MIX_KC, tid, b, mBase, nBase);

    int sc = 0;
    for (int c = 0; c < MIX_NCH; c++) {
        if (c + 2 < MIX_NCH) {
            const int ns = (sc + 2 >= MNSTG) ? sc + 2 - MNSTG : sc + 2;
            mix_load_chunk(sbase + ns*MSTAGE, (c+2)*MIX_KC, tid, b, mBase, nBase);
            cp_wait<2>();
        } else if (c + 1 < MIX_NCH) {
            cp_wait<1>();
        } else {
            cp_wait<0>();
        }
        __syncthreads();

        const uint32_t sA = sbase + sc*MSTAGE;
        const uint32_t sB = sA + 2*MTILE;

        #pragma unroll
        for (int k16 = 0; k16 < 2; k16++) {
            const uint32_t kb = k16*32;
            uint32_t bb[2][4];
            #pragma unroll
            for (int p = 0; p < 2; p++) {
                ldsm_x4(bb[p], sB + (wn*32 + p*16 + bRowOff)*MRS + kb + bSegOff);
            }
            #pragma unroll
            for (int mt = 0; mt < 4; mt++) {
                const uint32_t aaddr = sA + (wm*64 + mt*16 + aRowOff)*MRS + kb + aSegOff;
                uint32_t a[4], a2[4];
                ldsm_x4(a, aaddr);
                ldsm_x4(a2, aaddr + MTILE);
                #pragma unroll
                for (int nt = 0; nt < 4; nt++) {
                    const uint32_t* pb = &bb[nt >> 1][(nt & 1)*2];
                    mma16816h(acc[mt][nt], a,  pb);
                    mma16816h(acc[mt][nt], a2, pb);
                }
            }
        }
        __syncthreads();
        sc = (sc + 1 >= MNSTG) ? 0 : sc + 1;
    }

    // Epilogue
    const int r0 = mBase + wm*64 + (lane >> 2);
    const int c0 = nBase + wn*32 + (lane & 3)*2;
    #pragma unroll
    for (int mt = 0; mt < 4; mt++) {
        #pragma unroll
        for (int half = 0; half < 2; half++) {
            const int n = r0 + mt*16 + half*8;
            if (n < N_) {
                #pragma unroll
                for (int nt = 0; nt < 4; nt++) {
                    const int cc = c0 + nt*8;
                    const int t  = cc >> 6;
                    const int u  = cc & 63;
                    float2 v = make_float2(acc[mt][nt][half*2+0]*0.25f,
                                           acc[mt][nt][half*2+1]*0.25f);
                    *(float2*)&out[(((size_t)b*T_ + t)*N_ + n)*U_ + u] = v;
                }
            }
        }
    }
}

// ---------------------------------------------------------------------------
extern "C" void kernel_launch(void* const* d_in, const int* in_sizes, int n_in,
                              void* d_out, int out_size)
{
    const float* prev = (const float*)d_in[0];   // [8,500,200]
    const float* curr = (const float*)d_in[1];   // [8,32,500,128]
    const float* Wsrc = (const float*)d_in[2];   // [4,200,64]
    const float* Wdst = (const float*)d_in[3];   // [4,200,64]
    const float* aV   = (const float*)d_in[4];   // [4,64,1]
    const float* Wmsg = (const float*)d_in[5];   // [4,128,64]
    float* out = (float*)d_out;                  // [8,32,500,64]

    // A: projections  (M=4000, N=512, K=200)
    proj_gemm<<<dim3(32, 4), 256>>>(prev, Wsrc, Wdst);

    // B: scores + softmax -> fp16 hi/lo attn
    const size_t shB = (size_t)(512*65 + 16*64 + 128 + 16*500) * sizeof(float);
    cudaFuncSetAttribute(score_softmax_kernel,
                         cudaFuncAttributeMaxDynamicSharedMemorySize, (int)shB);
    score_softmax_kernel<<<dim3(32, 32), 256, shB>>>(aV);

    // C: msg GEMM on tensor cores -> transposed single-fp16 msgT
    cudaFuncSetAttribute(msg_mma,
                         cudaFuncAttributeMaxDynamicSharedMemorySize, QSMEM);
    msg_mma<<<1000, 512, QSMEM>>>(curr, Wmsg);

    // D: mix GEMM on tensor cores (per batch: M=500, N=2048, K=2000), 2 CTAs/SM
    cudaFuncSetAttribute(mix_mma,
                         cudaFuncAttributeMaxDynamicSharedMemorySize, MSM_TOTAL);
    mix_mma<<<dim3(4, 16, 8), 256, MSM_TOTAL>>>(out);
}

// round 12
// speedup vs baseline: 2.1840x; 1.2044x over previous
#include <cuda_runtime.h>
#include <cuda_bf16.h>
#include <cuda_fp16.h>
#include <cstdint>
#include <cstddef>

// Problem constants
#define B_   8
#define T_   32
#define N_   500
#define DP_  200
#define DC_  128
#define H_   4
#define U_   64
#define HM_  2000   // H_*N_  (K dim of mix GEMM)
#define TU_  2048   // T_*U_  (N dim of mix GEMM)

// Scratch (device globals: allocation-free rule)
__device__ float g_S[B_*H_*N_*U_];                    // [b][h][n][u]
__device__ float g_D[B_*H_*N_*U_];                    // [b][h][m][u]
__device__ __half g_attn[(size_t)B_*N_*HM_];          // [b][n][hm] single fp16
__device__ __half g_msgT[(size_t)B_*TU_*HM_];         // [b][tu][hm] single fp16

// ---------------------------------------------------------------------------
// Helpers (compute_103-safe: cp.async / ldmatrix / mma.sync)
// ---------------------------------------------------------------------------
__device__ __forceinline__ uint32_t smem_u32(const void* p) {
    uint32_t a;
    asm("{ .reg .u64 t; cvta.to.shared.u64 t, %1; cvt.u32.u64 %0, t; }" : "=r"(a) : "l"(p));
    return a;
}
__device__ __forceinline__ void cp16(uint32_t dst, const void* src, bool ok) {
    int sz = ok ? 16 : 0;   // src-size 0 => zero-fill 16B
    asm volatile("cp.async.cg.shared.global [%0], [%1], 16, %2;" :: "r"(dst), "l"(src), "r"(sz) : "memory");
}
__device__ __forceinline__ void cp_commit() {
    asm volatile("cp.async.commit_group;" ::: "memory");
}
template <int NW>
__device__ __forceinline__ void cp_wait() {
    asm volatile("cp.async.wait_group %0;" :: "n"(NW) : "memory");
}
__device__ __forceinline__ void ldsm_x4(uint32_t* r, uint32_t addr) {
    asm volatile("ldmatrix.sync.aligned.m8n8.x4.shared.b16 {%0,%1,%2,%3}, [%4];"
                 : "=r"(r[0]), "=r"(r[1]), "=r"(r[2]), "=r"(r[3]) : "r"(addr));
}
// fp16 MMA, fp32 accumulate
__device__ __forceinline__ void mma16816h(float* c, const uint32_t* a, const uint32_t* b) {
    asm volatile(
        "mma.sync.aligned.m16n8k16.row.col.f32.f16.f16.f32 "
        "{%0,%1,%2,%3}, {%4,%5,%6,%7}, {%8,%9}, {%0,%1,%2,%3};"
        : "+f"(c[0]), "+f"(c[1]), "+f"(c[2]), "+f"(c[3])
        : "r"(a[0]), "r"(a[1]), "r"(a[2]), "r"(a[3]), "r"(b[0]), "r"(b[1]));
}
__device__ __forceinline__ void f16_split(float v, __half& hi, __half& lo) {
    hi = __float2half_rn(v);
    lo = __float2half_rn(v - __half2float(hi));
}

// ---------------------------------------------------------------------------
// Kernel A: projections.  GEMM M=4000 (b*500+n), K=200, Ncols=512
// ---------------------------------------------------------------------------
__global__ __launch_bounds__(256, 2)
void proj_gemm(const float* __restrict__ prev,
               const float* __restrict__ Wsrc,
               const float* __restrict__ Wdst)
{
    const int rowBase = blockIdx.x * 128;
    const int colBase = blockIdx.y * 128;

    __shared__ float As[2][8][132];
    __shared__ float Bs[2][8][128];

    const int tid  = threadIdx.x;
    const int aRow = tid >> 1;
    const int aK   = (tid & 1) * 4;
    const int bK   = tid >> 5;
    const int bCol = (tid & 31) * 4;
    const int tx   = tid & 15;
    const int ty   = tid >> 4;

    const int gRow  = rowBase + aRow;
    const bool rowOk = gRow < 4000;
    const float* aPtr = prev + (size_t)gRow * DP_ + aK;

    const int cB   = colBase + bCol;
    const int matB = cB >> 8;
    const int hB   = (cB >> 6) & 3;
    const int uB   = cB & 63;
    const float* bPtr = (matB ? Wdst : Wsrc) + hB * (DP_*U_) + bK * U_ + uB;

    const int KSTEPS = DP_ / 8;  // 25

    float4 aReg = rowOk ? *(const float4*)aPtr : make_float4(0,0,0,0);
    float4 bReg = *(const float4*)bPtr;

    As[0][aK+0][aRow] = aReg.x; As[0][aK+1][aRow] = aReg.y;
    As[0][aK+2][aRow] = aReg.z; As[0][aK+3][aRow] = aReg.w;
    *(float4*)&Bs[0][bK][bCol] = bReg;
    __syncthreads();

    float acc[2][2][4][4] = {};

    for (int ks = 0; ks < KSTEPS; ks++) {
        const int cur = ks & 1;
        if (ks + 1 < KSTEPS) {
            aReg = rowOk ? *(const float4*)(aPtr + (ks+1)*8) : make_float4(0,0,0,0);
            bReg = *(const float4*)(bPtr + (ks+1)*8*U_);
        }
        #pragma unroll
        for (int kk = 0; kk < 8; kk++) {
            float ar[2][4], br[2][4];
            *(float4*)ar[0] = *(const float4*)&As[cur][kk][ty*4];
            *(float4*)ar[1] = *(const float4*)&As[cur][kk][ty*4 + 64];
            *(float4*)br[0] = *(const float4*)&Bs[cur][kk][tx*4];
            *(float4*)br[1] = *(const float4*)&Bs[cur][kk][tx*4 + 64];
            #pragma unroll
            for (int rg=0; rg<2; rg++)
              #pragma unroll
              for (int cg=0; cg<2; cg++)
                #pragma unroll
                for (int i=0;i<4;i++)
                  #pragma unroll
                  for (int j=0;j<4;j++)
                    acc[rg][cg][i][j] = fmaf(ar[rg][i], br[cg][j], acc[rg][cg][i][j]);
        }
        if (ks + 1 < KSTEPS) {
            const int nxt = cur ^ 1;
            As[nxt][aK+0][aRow] = aReg.x; As[nxt][aK+1][aRow] = aReg.y;
            As[nxt][aK+2][aRow] = aReg.z; As[nxt][aK+3][aRow] = aReg.w;
            *(float4*)&Bs[nxt][bK][bCol] = bReg;
            __syncthreads();
        }
    }

    #pragma unroll
    for (int rg=0; rg<2; rg++) {
        #pragma unroll
        for (int i=0;i<4;i++) {
            const int r = rowBase + ty*4 + rg*64 + i;
            if (r < 4000) {
                const int b = r / N_;
                const int n = r - b * N_;
                #pragma unroll
                for (int cg=0; cg<2; cg++) {
                    const int c = colBase + tx*4 + cg*64;
                    const int mat = c >> 8;
                    const int h   = (c >> 6) & 3;
                    const int u   = c & 63;
                    float* dst = (mat ? g_D : g_S) + ((size_t)(b*H_ + h)*N_ + n)*U_ + u;
                    float4 v = make_float4(acc[rg][cg][i][0], acc[rg][cg][i][1],
                                           acc[rg][cg][i][2], acc[rg][cg][i][3]);
                    *(float4*)dst = v;
                }
            }
        }
    }
}

// ---------------------------------------------------------------------------
// Kernel B: GATv2 scores + softmax -> attn written as single fp16 [b][n][hm]
// ---------------------------------------------------------------------------
__global__ __launch_bounds__(256)
void score_softmax_kernel(const float* __restrict__ aVec)
{
    extern __shared__ float sh[];
    float* Dsh = sh;                     // 512*65
    float* Ssh = Dsh + 512*65;           // 16*64
    float* aSh = Ssh + 16*64;            // 64 (+64 pad)
    float* sc  = aSh + 128;              // 16*500

    const int bh = blockIdx.y;           // b*4 + h
    const int b  = bh >> 2;
    const int h  = bh & 3;
    const int nBase = blockIdx.x * 16;
    const int tid = threadIdx.x;

    const float* Dg = g_D + (size_t)bh * N_ * U_;
    const float* Sg = g_S + (size_t)bh * N_ * U_;

    for (int idx = tid; idx < 512*16; idx += 256) {
        const int m = idx >> 4;
        const int u = (idx & 15) * 4;
        float4 v = (m < N_) ? *(const float4*)(Dg + m*U_ + u) : make_float4(0,0,0,0);
        float* dst = &Dsh[m*65 + u];
        dst[0]=v.x; dst[1]=v.y; dst[2]=v.z; dst[3]=v.w;
    }
    for (int idx = tid; idx < 16*16; idx += 256) {
        const int r = idx >> 4;
        const int u = (idx & 15) * 4;
        const int n = nBase + r;
        float4 v = (n < N_) ? *(const float4*)(Sg + n*U_ + u) : make_float4(0,0,0,0);
        float* dst = &Ssh[r*U_ + u];
        dst[0]=v.x; dst[1]=v.y; dst[2]=v.z; dst[3]=v.w;
    }
    if (tid < 64) aSh[tid] = aVec[h*U_ + tid];
    __syncthreads();

    const int tx  = tid & 63;
    const int tyy = tid >> 6;

    float acc[4][8];
    #pragma unroll
    for (int i=0;i<4;i++)
        #pragma unroll
        for (int k=0;k<8;k++) acc[i][k]=0.f;

    for (int u = 0; u < U_; u++) {
        const float au = aSh[u];
        float s[4];
        #pragma unroll
        for (int i=0;i<4;i++) s[i] = Ssh[(tyy*4+i)*U_ + u];
        #pragma unroll
        for (int k=0;k<8;k++) {
            const float d = Dsh[(tx + 64*k)*65 + u];
            #pragma unroll
            for (int i=0;i<4;i++) {
                const float t  = s[i] + d;
                const float lr = fmaxf(t, 0.2f * t);
                acc[i][k] = fmaf(au, lr, acc[i][k]);
            }
        }
    }
    #pragma unroll
    for (int i=0;i<4;i++)
        #pragma unroll
        for (int k=0;k<8;k++) {
            const int m = tx + 64*k;
            if (m < N_) sc[(tyy*4+i)*N_ + m] = acc[i][k];
        }
    __syncthreads();

    const int warp = tid >> 5, lane = tid & 31;
    #pragma unroll
    for (int rr = 0; rr < 2; rr++) {
        const int r = warp*2 + rr;
        const int n = nBase + r;
        float mx = -1e30f;
        for (int m = lane; m < N_; m += 32) mx = fmaxf(mx, sc[r*N_+m]);
        #pragma unroll
        for (int o=16;o>0;o>>=1) mx = fmaxf(mx, __shfl_xor_sync(0xffffffffu, mx, o));
        float sum = 0.f;
        for (int m = lane; m < N_; m += 32) {
            const float e = __expf(sc[r*N_+m] - mx);
            sc[r*N_+m] = e;
            sum += e;
        }
        #pragma unroll
        for (int o=16;o>0;o>>=1) sum += __shfl_xor_sync(0xffffffffu, sum, o);
        const float inv = 1.f / sum;
        if (n < N_) {
            __half* dH = g_attn + ((size_t)b*N_ + n)*HM_ + (size_t)h*N_;
            for (int m = lane; m < N_; m += 32)
                dH[m] = __float2half_rn(sc[r*N_+m]*inv);
        }
    }
}

// ---------------------------------------------------------------------------
// Kernel C: msg GEMM on tensor cores (3-term fp16 split, K=128 resident).
// (unchanged from R11)
// ---------------------------------------------------------------------------
#define QRS    272                        // smem row stride (17 x 16B, odd units)
#define QAHI   0
#define QALO   (128*QRS)                  // 34816
#define QWHI   (2*128*QRS)                // 69632
#define QWLO   (QWHI + 256*QRS)           // 139264
#define QSMEM  (QWLO + 256*QRS)           // 208896
#define QCS    260                        // C staging stride (fp32 words)

__global__ __launch_bounds__(512, 1)
void msg_mma(const float* __restrict__ curr,
             const float* __restrict__ Wmsg)
{
    extern __shared__ __align__(128) char smq[];
    const uint32_t sbase = smem_u32(smq);
    const int tid  = threadIdx.x;
    const int wid  = tid >> 5;
    const int lane = tid & 31;
    const int r0   = blockIdx.x * 128;

    // ---- A: curr rows -> split fp16 smem.  128 rows x 16 segs (8 d each) ----
    #pragma unroll
    for (int i = 0; i < 4; i++) {
        const int g   = tid + i*512;            // 0..2047
        const int row = g >> 4;
        const int s   = g & 15;
        const float* src = curr + (size_t)(r0 + row)*DC_ + s*8;
        float4 v0 = *(const float4*)(src);
        float4 v1 = *(const float4*)(src + 4);
        union { __half x[8]; uint4 v; } ph, pl;
        f16_split(v0.x, ph.x[0], pl.x[0]);
        f16_split(v0.y, ph.x[1], pl.x[1]);
        f16_split(v0.z, ph.x[2], pl.x[2]);
        f16_split(v0.w, ph.x[3], pl.x[3]);
        f16_split(v1.x, ph.x[4], pl.x[4]);
        f16_split(v1.y, ph.x[5], pl.x[5]);
        f16_split(v1.z, ph.x[6], pl.x[6]);
        f16_split(v1.w, ph.x[7], pl.x[7]);
        *(uint4*)(smq + QAHI + row*QRS + s*16) = ph.v;
        *(uint4*)(smq + QALO + row*QRS + s*16) = pl.v;
    }
    // ---- B: Wmsg[h][d][u] -> Wsm[(h,u)][d] split fp16.  256 rows x 16 segs ----
    #pragma unroll
    for (int i = 0; i < 8; i++) {
        const int g = tid + i*512;              // 0..4095
        const int n = g >> 4;                   // (h,u)
        const int s = g & 15;
        const int h = n >> 6;
        const int u = n & 63;
        const int d0 = s * 8;
        union { __half x[8]; uint4 v; } ph, pl;
        #pragma unroll
        for (int j = 0; j < 8; j++) {
            const float w = __ldg(Wmsg + h*(DC_*U_) + (d0 + j)*U_ + u);
            f16_split(w, ph.x[j], pl.x[j]);
        }
        *(uint4*)(smq + QWHI + n*QRS + s*16) = ph.v;
        *(uint4*)(smq + QWLO + n*QRS + s*16) = pl.v;
    }
    __syncthreads();

    // ---- MMA: 16 warps, warp tile 64(m) x 32(n); 8 k16 steps, no syncs ----
    const int wm = wid & 1;        // 2 m-bands of 64
    const int wn = wid >> 1;       // 8 n-bands of 32
    const uint32_t aRowOff = (lane & 7) + ((lane >> 3) & 1) * 8;
    const uint32_t aSegOff = (lane >> 4) * 16;
    const uint32_t bRowOff = (lane & 7) + (lane >> 4) * 8;
    const uint32_t bSegOff = ((lane >> 3) & 1) * 16;

    float acc[4][4][4] = {};       // [mt][nt][4]
    const uint32_t sAh = sbase + QAHI;
    const uint32_t sWh = sbase + QWHI;

    #pragma unroll
    for (int k16 = 0; k16 < 8; k16++) {
        const uint32_t kb = k16*32;
        uint32_t bh[2][4], bl[2][4];
        #pragma unroll
        for (int p = 0; p < 2; p++) {
            const uint32_t addr = sWh + (wn*32 + p*16 + bRowOff)*QRS + kb + bSegOff;
            ldsm_x4(bh[p], addr);
            ldsm_x4(bl[p], addr + (QWLO - QWHI));
        }
        #pragma unroll
        for (int mt = 0; mt < 4; mt++) {
            const uint32_t aaddr = sAh + (wm*64 + mt*16 + aRowOff)*QRS + kb + aSegOff;
            uint32_t a[4], a2[4];
            ldsm_x4(a, aaddr);
            ldsm_x4(a2, aaddr + (QALO - QAHI));
            #pragma unroll
            for (int nt = 0; nt < 4; nt++) {
                const uint32_t* ph = &bh[nt >> 1][(nt & 1)*2];
                const uint32_t* pl = &bl[nt >> 1][(nt & 1)*2];
                mma16816h(acc[mt][nt], a,  ph);
                mma16816h(acc[mt][nt], a,  pl);
                mma16816h(acc[mt][nt], a2, ph);
            }
        }
    }

    // ---- Stage C (fp32) in smem ----
    __syncthreads();
    float* Cs = (float*)smq;
    const int cr0 = wm*64 + (lane >> 2);
    const int cc0 = wn*32 + (lane & 3)*2;
    #pragma unroll
    for (int mt = 0; mt < 4; mt++) {
        #pragma unroll
        for (int half = 0; half < 2; half++) {
            const int r = cr0 + mt*16 + half*8;
            #pragma unroll
            for (int nt = 0; nt < 4; nt++) {
                *(float2*)&Cs[r*QCS + cc0 + nt*8] =
                    make_float2(acc[mt][nt][half*2+0], acc[mt][nt][half*2+1]);
            }
        }
    }
    __syncthreads();

    // ---- Transposed fp16 store: msgT[b][t*64+u][h*500+m], 4 m per store ----
    #pragma unroll
    for (int i = 0; i < 16; i++) {
        const int g  = tid + i*512;      // 0..8191 (256 c x 32 mq)
        const int c  = g & 255;
        const int mq = g >> 8;
        const int rloc = mq*4;
        const int rg = r0 + rloc;
        const int bb  = rg / (T_*N_);
        const int rem = rg - bb*(T_*N_);
        const int t   = rem / N_;
        const int m   = rem - t*N_;      // 4-aligned; quad never crosses t (500%4==0)
        const int h   = c >> 6;
        const int u   = c & 63;
        union { __half x[4]; uint2 v; } p;
        #pragma unroll
        for (int j = 0; j < 4; j++)
            p.x[j] = __float2half_rn(Cs[(rloc + j)*QCS + c]);
        const size_t off = ((size_t)bb*TU_ + t*U_ + u)*HM_ + (size_t)h*N_ + m;
        *(uint2*)&g_msgT[off] = p.v;
    }
}

// ---------------------------------------------------------------------------
// Kernel D: mix GEMM via mma.sync (single fp16 A and B), 2 CTAs/SM,
// 4-stage cp.async pipeline (prefetch distance 3).
// Per (Mtile 128, Ntile 128, b): C = A*B  (fp32 acc), K zero-pad 2016.
// ---------------------------------------------------------------------------
#define MIX_KC    32
#define MIX_NCH   63          // ceil(2000/32), zero-filled to 2016
#define MRS       80          // smem row stride bytes (64B data + 16B pad)
#define MTILE     10240       // 128 rows * 80B
#define MSTAGE    (2*MTILE)   // A, B = 20480
#define MNSTG     4
#define MSM_TOTAL (MNSTG*MSTAGE)  // 81920

__device__ __forceinline__ void mix_load_chunk(
    uint32_t sstage, int kc, int tid, int b, int mBase, int nBase)
{
    const __half* Am = g_attn + (size_t)b * N_ * HM_;
    const __half* Bm = g_msgT + (size_t)b * TU_ * HM_;
    #pragma unroll
    for (int i = 0; i < 4; i++) {
        const int g    = tid + i*256;       // 0..1023
        const int tile = g >> 9;            // 0:A 1:B
        const int rem  = g & 511;
        const int row  = rem >> 2;
        const int seg  = rem & 3;
        const int k    = kc + seg*8;
        const uint32_t dst = sstage + tile*MTILE + row*MRS + seg*16;
        if (tile == 0) {
            const int n = mBase + row;
            const bool ok = (n < N_) && (k < HM_);
            cp16(dst, Am + (ok ? ((size_t)n*HM_ + k) : 0), ok);
        } else {
            const bool ok = (k < HM_);
            cp16(dst, Bm + (ok ? ((size_t)(nBase + row)*HM_ + k) : 0), ok);
        }
    }
    cp_commit();
}

__global__ __launch_bounds__(256, 2)
void mix_mma(float* __restrict__ out)
{
    extern __shared__ __align__(128) char smx[];
    const uint32_t sbase = smem_u32(smx);
    const int tid  = threadIdx.x;
    const int wid  = tid >> 5;
    const int lane = tid & 31;
    const int b     = blockIdx.z;
    const int mBase = blockIdx.x * 128;
    const int nBase = blockIdx.y * 128;

    const int wm = wid & 1;       // m band (2 x 64)
    const int wn = wid >> 1;      // n band (4 x 32)

    const uint32_t aRowOff = (lane & 7) + ((lane >> 3) & 1) * 8;
    const uint32_t aSegOff = (lane >> 4) * 16;
    const uint32_t bRowOff = (lane & 7) + (lane >> 4) * 8;
    const uint32_t bSegOff = ((lane >> 3) & 1) * 16;

    float acc[4][4][4] = {};   // [mt][nt][4]

    mix_load_chunk(sbase + 0*MSTAGE, 0*MIX_KC, tid, b, mBase, nBase);
    mix_load_chunk(sbase + 1*MSTAGE, 1*MIX_KC, tid, b, mBase, nBase);
    mix_load_chunk(sbase + 2*MSTAGE, 2*MIX_KC, tid, b, mBase, nBase);

    int sc = 0;
    for (int c = 0; c < MIX_NCH; c++) {
        if (c + 3 < MIX_NCH) {
            const int ns = (sc + 3) & 3;
            mix_load_chunk(sbase + ns*MSTAGE, (c+3)*MIX_KC, tid, b, mBase, nBase);
            cp_wait<3>();
        } else if (c + 2 < MIX_NCH) {
            cp_wait<2>();
        } else if (c + 1 < MIX_NCH) {
            cp_wait<1>();
        } else {
            cp_wait<0>();
        }
        __syncthreads();

        const uint32_t sA = sbase + sc*MSTAGE;
        const uint32_t sB = sA + MTILE;

        #pragma unroll
        for (int k16 = 0; k16 < 2; k16++) {
            const uint32_t kb = k16*32;
            uint32_t bb[2][4];
            #pragma unroll
            for (int p = 0; p < 2; p++) {
                ldsm_x4(bb[p], sB + (wn*32 + p*16 + bRowOff)*MRS + kb + bSegOff);
            }
            #pragma unroll
            for (int mt = 0; mt < 4; mt++) {
                uint32_t a[4];
                ldsm_x4(a, sA + (wm*64 + mt*16 + aRowOff)*MRS + kb + aSegOff);
                #pragma unroll
                for (int nt = 0; nt < 4; nt++) {
                    mma16816h(acc[mt][nt], a, &bb[nt >> 1][(nt & 1)*2]);
                }
            }
        }
        __syncthreads();
        sc = (sc + 1) & 3;
    }

    // Epilogue
    const int r0 = mBase + wm*64 + (lane >> 2);
    const int c0 = nBase + wn*32 + (lane & 3)*2;
    #pragma unroll
    for (int mt = 0; mt < 4; mt++) {
        #pragma unroll
        for (int half = 0; half < 2; half++) {
            const int n = r0 + mt*16 + half*8;
            if (n < N_) {
                #pragma unroll
                for (int nt = 0; nt < 4; nt++) {
                    const int cc = c0 + nt*8;
                    const int t  = cc >> 6;
                    const int u  = cc & 63;
                    float2 v = make_float2(acc[mt][nt][half*2+0]*0.25f,
                                           acc[mt][nt][half*2+1]*0.25f);
                    *(float2*)&out[(((size_t)b*T_ + t)*N_ + n)*U_ + u] = v;
                }
            }
        }
    }
}

// ---------------------------------------------------------------------------
extern "C" void kernel_launch(void* const* d_in, const int* in_sizes, int n_in,
                              void* d_out, int out_size)
{
    const float* prev = (const float*)d_in[0];   // [8,500,200]
    const float* curr = (const float*)d_in[1];   // [8,32,500,128]
    const float* Wsrc = (const float*)d_in[2];   // [4,200,64]
    const float* Wdst = (const float*)d_in[3];   // [4,200,64]
    const float* aV   = (const float*)d_in[4];   // [4,64,1]
    const float* Wmsg = (const float*)d_in[5];   // [4,128,64]
    float* out = (float*)d_out;                  // [8,32,500,64]

    // A: projections  (M=4000, N=512, K=200)
    proj_gemm<<<dim3(32, 4), 256>>>(prev, Wsrc, Wdst);

    // B: scores + softmax -> single fp16 attn
    const size_t shB = (size_t)(512*65 + 16*64 + 128 + 16*500) * sizeof(float);
    cudaFuncSetAttribute(score_softmax_kernel,
                         cudaFuncAttributeMaxDynamicSharedMemorySize, (int)shB);
    score_softmax_kernel<<<dim3(32, 32), 256, shB>>>(aV);

    // C: msg GEMM on tensor cores -> transposed single-fp16 msgT
    cudaFuncSetAttribute(msg_mma,
                         cudaFuncAttributeMaxDynamicSharedMemorySize, QSMEM);
    msg_mma<<<1000, 512, QSMEM>>>(curr, Wmsg);

    // D: mix GEMM on tensor cores (per batch: M=500, N=2048, K=2000), 2 CTAs/SM
    cudaFuncSetAttribute(mix_mma,
                         cudaFuncAttributeMaxDynamicSharedMemorySize, MSM_TOTAL);
    mix_mma<<<dim3(4, 16, 8), 256, MSM_TOTAL>>>(out);
}

// round 13
// speedup vs baseline: 2.4296x; 1.1125x over previous
#include <cuda_runtime.h>
#include <cuda_bf16.h>
#include <cuda_fp16.h>
#include <cstdint>
#include <cstddef>

// Problem constants
#define B_   8
#define T_   32
#define N_   500
#define DP_  200
#define DC_  128
#define H_   4
#define U_   64
#define HM_  2000   // H_*N_  (K dim of mix GEMM)
#define TU_  2048   // T_*U_  (N dim of mix GEMM)

// Scratch (device globals: allocation-free rule)
__device__ float g_S[B_*H_*N_*U_];                    // [b][h][n][u]
__device__ float g_D[B_*H_*N_*U_];                    // [b][h][m][u]
__device__ __half g_attn[(size_t)B_*N_*HM_];          // [b][n][hm] single fp16
__device__ __half g_msgT[(size_t)B_*TU_*HM_];         // [b][tu][hm] single fp16
__device__ __half g_WT_hi[256*128];                   // [(h,u)][d] Wmsg^T hi
__device__ __half g_WT_lo[256*128];                   // [(h,u)][d] Wmsg^T lo

// ---------------------------------------------------------------------------
// Helpers (compute_103-safe: cp.async / ldmatrix / mma.sync)
// ---------------------------------------------------------------------------
__device__ __forceinline__ uint32_t smem_u32(const void* p) {
    uint32_t a;
    asm("{ .reg .u64 t; cvta.to.shared.u64 t, %1; cvt.u32.u64 %0, t; }" : "=r"(a) : "l"(p));
    return a;
}
__device__ __forceinline__ void cp16(uint32_t dst, const void* src, bool ok) {
    int sz = ok ? 16 : 0;   // src-size 0 => zero-fill 16B
    asm volatile("cp.async.cg.shared.global [%0], [%1], 16, %2;" :: "r"(dst), "l"(src), "r"(sz) : "memory");
}
__device__ __forceinline__ void cp_commit() {
    asm volatile("cp.async.commit_group;" ::: "memory");
}
template <int NW>
__device__ __forceinline__ void cp_wait() {
    asm volatile("cp.async.wait_group %0;" :: "n"(NW) : "memory");
}
__device__ __forceinline__ void ldsm_x4(uint32_t* r, uint32_t addr) {
    asm volatile("ldmatrix.sync.aligned.m8n8.x4.shared.b16 {%0,%1,%2,%3}, [%4];"
                 : "=r"(r[0]), "=r"(r[1]), "=r"(r[2]), "=r"(r[3]) : "r"(addr));
}
// fp16 MMA, fp32 accumulate
__device__ __forceinline__ void mma16816h(float* c, const uint32_t* a, const uint32_t* b) {
    asm volatile(
        "mma.sync.aligned.m16n8k16.row.col.f32.f16.f16.f32 "
        "{%0,%1,%2,%3}, {%4,%5,%6,%7}, {%8,%9}, {%0,%1,%2,%3};"
        : "+f"(c[0]), "+f"(c[1]), "+f"(c[2]), "+f"(c[3])
        : "r"(a[0]), "r"(a[1]), "r"(a[2]), "r"(a[3]), "r"(b[0]), "r"(b[1]));
}
__device__ __forceinline__ void f16_split(float v, __half& hi, __half& lo) {
    hi = __float2half_rn(v);
    lo = __float2half_rn(v - __half2float(hi));
}

// ---------------------------------------------------------------------------
// Kernel W: one-shot Wmsg transpose+split -> g_WT_hi/lo [(h,u)][d] fp16
// ---------------------------------------------------------------------------
__global__ __launch_bounds__(256)
void wprep(const float* __restrict__ Wmsg)
{
    const int g = blockIdx.x * 256 + threadIdx.x;   // 0..4095
    const int n = g >> 4;          // (h,u) row
    const int s = g & 15;          // 8-d segment
    const int h = n >> 6;
    const int u = n & 63;
    const int d0 = s * 8;
    union { __half x[8]; uint4 v; } ph, pl;
    #pragma unroll
    for (int j = 0; j < 8; j++) {
        const float w = __ldg(Wmsg + h*(DC_*U_) + (d0 + j)*U_ + u);
        f16_split(w, ph.x[j], pl.x[j]);
    }
    *(uint4*)&g_WT_hi[n*128 + d0] = ph.v;
    *(uint4*)&g_WT_lo[n*128 + d0] = pl.v;
}

// ---------------------------------------------------------------------------
// Kernel A: projections.  GEMM M=4000 (b*500+n), K=200, Ncols=512
// ---------------------------------------------------------------------------
__global__ __launch_bounds__(256, 2)
void proj_gemm(const float* __restrict__ prev,
               const float* __restrict__ Wsrc,
               const float* __restrict__ Wdst)
{
    const int rowBase = blockIdx.x * 128;
    const int colBase = blockIdx.y * 128;

    __shared__ float As[2][8][132];
    __shared__ float Bs[2][8][128];

    const int tid  = threadIdx.x;
    const int aRow = tid >> 1;
    const int aK   = (tid & 1) * 4;
    const int bK   = tid >> 5;
    const int bCol = (tid & 31) * 4;
    const int tx   = tid & 15;
    const int ty   = tid >> 4;

    const int gRow  = rowBase + aRow;
    const bool rowOk = gRow < 4000;
    const float* aPtr = prev + (size_t)gRow * DP_ + aK;

    const int cB   = colBase + bCol;
    const int matB = cB >> 8;
    const int hB   = (cB >> 6) & 3;
    const int uB   = cB & 63;
    const float* bPtr = (matB ? Wdst : Wsrc) + hB * (DP_*U_) + bK * U_ + uB;

    const int KSTEPS = DP_ / 8;  // 25

    float4 aReg = rowOk ? *(const float4*)aPtr : make_float4(0,0,0,0);
    float4 bReg = *(const float4*)bPtr;

    As[0][aK+0][aRow] = aReg.x; As[0][aK+1][aRow] = aReg.y;
    As[0][aK+2][aRow] = aReg.z; As[0][aK+3][aRow] = aReg.w;
    *(float4*)&Bs[0][bK][bCol] = bReg;
    __syncthreads();

    float acc[2][2][4][4] = {};

    for (int ks = 0; ks < KSTEPS; ks++) {
        const int cur = ks & 1;
        if (ks + 1 < KSTEPS) {
            aReg = rowOk ? *(const float4*)(aPtr + (ks+1)*8) : make_float4(0,0,0,0);
            bReg = *(const float4*)(bPtr + (ks+1)*8*U_);
        }
        #pragma unroll
        for (int kk = 0; kk < 8; kk++) {
            float ar[2][4], br[2][4];
            *(float4*)ar[0] = *(const float4*)&As[cur][kk][ty*4];
            *(float4*)ar[1] = *(const float4*)&As[cur][kk][ty*4 + 64];
            *(float4*)br[0] = *(const float4*)&Bs[cur][kk][tx*4];
            *(float4*)br[1] = *(const float4*)&Bs[cur][kk][tx*4 + 64];
            #pragma unroll
            for (int rg=0; rg<2; rg++)
              #pragma unroll
              for (int cg=0; cg<2; cg++)
                #pragma unroll
                for (int i=0;i<4;i++)
                  #pragma unroll
                  for (int j=0;j<4;j++)
                    acc[rg][cg][i][j] = fmaf(ar[rg][i], br[cg][j], acc[rg][cg][i][j]);
        }
        if (ks + 1 < KSTEPS) {
            const int nxt = cur ^ 1;
            As[nxt][aK+0][aRow] = aReg.x; As[nxt][aK+1][aRow] = aReg.y;
            As[nxt][aK+2][aRow] = aReg.z; As[nxt][aK+3][aRow] = aReg.w;
            *(float4*)&Bs[nxt][bK][bCol] = bReg;
            __syncthreads();
        }
    }

    #pragma unroll
    for (int rg=0; rg<2; rg++) {
        #pragma unroll
        for (int i=0;i<4;i++) {
            const int r = rowBase + ty*4 + rg*64 + i;
            if (r < 4000) {
                const int b = r / N_;
                const int n = r - b * N_;
                #pragma unroll
                for (int cg=0; cg<2; cg++) {
                    const int c = colBase + tx*4 + cg*64;
                    const int mat = c >> 8;
                    const int h   = (c >> 6) & 3;
                    const int u   = c & 63;
                    float* dst = (mat ? g_D : g_S) + ((size_t)(b*H_ + h)*N_ + n)*U_ + u;
                    float4 v = make_float4(acc[rg][cg][i][0], acc[rg][cg][i][1],
                                           acc[rg][cg][i][2], acc[rg][cg][i][3]);
                    *(float4*)dst = v;
                }
            }
        }
    }
}

// ---------------------------------------------------------------------------
// Kernel B: GATv2 scores + softmax -> attn written as single fp16 [b][n][hm]
// ---------------------------------------------------------------------------
__global__ __launch_bounds__(256)
void score_softmax_kernel(const float* __restrict__ aVec)
{
    extern __shared__ float sh[];
    float* Dsh = sh;                     // 512*65
    float* Ssh = Dsh + 512*65;           // 16*64
    float* aSh = Ssh + 16*64;            // 64 (+64 pad)
    float* sc  = aSh + 128;              // 16*500

    const int bh = blockIdx.y;           // b*4 + h
    const int b  = bh >> 2;
    const int h  = bh & 3;
    const int nBase = blockIdx.x * 16;
    const int tid = threadIdx.x;

    const float* Dg = g_D + (size_t)bh * N_ * U_;
    const float* Sg = g_S + (size_t)bh * N_ * U_;

    for (int idx = tid; idx < 512*16; idx += 256) {
        const int m = idx >> 4;
        const int u = (idx & 15) * 4;
        float4 v = (m < N_) ? *(const float4*)(Dg + m*U_ + u) : make_float4(0,0,0,0);
        float* dst = &Dsh[m*65 + u];
        dst[0]=v.x; dst[1]=v.y; dst[2]=v.z; dst[3]=v.w;
    }
    for (int idx = tid; idx < 16*16; idx += 256) {
        const int r = idx >> 4;
        const int u = (idx & 15) * 4;
        const int n = nBase + r;
        float4 v = (n < N_) ? *(const float4*)(Sg + n*U_ + u) : make_float4(0,0,0,0);
        float* dst = &Ssh[r*U_ + u];
        dst[0]=v.x; dst[1]=v.y; dst[2]=v.z; dst[3]=v.w;
    }
    if (tid < 64) aSh[tid] = aVec[h*U_ + tid];
    __syncthreads();

    const int tx  = tid & 63;
    const int tyy = tid >> 6;

    float acc[4][8];
    #pragma unroll
    for (int i=0;i<4;i++)
        #pragma unroll
        for (int k=0;k<8;k++) acc[i][k]=0.f;

    for (int u = 0; u < U_; u++) {
        const float au = aSh[u];
        float s[4];
        #pragma unroll
        for (int i=0;i<4;i++) s[i] = Ssh[(tyy*4+i)*U_ + u];
        #pragma unroll
        for (int k=0;k<8;k++) {
            const float d = Dsh[(tx + 64*k)*65 + u];
            #pragma unroll
            for (int i=0;i<4;i++) {
                const float t  = s[i] + d;
                const float lr = fmaxf(t, 0.2f * t);
                acc[i][k] = fmaf(au, lr, acc[i][k]);
            }
        }
    }
    #pragma unroll
    for (int i=0;i<4;i++)
        #pragma unroll
        for (int k=0;k<8;k++) {
            const int m = tx + 64*k;
            if (m < N_) sc[(tyy*4+i)*N_ + m] = acc[i][k];
        }
    __syncthreads();

    const int warp = tid >> 5, lane = tid & 31;
    #pragma unroll
    for (int rr = 0; rr < 2; rr++) {
        const int r = warp*2 + rr;
        const int n = nBase + r;
        float mx = -1e30f;
        for (int m = lane; m < N_; m += 32) mx = fmaxf(mx, sc[r*N_+m]);
        #pragma unroll
        for (int o=16;o>0;o>>=1) mx = fmaxf(mx, __shfl_xor_sync(0xffffffffu, mx, o));
        float sum = 0.f;
        for (int m = lane; m < N_; m += 32) {
            const float e = __expf(sc[r*N_+m] - mx);
            sc[r*N_+m] = e;
            sum += e;
        }
        #pragma unroll
        for (int o=16;o>0;o>>=1) sum += __shfl_xor_sync(0xffffffffu, sum, o);
        const float inv = 1.f / sum;
        if (n < N_) {
            __half* dH = g_attn + ((size_t)b*N_ + n)*HM_ + (size_t)h*N_;
            for (int m = lane; m < N_; m += 32)
                dH[m] = __float2half_rn(sc[r*N_+m]*inv);
        }
    }
}

// ---------------------------------------------------------------------------
// Kernel C: msg GEMM on tensor cores (3-term fp16 split, K=128 resident).
// B now cp.async'd coalesced from precomputed g_WT_hi/lo; epilogue stores
// coalesced along m (warp = 32 consecutive m-quads).
// ---------------------------------------------------------------------------
#define QRS    272                        // smem row stride (17 x 16B, odd units)
#define QAHI   0
#define QALO   (128*QRS)                  // 34816
#define QWHI   (2*128*QRS)                // 69632
#define QWLO   (QWHI + 256*QRS)           // 139264
#define QSMEM  (QWLO + 256*QRS)           // 208896
#define QCS    257                        // C staging stride (fp32 words, odd)

__global__ __launch_bounds__(512, 1)
void msg_mma(const float* __restrict__ curr)
{
    extern __shared__ __align__(128) char smq[];
    const uint32_t sbase = smem_u32(smq);
    const int tid  = threadIdx.x;
    const int wid  = tid >> 5;
    const int lane = tid & 31;
    const int r0   = blockIdx.x * 128;

    // ---- B: cp.async coalesced from precomputed WT (256 rows x 16 segs) ----
    #pragma unroll
    for (int i = 0; i < 8; i++) {
        const int g = tid + i*512;              // 0..4095
        const int n = g >> 4;
        const int s = g & 15;
        cp16(sbase + QWHI + n*QRS + s*16, g_WT_hi + n*128 + s*8, true);
        cp16(sbase + QWLO + n*QRS + s*16, g_WT_lo + n*128 + s*8, true);
    }
    cp_commit();

    // ---- A: curr rows -> split fp16 smem.  128 rows x 16 segs (8 d each) ----
    #pragma unroll
    for (int i = 0; i < 4; i++) {
        const int g   = tid + i*512;            // 0..2047
        const int row = g >> 4;
        const int s   = g & 15;
        const float* src = curr + (size_t)(r0 + row)*DC_ + s*8;
        float4 v0 = *(const float4*)(src);
        float4 v1 = *(const float4*)(src + 4);
        union { __half x[8]; uint4 v; } ph, pl;
        f16_split(v0.x, ph.x[0], pl.x[0]);
        f16_split(v0.y, ph.x[1], pl.x[1]);
        f16_split(v0.z, ph.x[2], pl.x[2]);
        f16_split(v0.w, ph.x[3], pl.x[3]);
        f16_split(v1.x, ph.x[4], pl.x[4]);
        f16_split(v1.y, ph.x[5], pl.x[5]);
        f16_split(v1.z, ph.x[6], pl.x[6]);
        f16_split(v1.w, ph.x[7], pl.x[7]);
        *(uint4*)(smq + QAHI + row*QRS + s*16) = ph.v;
        *(uint4*)(smq + QALO + row*QRS + s*16) = pl.v;
    }
    cp_wait<0>();
    __syncthreads();

    // ---- MMA: 16 warps, warp tile 64(m) x 32(n); 8 k16 steps, no syncs ----
    const int wm = wid & 1;        // 2 m-bands of 64
    const int wn = wid >> 1;       // 8 n-bands of 32
    const uint32_t aRowOff = (lane & 7) + ((lane >> 3) & 1) * 8;
    const uint32_t aSegOff = (lane >> 4) * 16;
    const uint32_t bRowOff = (lane & 7) + (lane >> 4) * 8;
    const uint32_t bSegOff = ((lane >> 3) & 1) * 16;

    float acc[4][4][4] = {};       // [mt][nt][4]
    const uint32_t sAh = sbase + QAHI;
    const uint32_t sWh = sbase + QWHI;

    #pragma unroll
    for (int k16 = 0; k16 < 8; k16++) {
        const uint32_t kb = k16*32;
        uint32_t bh[2][4], bl[2][4];
        #pragma unroll
        for (int p = 0; p < 2; p++) {
            const uint32_t addr = sWh + (wn*32 + p*16 + bRowOff)*QRS + kb + bSegOff;
            ldsm_x4(bh[p], addr);
            ldsm_x4(bl[p], addr + (QWLO - QWHI));
        }
        #pragma unroll
        for (int mt = 0; mt < 4; mt++) {
            const uint32_t aaddr = sAh + (wm*64 + mt*16 + aRowOff)*QRS + kb + aSegOff;
            uint32_t a[4], a2[4];
            ldsm_x4(a, aaddr);
            ldsm_x4(a2, aaddr + (QALO - QAHI));
            #pragma unroll
            for (int nt = 0; nt < 4; nt++) {
                const uint32_t* ph = &bh[nt >> 1][(nt & 1)*2];
                const uint32_t* pl = &bl[nt >> 1][(nt & 1)*2];
                mma16816h(acc[mt][nt], a,  ph);
                mma16816h(acc[mt][nt], a,  pl);
                mma16816h(acc[mt][nt], a2, ph);
            }
        }
    }

    // ---- Stage C (fp32 scalar, odd stride) in smem ----
    __syncthreads();
    float* Cs = (float*)smq;               // [128][QCS]; 128*257*4 = 131584 <= QSMEM
    const int cr0 = wm*64 + (lane >> 2);
    const int cc0 = wn*32 + (lane & 3)*2;
    #pragma unroll
    for (int mt = 0; mt < 4; mt++) {
        #pragma unroll
        for (int half = 0; half < 2; half++) {
            const int r = cr0 + mt*16 + half*8;
            #pragma unroll
            for (int nt = 0; nt < 4; nt++) {
                Cs[r*QCS + cc0 + nt*8]     = acc[mt][nt][half*2+0];
                Cs[r*QCS + cc0 + nt*8 + 1] = acc[mt][nt][half*2+1];
            }
        }
    }
    __syncthreads();

    // ---- Transposed fp16 store: warp = 32 consecutive m-quads (coalesced) ----
    #pragma unroll
    for (int i = 0; i < 16; i++) {
        const int g  = tid + i*512;      // 0..8191
        const int mq = g & 31;           // == lane
        const int c  = g >> 5;           // 0..255
        const int rloc = mq*4;
        const int rg = r0 + rloc;
        const int bb  = rg / (T_*N_);
        const int rem = rg - bb*(T_*N_);
        const int t   = rem / N_;
        const int m   = rem - t*N_;      // 4-aligned; quad never crosses t (500%4==0)
        const int h   = c >> 6;
        const int u   = c & 63;
        union { __half x[4]; uint2 v; } p;
        #pragma unroll
        for (int j = 0; j < 4; j++)
            p.x[j] = __float2half_rn(Cs[(rloc + j)*QCS + c]);
        const size_t off = ((size_t)bb*TU_ + t*U_ + u)*HM_ + (size_t)h*N_ + m;
        *(uint2*)&g_msgT[off] = p.v;
    }
}

// ---------------------------------------------------------------------------
// Kernel D: mix GEMM via mma.sync (single fp16 A and B), 2 CTAs/SM,
// 4-stage cp.async pipeline (prefetch distance 3).  (unchanged from R12)
// ---------------------------------------------------------------------------
#define MIX_KC    32
#define MIX_NCH   63          // ceil(2000/32), zero-filled to 2016
#define MRS       80          // smem row stride bytes (64B data + 16B pad)
#define MTILE     10240       // 128 rows * 80B
#define MSTAGE    (2*MTILE)   // A, B = 20480
#define MNSTG     4
#define MSM_TOTAL (MNSTG*MSTAGE)  // 81920

__device__ __forceinline__ void mix_load_chunk(
    uint32_t sstage, int kc, int tid, int b, int mBase, int nBase)
{
    const __half* Am = g_attn + (size_t)b * N_ * HM_;
    const __half* Bm = g_msgT + (size_t)b * TU_ * HM_;
    #pragma unroll
    for (int i = 0; i < 4; i++) {
        const int g    = tid + i*256;       // 0..1023
        const int tile = g >> 9;            // 0:A 1:B
        const int rem  = g & 511;
        const int row  = rem >> 2;
        const int seg  = rem & 3;
        const int k    = kc + seg*8;
        const uint32_t dst = sstage + tile*MTILE + row*MRS + seg*16;
        if (tile == 0) {
            const int n = mBase + row;
            const bool ok = (n < N_) && (k < HM_);
            cp16(dst, Am + (ok ? ((size_t)n*HM_ + k) : 0), ok);
        } else {
            const bool ok = (k < HM_);
            cp16(dst, Bm + (ok ? ((size_t)(nBase + row)*HM_ + k) : 0), ok);
        }
    }
    cp_commit();
}

__global__ __launch_bounds__(256, 2)
void mix_mma(float* __restrict__ out)
{
    extern __shared__ __align__(128) char smx[];
    const uint32_t sbase = smem_u32(smx);
    const int tid  = threadIdx.x;
    const int wid  = tid >> 5;
    const int lane = tid & 31;
    const int b     = blockIdx.z;
    const int mBase = blockIdx.x * 128;
    const int nBase = blockIdx.y * 128;

    const int wm = wid & 1;       // m band (2 x 64)
    const int wn = wid >> 1;      // n band (4 x 32)

    const uint32_t aRowOff = (lane & 7) + ((lane >> 3) & 1) * 8;
    const uint32_t aSegOff = (lane >> 4) * 16;
    const uint32_t bRowOff = (lane & 7) + (lane >> 4) * 8;
    const uint32_t bSegOff = ((lane >> 3) & 1) * 16;

    float acc[4][4][4] = {};   // [mt][nt][4]

    mix_load_chunk(sbase + 0*MSTAGE, 0*MIX_KC, tid, b, mBase, nBase);
    mix_load_chunk(sbase + 1*MSTAGE, 1*MIX_KC, tid, b, mBase, nBase);
    mix_load_chunk(sbase + 2*MSTAGE, 2*MIX_KC, tid, b, mBase, nBase);

    int sc = 0;
    for (int c = 0; c < MIX_NCH; c++) {
        if (c + 3 < MIX_NCH) {
            const int ns = (sc + 3) & 3;
            mix_load_chunk(sbase + ns*MSTAGE, (c+3)*MIX_KC, tid, b, mBase, nBase);
            cp_wait<3>();
        } else if (c + 2 < MIX_NCH) {
            cp_wait<2>();
        } else if (c + 1 < MIX_NCH) {
            cp_wait<1>();
        } else {
            cp_wait<0>();
        }
        __syncthreads();

        const uint32_t sA = sbase + sc*MSTAGE;
        const uint32_t sB = sA + MTILE;

        #pragma unroll
        for (int k16 = 0; k16 < 2; k16++) {
            const uint32_t kb = k16*32;
            uint32_t bb[2][4];
            #pragma unroll
            for (int p = 0; p < 2; p++) {
                ldsm_x4(bb[p], sB + (wn*32 + p*16 + bRowOff)*MRS + kb + bSegOff);
            }
            #pragma unroll
            for (int mt = 0; mt < 4; mt++) {
                uint32_t a[4];
                ldsm_x4(a, sA + (wm*64 + mt*16 + aRowOff)*MRS + kb + aSegOff);
                #pragma unroll
                for (int nt = 0; nt < 4; nt++) {
                    mma16816h(acc[mt][nt], a, &bb[nt >> 1][(nt & 1)*2]);
                }
            }
        }
        __syncthreads();
        sc = (sc + 1) & 3;
    }

    // Epilogue
    const int r0 = mBase + wm*64 + (lane >> 2);
    const int c0 = nBase + wn*32 + (lane & 3)*2;
    #pragma unroll
    for (int mt = 0; mt < 4; mt++) {
        #pragma unroll
        for (int half = 0; half < 2; half++) {
            const int n = r0 + mt*16 + half*8;
            if (n < N_) {
                #pragma unroll
                for (int nt = 0; nt < 4; nt++) {
                    const int cc = c0 + nt*8;
                    const int t  = cc >> 6;
                    const int u  = cc & 63;
                    float2 v = make_float2(acc[mt][nt][half*2+0]*0.25f,
                                           acc[mt][nt][half*2+1]*0.25f);
                    *(float2*)&out[(((size_t)b*T_ + t)*N_ + n)*U_ + u] = v;
                }
            }
        }
    }
}

// ---------------------------------------------------------------------------
extern "C" void kernel_launch(void* const* d_in, const int* in_sizes, int n_in,
                              void* d_out, int out_size)
{
    const float* prev = (const float*)d_in[0];   // [8,500,200]
    const float* curr = (const float*)d_in[1];   // [8,32,500,128]
    const float* Wsrc = (const float*)d_in[2];   // [4,200,64]
    const float* Wdst = (const float*)d_in[3];   // [4,200,64]
    const float* aV   = (const float*)d_in[4];   // [4,64,1]
    const float* Wmsg = (const float*)d_in[5];   // [4,128,64]
    float* out = (float*)d_out;                  // [8,32,500,64]

    // W: Wmsg transpose+split (once per launch; stream-ordered before msg_mma)
    wprep<<<16, 256>>>(Wmsg);

    // A: projections  (M=4000, N=512, K=200)
    proj_gemm<<<dim3(32, 4), 256>>>(prev, Wsrc, Wdst);

    // B: scores + softmax -> single fp16 attn
    const size_t shB = (size_t)(512*65 + 16*64 + 128 + 16*500) * sizeof(float);
    cudaFuncSetAttribute(score_softmax_kernel,
                         cudaFuncAttributeMaxDynamicSharedMemorySize, (int)shB);
    score_softmax_kernel<<<dim3(32, 32), 256, shB>>>(aV);

    // C: msg GEMM on tensor cores -> transposed single-fp16 msgT
    cudaFuncSetAttribute(msg_mma,
                         cudaFuncAttributeMaxDynamicSharedMemorySize, QSMEM);
    msg_mma<<<1000, 512, QSMEM>>>(curr);

    // D: mix GEMM on tensor cores (per batch: M=500, N=2048, K=2000), 2 CTAs/SM
    cudaFuncSetAttribute(mix_mma,
                         cudaFuncAttributeMaxDynamicSharedMemorySize, MSM_TOTAL);
    mix_mma<<<dim3(4, 16, 8), 256, MSM_TOTAL>>>(out);
}

// round 14
// speedup vs baseline: 2.7487x; 1.1313x over previous
#include <cuda_runtime.h>
#include <cuda_bf16.h>
#include <cuda_fp16.h>
#include <cstdint>
#include <cstddef>

// Problem constants
#define B_   8
#define T_   32
#define N_   500
#define DP_  200
#define DC_  128
#define H_   4
#define U_   64
#define HM_  2000   // H_*N_  (K dim of mix GEMM)
#define TU_  2048   // T_*U_  (N dim of mix GEMM)

// Scratch (device globals: allocation-free rule)
__device__ float g_S[B_*H_*N_*U_];                    // [b][h][n][u]
__device__ float g_D[B_*H_*N_*U_];                    // [b][h][m][u]
__device__ __half g_attn[(size_t)B_*N_*HM_];          // [b][n][hm] single fp16
__device__ __half g_msgT[(size_t)B_*TU_*HM_];         // [b][tu][hm] single fp16
__device__ __half g_WT[256*128];                      // [(h,u)][d] Wmsg^T fp16

// ---------------------------------------------------------------------------
// Helpers (compute_103-safe: cp.async / ldmatrix / mma.sync)
// ---------------------------------------------------------------------------
__device__ __forceinline__ uint32_t smem_u32(const void* p) {
    uint32_t a;
    asm("{ .reg .u64 t; cvta.to.shared.u64 t, %1; cvt.u32.u64 %0, t; }" : "=r"(a) : "l"(p));
    return a;
}
__device__ __forceinline__ void cp16(uint32_t dst, const void* src, bool ok) {
    int sz = ok ? 16 : 0;   // src-size 0 => zero-fill 16B
    asm volatile("cp.async.cg.shared.global [%0], [%1], 16, %2;" :: "r"(dst), "l"(src), "r"(sz) : "memory");
}
__device__ __forceinline__ void cp_commit() {
    asm volatile("cp.async.commit_group;" ::: "memory");
}
template <int NW>
__device__ __forceinline__ void cp_wait() {
    asm volatile("cp.async.wait_group %0;" :: "n"(NW) : "memory");
}
__device__ __forceinline__ void ldsm_x4(uint32_t* r, uint32_t addr) {
    asm volatile("ldmatrix.sync.aligned.m8n8.x4.shared.b16 {%0,%1,%2,%3}, [%4];"
                 : "=r"(r[0]), "=r"(r[1]), "=r"(r[2]), "=r"(r[3]) : "r"(addr));
}
// fp16 MMA, fp32 accumulate
__device__ __forceinline__ void mma16816h(float* c, const uint32_t* a, const uint32_t* b) {
    asm volatile(
        "mma.sync.aligned.m16n8k16.row.col.f32.f16.f16.f32 "
        "{%0,%1,%2,%3}, {%4,%5,%6,%7}, {%8,%9}, {%0,%1,%2,%3};"
        : "+f"(c[0]), "+f"(c[1]), "+f"(c[2]), "+f"(c[3])
        : "r"(a[0]), "r"(a[1]), "r"(a[2]), "r"(a[3]), "r"(b[0]), "r"(b[1]));
}

// ---------------------------------------------------------------------------
// Kernel W: one-shot Wmsg transpose -> g_WT [(h,u)][d] fp16
// ---------------------------------------------------------------------------
__global__ __launch_bounds__(256)
void wprep(const float* __restrict__ Wmsg)
{
    const int g = blockIdx.x * 256 + threadIdx.x;   // 0..4095
    const int n = g >> 4;          // (h,u) row
    const int s = g & 15;          // 8-d segment
    const int h = n >> 6;
    const int u = n & 63;
    const int d0 = s * 8;
    union { __half x[8]; uint4 v; } ph;
    #pragma unroll
    for (int j = 0; j < 8; j++) {
        const float w = __ldg(Wmsg + h*(DC_*U_) + (d0 + j)*U_ + u);
        ph.x[j] = __float2half_rn(w);
    }
    *(uint4*)&g_WT[n*128 + d0] = ph.v;
}

// ---------------------------------------------------------------------------
// Kernel A: projections.  GEMM M=4000 (b*500+n), K=200, Ncols=512
// ---------------------------------------------------------------------------
__global__ __launch_bounds__(256, 2)
void proj_gemm(const float* __restrict__ prev,
               const float* __restrict__ Wsrc,
               const float* __restrict__ Wdst)
{
    const int rowBase = blockIdx.x * 128;
    const int colBase = blockIdx.y * 128;

    __shared__ float As[2][8][132];
    __shared__ float Bs[2][8][128];

    const int tid  = threadIdx.x;
    const int aRow = tid >> 1;
    const int aK   = (tid & 1) * 4;
    const int bK   = tid >> 5;
    const int bCol = (tid & 31) * 4;
    const int tx   = tid & 15;
    const int ty   = tid >> 4;

    const int gRow  = rowBase + aRow;
    const bool rowOk = gRow < 4000;
    const float* aPtr = prev + (size_t)gRow * DP_ + aK;

    const int cB   = colBase + bCol;
    const int matB = cB >> 8;
    const int hB   = (cB >> 6) & 3;
    const int uB   = cB & 63;
    const float* bPtr = (matB ? Wdst : Wsrc) + hB * (DP_*U_) + bK * U_ + uB;

    const int KSTEPS = DP_ / 8;  // 25

    float4 aReg = rowOk ? *(const float4*)aPtr : make_float4(0,0,0,0);
    float4 bReg = *(const float4*)bPtr;

    As[0][aK+0][aRow] = aReg.x; As[0][aK+1][aRow] = aReg.y;
    As[0][aK+2][aRow] = aReg.z; As[0][aK+3][aRow] = aReg.w;
    *(float4*)&Bs[0][bK][bCol] = bReg;
    __syncthreads();

    float acc[2][2][4][4] = {};

    for (int ks = 0; ks < KSTEPS; ks++) {
        const int cur = ks & 1;
        if (ks + 1 < KSTEPS) {
            aReg = rowOk ? *(const float4*)(aPtr + (ks+1)*8) : make_float4(0,0,0,0);
            bReg = *(const float4*)(bPtr + (ks+1)*8*U_);
        }
        #pragma unroll
        for (int kk = 0; kk < 8; kk++) {
            float ar[2][4], br[2][4];
            *(float4*)ar[0] = *(const float4*)&As[cur][kk][ty*4];
            *(float4*)ar[1] = *(const float4*)&As[cur][kk][ty*4 + 64];
            *(float4*)br[0] = *(const float4*)&Bs[cur][kk][tx*4];
            *(float4*)br[1] = *(const float4*)&Bs[cur][kk][tx*4 + 64];
            #pragma unroll
            for (int rg=0; rg<2; rg++)
              #pragma unroll
              for (int cg=0; cg<2; cg++)
                #pragma unroll
                for (int i=0;i<4;i++)
                  #pragma unroll
                  for (int j=0;j<4;j++)
                    acc[rg][cg][i][j] = fmaf(ar[rg][i], br[cg][j], acc[rg][cg][i][j]);
        }
        if (ks + 1 < KSTEPS) {
            const int nxt = cur ^ 1;
            As[nxt][aK+0][aRow] = aReg.x; As[nxt][aK+1][aRow] = aReg.y;
            As[nxt][aK+2][aRow] = aReg.z; As[nxt][aK+3][aRow] = aReg.w;
            *(float4*)&Bs[nxt][bK][bCol] = bReg;
            __syncthreads();
        }
    }

    #pragma unroll
    for (int rg=0; rg<2; rg++) {
        #pragma unroll
        for (int i=0;i<4;i++) {
            const int r = rowBase + ty*4 + rg*64 + i;
            if (r < 4000) {
                const int b = r / N_;
                const int n = r - b * N_;
                #pragma unroll
                for (int cg=0; cg<2; cg++) {
                    const int c = colBase + tx*4 + cg*64;
                    const int mat = c >> 8;
                    const int h   = (c >> 6) & 3;
                    const int u   = c & 63;
                    float* dst = (mat ? g_D : g_S) + ((size_t)(b*H_ + h)*N_ + n)*U_ + u;
                    float4 v = make_float4(acc[rg][cg][i][0], acc[rg][cg][i][1],
                                           acc[rg][cg][i][2], acc[rg][cg][i][3]);
                    *(float4*)dst = v;
                }
            }
        }
    }
}

// ---------------------------------------------------------------------------
// Kernel B: GATv2 scores + softmax -> attn written as single fp16 [b][n][hm]
// ---------------------------------------------------------------------------
__global__ __launch_bounds__(256)
void score_softmax_kernel(const float* __restrict__ aVec)
{
    extern __shared__ float sh[];
    float* Dsh = sh;                     // 512*65
    float* Ssh = Dsh + 512*65;           // 16*64
    float* aSh = Ssh + 16*64;            // 64 (+64 pad)
    float* sc  = aSh + 128;              // 16*500

    const int bh = blockIdx.y;           // b*4 + h
    const int b  = bh >> 2;
    const int h  = bh & 3;
    const int nBase = blockIdx.x * 16;
    const int tid = threadIdx.x;

    const float* Dg = g_D + (size_t)bh * N_ * U_;
    const float* Sg = g_S + (size_t)bh * N_ * U_;

    for (int idx = tid; idx < 512*16; idx += 256) {
        const int m = idx >> 4;
        const int u = (idx & 15) * 4;
        float4 v = (m < N_) ? *(const float4*)(Dg + m*U_ + u) : make_float4(0,0,0,0);
        float* dst = &Dsh[m*65 + u];
        dst[0]=v.x; dst[1]=v.y; dst[2]=v.z; dst[3]=v.w;
    }
    for (int idx = tid; idx < 16*16; idx += 256) {
        const int r = idx >> 4;
        const int u = (idx & 15) * 4;
        const int n = nBase + r;
        float4 v = (n < N_) ? *(const float4*)(Sg + n*U_ + u) : make_float4(0,0,0,0);
        float* dst = &Ssh[r*U_ + u];
        dst[0]=v.x; dst[1]=v.y; dst[2]=v.z; dst[3]=v.w;
    }
    if (tid < 64) aSh[tid] = aVec[h*U_ + tid];
    __syncthreads();

    const int tx  = tid & 63;
    const int tyy = tid >> 6;

    float acc[4][8];
    #pragma unroll
    for (int i=0;i<4;i++)
        #pragma unroll
        for (int k=0;k<8;k++) acc[i][k]=0.f;

    for (int u = 0; u < U_; u++) {
        const float au = aSh[u];
        float s[4];
        #pragma unroll
        for (int i=0;i<4;i++) s[i] = Ssh[(tyy*4+i)*U_ + u];
        #pragma unroll
        for (int k=0;k<8;k++) {
            const float d = Dsh[(tx + 64*k)*65 + u];
            #pragma unroll
            for (int i=0;i<4;i++) {
                const float t  = s[i] + d;
                const float lr = fmaxf(t, 0.2f * t);
                acc[i][k] = fmaf(au, lr, acc[i][k]);
            }
        }
    }
    #pragma unroll
    for (int i=0;i<4;i++)
        #pragma unroll
        for (int k=0;k<8;k++) {
            const int m = tx + 64*k;
            if (m < N_) sc[(tyy*4+i)*N_ + m] = acc[i][k];
        }
    __syncthreads();

    const int warp = tid >> 5, lane = tid & 31;
    #pragma unroll
    for (int rr = 0; rr < 2; rr++) {
        const int r = warp*2 + rr;
        const int n = nBase + r;
        float mx = -1e30f;
        for (int m = lane; m < N_; m += 32) mx = fmaxf(mx, sc[r*N_+m]);
        #pragma unroll
        for (int o=16;o>0;o>>=1) mx = fmaxf(mx, __shfl_xor_sync(0xffffffffu, mx, o));
        float sum = 0.f;
        for (int m = lane; m < N_; m += 32) {
            const float e = __expf(sc[r*N_+m] - mx);
            sc[r*N_+m] = e;
            sum += e;
        }
        #pragma unroll
        for (int o=16;o>0;o>>=1) sum += __shfl_xor_sync(0xffffffffu, sum, o);
        const float inv = 1.f / sum;
        if (n < N_) {
            __half* dH = g_attn + ((size_t)b*N_ + n)*HM_ + (size_t)h*N_;
            for (int m = lane; m < N_; m += 32)
                dH[m] = __float2half_rn(sc[r*N_+m]*inv);
        }
    }
}

// ---------------------------------------------------------------------------
// Kernel C: msg GEMM on tensor cores (plain fp16, K=128 resident).
// CTA: 128 rows x 256 cols (h,u), K=128.  A = curr fp32->fp16, W from g_WT.
// Epilogue: two 64-row C-staging passes, coalesced fp16 stores along m.
// ---------------------------------------------------------------------------
#define QRS    272                        // smem row stride (17 x 16B, odd units)
#define QAHI   0
#define QWHI   (128*QRS)                  // 34816
#define QSMEM  (QWHI + 256*QRS)           // 104448
#define QCS    257                        // C staging stride (fp32 words, odd)

__global__ __launch_bounds__(512, 1)
void msg_mma(const float* __restrict__ curr)
{
    extern __shared__ __align__(128) char smq[];
    const uint32_t sbase = smem_u32(smq);
    const int tid  = threadIdx.x;
    const int wid  = tid >> 5;
    const int lane = tid & 31;
    const int r0   = blockIdx.x * 128;

    // ---- W: cp.async coalesced from precomputed WT (256 rows x 16 segs) ----
    #pragma unroll
    for (int i = 0; i < 8; i++) {
        const int g = tid + i*512;              // 0..4095
        const int n = g >> 4;
        const int s = g & 15;
        cp16(sbase + QWHI + n*QRS + s*16, g_WT + n*128 + s*8, true);
    }
    cp_commit();

    // ---- A: curr rows -> fp16 smem.  128 rows x 16 segs (8 d each) ----
    #pragma unroll
    for (int i = 0; i < 4; i++) {
        const int g   = tid + i*512;            // 0..2047
        const int row = g >> 4;
        const int s   = g & 15;
        const float* src = curr + (size_t)(r0 + row)*DC_ + s*8;
        float4 v0 = *(const float4*)(src);
        float4 v1 = *(const float4*)(src + 4);
        union { __half x[8]; uint4 v; } ph;
        ph.x[0] = __float2half_rn(v0.x);
        ph.x[1] = __float2half_rn(v0.y);
        ph.x[2] = __float2half_rn(v0.z);
        ph.x[3] = __float2half_rn(v0.w);
        ph.x[4] = __float2half_rn(v1.x);
        ph.x[5] = __float2half_rn(v1.y);
        ph.x[6] = __float2half_rn(v1.z);
        ph.x[7] = __float2half_rn(v1.w);
        *(uint4*)(smq + QAHI + row*QRS + s*16) = ph.v;
    }
    cp_wait<0>();
    __syncthreads();

    // ---- MMA: 16 warps, warp tile 64(m) x 32(n); 8 k16 steps ----
    const int wm = wid & 1;        // 2 m-bands of 64
    const int wn = wid >> 1;       // 8 n-bands of 32
    const uint32_t aRowOff = (lane & 7) + ((lane >> 3) & 1) * 8;
    const uint32_t aSegOff = (lane >> 4) * 16;
    const uint32_t bRowOff = (lane & 7) + (lane >> 4) * 8;
    const uint32_t bSegOff = ((lane >> 3) & 1) * 16;

    float acc[4][4][4] = {};       // [mt][nt][4]
    const uint32_t sAh = sbase + QAHI;
    const uint32_t sWh = sbase + QWHI;

    #pragma unroll
    for (int k16 = 0; k16 < 8; k16++) {
        const uint32_t kb = k16*32;
        uint32_t bh[2][4];
        #pragma unroll
        for (int p = 0; p < 2; p++) {
            ldsm_x4(bh[p], sWh + (wn*32 + p*16 + bRowOff)*QRS + kb + bSegOff);
        }
        #pragma unroll
        for (int mt = 0; mt < 4; mt++) {
            uint32_t a[4];
            ldsm_x4(a, sAh + (wm*64 + mt*16 + aRowOff)*QRS + kb + aSegOff);
            #pragma unroll
            for (int nt = 0; nt < 4; nt++) {
                mma16816h(acc[mt][nt], a, &bh[nt >> 1][(nt & 1)*2]);
            }
        }
    }

    // ---- Epilogue: two 64-row passes (C stage 64x257 fp32 = 65.8KB) ----
    float* Cs = (float*)smq;
    const int lr0 = (lane >> 2);            // 0..7 within band
    const int cc0 = wn*32 + (lane & 3)*2;

    #pragma unroll
    for (int pass = 0; pass < 2; pass++) {
        __syncthreads();                    // operand smem dead / prev store done
        if (wm == pass) {
            #pragma unroll
            for (int mt = 0; mt < 4; mt++) {
                #pragma unroll
                for (int half = 0; half < 2; half++) {
                    const int r = lr0 + mt*16 + half*8;   // 0..63 local
                    #pragma unroll
                    for (int nt = 0; nt < 4; nt++) {
                        Cs[r*QCS + cc0 + nt*8]     = acc[mt][nt][half*2+0];
                        Cs[r*QCS + cc0 + nt*8 + 1] = acc[mt][nt][half*2+1];
                    }
                }
            }
        }
        __syncthreads();

        // store 64 rows: 16 m-quads x 256 cols = 4096 items; 8 per thread
        #pragma unroll
        for (int i = 0; i < 8; i++) {
            const int g  = tid + i*512;     // 0..4095
            const int mq = g & 15;
            const int c  = g >> 4;          // 0..255
            const int rloc = mq*4;          // local row quad
            const int rg = r0 + pass*64 + rloc;
            const int bb  = rg / (T_*N_);
            const int rem = rg - bb*(T_*N_);
            const int t   = rem / N_;
            const int m   = rem - t*N_;     // 4-aligned; quad never crosses t
            const int h   = c >> 6;
            const int u   = c & 63;
            union { __half x[4]; uint2 v; } p;
            #pragma unroll
            for (int j = 0; j < 4; j++)
                p.x[j] = __float2half_rn(Cs[(rloc + j)*QCS + c]);
            const size_t off = ((size_t)bb*TU_ + t*U_ + u)*HM_ + (size_t)h*N_ + m;
            *(uint2*)&g_msgT[off] = p.v;
        }
    }
}

// ---------------------------------------------------------------------------
// Kernel D: mix GEMM via mma.sync (single fp16 A and B), 2 CTAs/SM,
// 4-stage cp.async pipeline (prefetch distance 3).  (unchanged from R12)
// ---------------------------------------------------------------------------
#define MIX_KC    32
#define MIX_NCH   63          // ceil(2000/32), zero-filled to 2016
#define MRS       80          // smem row stride bytes (64B data + 16B pad)
#define MTILE     10240       // 128 rows * 80B
#define MSTAGE    (2*MTILE)   // A, B = 20480
#define MNSTG     4
#define MSM_TOTAL (MNSTG*MSTAGE)  // 81920

__device__ __forceinline__ void mix_load_chunk(
    uint32_t sstage, int kc, int tid, int b, int mBase, int nBase)
{
    const __half* Am = g_attn + (size_t)b * N_ * HM_;
    const __half* Bm = g_msgT + (size_t)b * TU_ * HM_;
    #pragma unroll
    for (int i = 0; i < 4; i++) {
        const int g    = tid + i*256;       // 0..1023
        const int tile = g >> 9;            // 0:A 1:B
        const int rem  = g & 511;
        const int row  = rem >> 2;
        const int seg  = rem & 3;
        const int k    = kc + seg*8;
        const uint32_t dst = sstage + tile*MTILE + row*MRS + seg*16;
        if (tile == 0) {
            const int n = mBase + row;
            const bool ok = (n < N_) && (k < HM_);
            cp16(dst, Am + (ok ? ((size_t)n*HM_ + k) : 0), ok);
        } else {
            const bool ok = (k < HM_);
            cp16(dst, Bm + (ok ? ((size_t)(nBase + row)*HM_ + k) : 0), ok);
        }
    }
    cp_commit();
}

__global__ __launch_bounds__(256, 2)
void mix_mma(float* __restrict__ out)
{
    extern __shared__ __align__(128) char smx[];
    const uint32_t sbase = smem_u32(smx);
    const int tid  = threadIdx.x;
    const int wid  = tid >> 5;
    const int lane = tid & 31;
    const int b     = blockIdx.z;
    const int mBase = blockIdx.x * 128;
    const int nBase = blockIdx.y * 128;

    const int wm = wid & 1;       // m band (2 x 64)
    const int wn = wid >> 1;      // n band (4 x 32)

    const uint32_t aRowOff = (lane & 7) + ((lane >> 3) & 1) * 8;
    const uint32_t aSegOff = (lane >> 4) * 16;
    const uint32_t bRowOff = (lane & 7) + (lane >> 4) * 8;
    const uint32_t bSegOff = ((lane >> 3) & 1) * 16;

    float acc[4][4][4] = {};   // [mt][nt][4]

    mix_load_chunk(sbase + 0*MSTAGE, 0*MIX_KC, tid, b, mBase, nBase);
    mix_load_chunk(sbase + 1*MSTAGE, 1*MIX_KC, tid, b, mBase, nBase);
    mix_load_chunk(sbase + 2*MSTAGE, 2*MIX_KC, tid, b, mBase, nBase);

    int sc = 0;
    for (int c = 0; c < MIX_NCH; c++) {
        if (c + 3 < MIX_NCH) {
            const int ns = (sc + 3) & 3;
            mix_load_chunk(sbase + ns*MSTAGE, (c+3)*MIX_KC, tid, b, mBase, nBase);
            cp_wait<3>();
        } else if (c + 2 < MIX_NCH) {
            cp_wait<2>();
        } else if (c + 1 < MIX_NCH) {
            cp_wait<1>();
        } else {
            cp_wait<0>();
        }
        __syncthreads();

        const uint32_t sA = sbase + sc*MSTAGE;
        const uint32_t sB = sA + MTILE;

        #pragma unroll
        for (int k16 = 0; k16 < 2; k16++) {
            const uint32_t kb = k16*32;
            uint32_t bb[2][4];
            #pragma unroll
            for (int p = 0; p < 2; p++) {
                ldsm_x4(bb[p], sB + (wn*32 + p*16 + bRowOff)*MRS + kb + bSegOff);
            }
            #pragma unroll
            for (int mt = 0; mt < 4; mt++) {
                uint32_t a[4];
                ldsm_x4(a, sA + (wm*64 + mt*16 + aRowOff)*MRS + kb + aSegOff);
                #pragma unroll
                for (int nt = 0; nt < 4; nt++) {
                    mma16816h(acc[mt][nt], a, &bb[nt >> 1][(nt & 1)*2]);
                }
            }
        }
        __syncthreads();
        sc = (sc + 1) & 3;
    }

    // Epilogue
    const int r0 = mBase + wm*64 + (lane >> 2);
    const int c0 = nBase + wn*32 + (lane & 3)*2;
    #pragma unroll
    for (int mt = 0; mt < 4; mt++) {
        #pragma unroll
        for (int half = 0; half < 2; half++) {
            const int n = r0 + mt*16 + half*8;
            if (n < N_) {
                #pragma unroll
                for (int nt = 0; nt < 4; nt++) {
                    const int cc = c0 + nt*8;
                    const int t  = cc >> 6;
                    const int u  = cc & 63;
                    float2 v = make_float2(acc[mt][nt][half*2+0]*0.25f,
                                           acc[mt][nt][half*2+1]*0.25f);
                    *(float2*)&out[(((size_t)b*T_ + t)*N_ + n)*U_ + u] = v;
                }
            }
        }
    }
}

// ---------------------------------------------------------------------------
extern "C" void kernel_launch(void* const* d_in, const int* in_sizes, int n_in,
                              void* d_out, int out_size)
{
    const float* prev = (const float*)d_in[0];   // [8,500,200]
    const float* curr = (const float*)d_in[1];   // [8,32,500,128]
    const float* Wsrc = (const float*)d_in[2];   // [4,200,64]
    const float* Wdst = (const float*)d_in[3];   // [4,200,64]
    const float* aV   = (const float*)d_in[4];   // [4,64,1]
    const float* Wmsg = (const float*)d_in[5];   // [4,128,64]
    float* out = (float*)d_out;                  // [8,32,500,64]

    // W: Wmsg transpose (once per launch; stream-ordered before msg_mma)
    wprep<<<16, 256>>>(Wmsg);

    // A: projections  (M=4000, N=512, K=200)
    proj_gemm<<<dim3(32, 4), 256>>>(prev, Wsrc, Wdst);

    // B: scores + softmax -> single fp16 attn
    const size_t shB = (size_t)(512*65 + 16*64 + 128 + 16*500) * sizeof(float);
    cudaFuncSetAttribute(score_softmax_kernel,
                         cudaFuncAttributeMaxDynamicSharedMemorySize, (int)shB);
    score_softmax_kernel<<<dim3(32, 32), 256, shB>>>(aV);

    // C: msg GEMM on tensor cores (plain fp16) -> transposed msgT
    cudaFuncSetAttribute(msg_mma,
                         cudaFuncAttributeMaxDynamicSharedMemorySize, QSMEM);
    msg_mma<<<1000, 512, QSMEM>>>(curr);

    // D: mix GEMM on tensor cores (per batch: M=500, N=2048, K=2000), 2 CTAs/SM
    cudaFuncSetAttribute(mix_mma,
                         cudaFuncAttributeMaxDynamicSharedMemorySize, MSM_TOTAL);
    mix_mma<<<dim3(4, 16, 8), 256, MSM_TOTAL>>>(out);
}

// round 15
// speedup vs baseline: 3.0673x; 1.1159x over previous
#include <cuda_runtime.h>
#include <cuda_bf16.h>
#include <cuda_fp16.h>
#include <cstdint>
#include <cstddef>

// Problem constants
#define B_   8
#define T_   32
#define N_   500
#define DP_  200
#define DC_  128
#define H_   4
#define U_   64
#define HM_  2000   // H_*N_  (K dim of mix GEMM)
#define TU_  2048   // T_*U_  (N dim of mix GEMM)

// Scratch (device globals: allocation-free rule)
__device__ float g_S[B_*H_*N_*U_];                    // [b][h][n][u]
__device__ float g_D[B_*H_*N_*U_];                    // [b][h][m][u]
__device__ __half g_attn[(size_t)B_*N_*HM_];          // [b][n][hm] single fp16
__device__ __half g_msgT[(size_t)B_*TU_*HM_];         // [b][tu][hm] single fp16
__device__ __half g_WT[256*128];                      // [(h,u)][d] Wmsg^T fp16

// ---------------------------------------------------------------------------
// Helpers (compute_103-safe: cp.async / ldmatrix / mma.sync)
// ---------------------------------------------------------------------------
__device__ __forceinline__ uint32_t smem_u32(const void* p) {
    uint32_t a;
    asm("{ .reg .u64 t; cvta.to.shared.u64 t, %1; cvt.u32.u64 %0, t; }" : "=r"(a) : "l"(p));
    return a;
}
__device__ __forceinline__ void cp16(uint32_t dst, const void* src, bool ok) {
    int sz = ok ? 16 : 0;   // src-size 0 => zero-fill 16B
    asm volatile("cp.async.cg.shared.global [%0], [%1], 16, %2;" :: "r"(dst), "l"(src), "r"(sz) : "memory");
}
__device__ __forceinline__ void cp_commit() {
    asm volatile("cp.async.commit_group;" ::: "memory");
}
template <int NW>
__device__ __forceinline__ void cp_wait() {
    asm volatile("cp.async.wait_group %0;" :: "n"(NW) : "memory");
}
__device__ __forceinline__ void ldsm_x4(uint32_t* r, uint32_t addr) {
    asm volatile("ldmatrix.sync.aligned.m8n8.x4.shared.b16 {%0,%1,%2,%3}, [%4];"
                 : "=r"(r[0]), "=r"(r[1]), "=r"(r[2]), "=r"(r[3]) : "r"(addr));
}
// fp16 MMA, fp32 accumulate
__device__ __forceinline__ void mma16816h(float* c, const uint32_t* a, const uint32_t* b) {
    asm volatile(
        "mma.sync.aligned.m16n8k16.row.col.f32.f16.f16.f32 "
        "{%0,%1,%2,%3}, {%4,%5,%6,%7}, {%8,%9}, {%0,%1,%2,%3};"
        : "+f"(c[0]), "+f"(c[1]), "+f"(c[2]), "+f"(c[3])
        : "r"(a[0]), "r"(a[1]), "r"(a[2]), "r"(a[3]), "r"(b[0]), "r"(b[1]));
}

// ---------------------------------------------------------------------------
// Kernel W: one-shot Wmsg transpose -> g_WT [(h,u)][d] fp16
// ---------------------------------------------------------------------------
__global__ __launch_bounds__(256)
void wprep(const float* __restrict__ Wmsg)
{
    const int g = blockIdx.x * 256 + threadIdx.x;   // 0..4095
    const int n = g >> 4;          // (h,u) row
    const int s = g & 15;          // 8-d segment
    const int h = n >> 6;
    const int u = n & 63;
    const int d0 = s * 8;
    union { __half x[8]; uint4 v; } ph;
    #pragma unroll
    for (int j = 0; j < 8; j++) {
        const float w = __ldg(Wmsg + h*(DC_*U_) + (d0 + j)*U_ + u);
        ph.x[j] = __float2half_rn(w);
    }
    *(uint4*)&g_WT[n*128 + d0] = ph.v;
}

// ---------------------------------------------------------------------------
// Kernel A: projections.  GEMM M=4000 (b*500+n), K=200, Ncols=512
// ---------------------------------------------------------------------------
__global__ __launch_bounds__(256, 2)
void proj_gemm(const float* __restrict__ prev,
               const float* __restrict__ Wsrc,
               const float* __restrict__ Wdst)
{
    const int rowBase = blockIdx.x * 128;
    const int colBase = blockIdx.y * 128;

    __shared__ float As[2][8][132];
    __shared__ float Bs[2][8][128];

    const int tid  = threadIdx.x;
    const int aRow = tid >> 1;
    const int aK   = (tid & 1) * 4;
    const int bK   = tid >> 5;
    const int bCol = (tid & 31) * 4;
    const int tx   = tid & 15;
    const int ty   = tid >> 4;

    const int gRow  = rowBase + aRow;
    const bool rowOk = gRow < 4000;
    const float* aPtr = prev + (size_t)gRow * DP_ + aK;

    const int cB   = colBase + bCol;
    const int matB = cB >> 8;
    const int hB   = (cB >> 6) & 3;
    const int uB   = cB & 63;
    const float* bPtr = (matB ? Wdst : Wsrc) + hB * (DP_*U_) + bK * U_ + uB;

    const int KSTEPS = DP_ / 8;  // 25

    float4 aReg = rowOk ? *(const float4*)aPtr : make_float4(0,0,0,0);
    float4 bReg = *(const float4*)bPtr;

    As[0][aK+0][aRow] = aReg.x; As[0][aK+1][aRow] = aReg.y;
    As[0][aK+2][aRow] = aReg.z; As[0][aK+3][aRow] = aReg.w;
    *(float4*)&Bs[0][bK][bCol] = bReg;
    __syncthreads();

    float acc[2][2][4][4] = {};

    for (int ks = 0; ks < KSTEPS; ks++) {
        const int cur = ks & 1;
        if (ks + 1 < KSTEPS) {
            aReg = rowOk ? *(const float4*)(aPtr + (ks+1)*8) : make_float4(0,0,0,0);
            bReg = *(const float4*)(bPtr + (ks+1)*8*U_);
        }
        #pragma unroll
        for (int kk = 0; kk < 8; kk++) {
            float ar[2][4], br[2][4];
            *(float4*)ar[0] = *(const float4*)&As[cur][kk][ty*4];
            *(float4*)ar[1] = *(const float4*)&As[cur][kk][ty*4 + 64];
            *(float4*)br[0] = *(const float4*)&Bs[cur][kk][tx*4];
            *(float4*)br[1] = *(const float4*)&Bs[cur][kk][tx*4 + 64];
            #pragma unroll
            for (int rg=0; rg<2; rg++)
              #pragma unroll
              for (int cg=0; cg<2; cg++)
                #pragma unroll
                for (int i=0;i<4;i++)
                  #pragma unroll
                  for (int j=0;j<4;j++)
                    acc[rg][cg][i][j] = fmaf(ar[rg][i], br[cg][j], acc[rg][cg][i][j]);
        }
        if (ks + 1 < KSTEPS) {
            const int nxt = cur ^ 1;
            As[nxt][aK+0][aRow] = aReg.x; As[nxt][aK+1][aRow] = aReg.y;
            As[nxt][aK+2][aRow] = aReg.z; As[nxt][aK+3][aRow] = aReg.w;
            *(float4*)&Bs[nxt][bK][bCol] = bReg;
            __syncthreads();
        }
    }

    #pragma unroll
    for (int rg=0; rg<2; rg++) {
        #pragma unroll
        for (int i=0;i<4;i++) {
            const int r = rowBase + ty*4 + rg*64 + i;
            if (r < 4000) {
                const int b = r / N_;
                const int n = r - b * N_;
                #pragma unroll
                for (int cg=0; cg<2; cg++) {
                    const int c = colBase + tx*4 + cg*64;
                    const int mat = c >> 8;
                    const int h   = (c >> 6) & 3;
                    const int u   = c & 63;
                    float* dst = (mat ? g_D : g_S) + ((size_t)(b*H_ + h)*N_ + n)*U_ + u;
                    float4 v = make_float4(acc[rg][cg][i][0], acc[rg][cg][i][1],
                                           acc[rg][cg][i][2], acc[rg][cg][i][3]);
                    *(float4*)dst = v;
                }
            }
        }
    }
}

// ---------------------------------------------------------------------------
// Kernel B: GATv2 scores + softmax -> single fp16 attn [b][n][hm].
// Uses lrelu(x) = 0.6x + 0.4|x|:
//   score[n][m] = 0.6*(sa[n]+da[m]) + 0.4*sum_u a_u*|S[n,u]+D[m,u]|
// Inner loop: FADD + FFMA(|x|) = 2 ops/tuple (was 4).
// ---------------------------------------------------------------------------
__global__ __launch_bounds__(256)
void score_softmax_kernel(const float* __restrict__ aVec)
{
    extern __shared__ float sh[];
    float* Dsh = sh;                     // 512*65
    float* Ssh = Dsh + 512*65;           // 16*64
    float* aSh = Ssh + 16*64;            // 64 (+64 pad)
    float* sc  = aSh + 128;              // 16*500
    float* daSh = sc + 16*500;           // 512
    float* saSh = daSh + 512;            // 16

    const int bh = blockIdx.y;           // b*4 + h
    const int b  = bh >> 2;
    const int h  = bh & 3;
    const int nBase = blockIdx.x * 16;
    const int tid = threadIdx.x;

    const float* Dg = g_D + (size_t)bh * N_ * U_;
    const float* Sg = g_S + (size_t)bh * N_ * U_;

    for (int idx = tid; idx < 512*16; idx += 256) {
        const int m = idx >> 4;
        const int u = (idx & 15) * 4;
        float4 v = (m < N_) ? *(const float4*)(Dg + m*U_ + u) : make_float4(0,0,0,0);
        float* dst = &Dsh[m*65 + u];
        dst[0]=v.x; dst[1]=v.y; dst[2]=v.z; dst[3]=v.w;
    }
    for (int idx = tid; idx < 16*16; idx += 256) {
        const int r = idx >> 4;
        const int u = (idx & 15) * 4;
        const int n = nBase + r;
        float4 v = (n < N_) ? *(const float4*)(Sg + n*U_ + u) : make_float4(0,0,0,0);
        float* dst = &Ssh[r*U_ + u];
        dst[0]=v.x; dst[1]=v.y; dst[2]=v.z; dst[3]=v.w;
    }
    if (tid < 64) aSh[tid] = aVec[h*U_ + tid];
    __syncthreads();

    // Rank-1 precomputes: da[m] = sum_u a_u*D[m,u];  sa[r] = sum_u a_u*S[r,u]
    for (int m = tid; m < 512; m += 256) {
        float s = 0.f;
        #pragma unroll 16
        for (int u = 0; u < U_; u++) s = fmaf(aSh[u], Dsh[m*65 + u], s);
        daSh[m] = s;
    }
    if (tid < 16) {
        float s = 0.f;
        #pragma unroll 16
        for (int u = 0; u < U_; u++) s = fmaf(aSh[u], Ssh[tid*U_ + u], s);
        saSh[tid] = s;
    }
    __syncthreads();

    const int tx  = tid & 63;
    const int tyy = tid >> 6;

    float acc[4][8];
    #pragma unroll
    for (int i=0;i<4;i++)
        #pragma unroll
        for (int k=0;k<8;k++) acc[i][k]=0.f;

    for (int u = 0; u < U_; u++) {
        const float au = aSh[u];
        float s[4];
        #pragma unroll
        for (int i=0;i<4;i++) s[i] = Ssh[(tyy*4+i)*U_ + u];
        #pragma unroll
        for (int k=0;k<8;k++) {
            const float d = Dsh[(tx + 64*k)*65 + u];
            #pragma unroll
            for (int i=0;i<4;i++) {
                acc[i][k] = fmaf(au, fabsf(s[i] + d), acc[i][k]);
            }
        }
    }
    #pragma unroll
    for (int i=0;i<4;i++) {
        const float sa = saSh[tyy*4+i];
        #pragma unroll
        for (int k=0;k<8;k++) {
            const int m = tx + 64*k;
            if (m < N_)
                sc[(tyy*4+i)*N_ + m] = 0.6f*(sa + daSh[m]) + 0.4f*acc[i][k];
        }
    }
    __syncthreads();

    const int warp = tid >> 5, lane = tid & 31;
    #pragma unroll
    for (int rr = 0; rr < 2; rr++) {
        const int r = warp*2 + rr;
        const int n = nBase + r;
        float mx = -1e30f;
        for (int m = lane; m < N_; m += 32) mx = fmaxf(mx, sc[r*N_+m]);
        #pragma unroll
        for (int o=16;o>0;o>>=1) mx = fmaxf(mx, __shfl_xor_sync(0xffffffffu, mx, o));
        float sum = 0.f;
        for (int m = lane; m < N_; m += 32) {
            const float e = __expf(sc[r*N_+m] - mx);
            sc[r*N_+m] = e;
            sum += e;
        }
        #pragma unroll
        for (int o=16;o>0;o>>=1) sum += __shfl_xor_sync(0xffffffffu, sum, o);
        const float inv = 1.f / sum;
        if (n < N_) {
            __half* dH = g_attn + ((size_t)b*N_ + n)*HM_ + (size_t)h*N_;
            for (int m = lane; m < N_; m += 32)
                dH[m] = __float2half_rn(sc[r*N_+m]*inv);
        }
    }
}

// ---------------------------------------------------------------------------
// Kernel C: msg GEMM on tensor cores (plain fp16, K=128 resident).
// (unchanged from R14)
// ---------------------------------------------------------------------------
#define QRS    272                        // smem row stride (17 x 16B, odd units)
#define QAHI   0
#define QWHI   (128*QRS)                  // 34816
#define QSMEM  (QWHI + 256*QRS)           // 104448
#define QCS    257                        // C staging stride (fp32 words, odd)

__global__ __launch_bounds__(512, 1)
void msg_mma(const float* __restrict__ curr)
{
    extern __shared__ __align__(128) char smq[];
    const uint32_t sbase = smem_u32(smq);
    const int tid  = threadIdx.x;
    const int wid  = tid >> 5;
    const int lane = tid & 31;
    const int r0   = blockIdx.x * 128;

    // ---- W: cp.async coalesced from precomputed WT ----
    #pragma unroll
    for (int i = 0; i < 8; i++) {
        const int g = tid + i*512;              // 0..4095
        const int n = g >> 4;
        const int s = g & 15;
        cp16(sbase + QWHI + n*QRS + s*16, g_WT + n*128 + s*8, true);
    }
    cp_commit();

    // ---- A: curr rows -> fp16 smem ----
    #pragma unroll
    for (int i = 0; i < 4; i++) {
        const int g   = tid + i*512;            // 0..2047
        const int row = g >> 4;
        const int s   = g & 15;
        const float* src = curr + (size_t)(r0 + row)*DC_ + s*8;
        float4 v0 = *(const float4*)(src);
        float4 v1 = *(const float4*)(src + 4);
        union { __half x[8]; uint4 v; } ph;
        ph.x[0] = __float2half_rn(v0.x);
        ph.x[1] = __float2half_rn(v0.y);
        ph.x[2] = __float2half_rn(v0.z);
        ph.x[3] = __float2half_rn(v0.w);
        ph.x[4] = __float2half_rn(v1.x);
        ph.x[5] = __float2half_rn(v1.y);
        ph.x[6] = __float2half_rn(v1.z);
        ph.x[7] = __float2half_rn(v1.w);
        *(uint4*)(smq + QAHI + row*QRS + s*16) = ph.v;
    }
    cp_wait<0>();
    __syncthreads();

    // ---- MMA: 16 warps, warp tile 64(m) x 32(n); 8 k16 steps ----
    const int wm = wid & 1;
    const int wn = wid >> 1;
    const uint32_t aRowOff = (lane & 7) + ((lane >> 3) & 1) * 8;
    const uint32_t aSegOff = (lane >> 4) * 16;
    const uint32_t bRowOff = (lane & 7) + (lane >> 4) * 8;
    const uint32_t bSegOff = ((lane >> 3) & 1) * 16;

    float acc[4][4][4] = {};
    const uint32_t sAh = sbase + QAHI;
    const uint32_t sWh = sbase + QWHI;

    #pragma unroll
    for (int k16 = 0; k16 < 8; k16++) {
        const uint32_t kb = k16*32;
        uint32_t bh[2][4];
        #pragma unroll
        for (int p = 0; p < 2; p++) {
            ldsm_x4(bh[p], sWh + (wn*32 + p*16 + bRowOff)*QRS + kb + bSegOff);
        }
        #pragma unroll
        for (int mt = 0; mt < 4; mt++) {
            uint32_t a[4];
            ldsm_x4(a, sAh + (wm*64 + mt*16 + aRowOff)*QRS + kb + aSegOff);
            #pragma unroll
            for (int nt = 0; nt < 4; nt++) {
                mma16816h(acc[mt][nt], a, &bh[nt >> 1][(nt & 1)*2]);
            }
        }
    }

    // ---- Epilogue: two 64-row passes ----
    float* Cs = (float*)smq;
    const int lr0 = (lane >> 2);
    const int cc0 = wn*32 + (lane & 3)*2;

    #pragma unroll
    for (int pass = 0; pass < 2; pass++) {
        __syncthreads();
        if (wm == pass) {
            #pragma unroll
            for (int mt = 0; mt < 4; mt++) {
                #pragma unroll
                for (int half = 0; half < 2; half++) {
                    const int r = lr0 + mt*16 + half*8;
                    #pragma unroll
                    for (int nt = 0; nt < 4; nt++) {
                        Cs[r*QCS + cc0 + nt*8]     = acc[mt][nt][half*2+0];
                        Cs[r*QCS + cc0 + nt*8 + 1] = acc[mt][nt][half*2+1];
                    }
                }
            }
        }
        __syncthreads();

        #pragma unroll
        for (int i = 0; i < 8; i++) {
            const int g  = tid + i*512;
            const int mq = g & 15;
            const int c  = g >> 4;
            const int rloc = mq*4;
            const int rg = r0 + pass*64 + rloc;
            const int bb  = rg / (T_*N_);
            const int rem = rg - bb*(T_*N_);
            const int t   = rem / N_;
            const int m   = rem - t*N_;
            const int h   = c >> 6;
            const int u   = c & 63;
            union { __half x[4]; uint2 v; } p;
            #pragma unroll
            for (int j = 0; j < 4; j++)
                p.x[j] = __float2half_rn(Cs[(rloc + j)*QCS + c]);
            const size_t off = ((size_t)bb*TU_ + t*U_ + u)*HM_ + (size_t)h*N_ + m;
            *(uint2*)&g_msgT[off] = p.v;
        }
    }
}

// ---------------------------------------------------------------------------
// Kernel D: mix GEMM via mma.sync (single fp16 A and B), 2 CTAs/SM,
// 4-stage cp.async pipeline.  (unchanged from R12)
// ---------------------------------------------------------------------------
#define MIX_KC    32
#define MIX_NCH   63          // ceil(2000/32), zero-filled to 2016
#define MRS       80          // smem row stride bytes (64B data + 16B pad)
#define MTILE     10240       // 128 rows * 80B
#define MSTAGE    (2*MTILE)   // A, B = 20480
#define MNSTG     4
#define MSM_TOTAL (MNSTG*MSTAGE)  // 81920

__device__ __forceinline__ void mix_load_chunk(
    uint32_t sstage, int kc, int tid, int b, int mBase, int nBase)
{
    const __half* Am = g_attn + (size_t)b * N_ * HM_;
    const __half* Bm = g_msgT + (size_t)b * TU_ * HM_;
    #pragma unroll
    for (int i = 0; i < 4; i++) {
        const int g    = tid + i*256;       // 0..1023
        const int tile = g >> 9;            // 0:A 1:B
        const int rem  = g & 511;
        const int row  = rem >> 2;
        const int seg  = rem & 3;
        const int k    = kc + seg*8;
        const uint32_t dst = sstage + tile*MTILE + row*MRS + seg*16;
        if (tile == 0) {
            const int n = mBase + row;
            const bool ok = (n < N_) && (k < HM_);
            cp16(dst, Am + (ok ? ((size_t)n*HM_ + k) : 0), ok);
        } else {
            const bool ok = (k < HM_);
            cp16(dst, Bm + (ok ? ((size_t)(nBase + row)*HM_ + k) : 0), ok);
        }
    }
    cp_commit();
}

__global__ __launch_bounds__(256, 2)
void mix_mma(float* __restrict__ out)
{
    extern __shared__ __align__(128) char smx[];
    const uint32_t sbase = smem_u32(smx);
    const int tid  = threadIdx.x;
    const int wid  = tid >> 5;
    const int lane = tid & 31;
    const int b     = blockIdx.z;
    const int mBase = blockIdx.x * 128;
    const int nBase = blockIdx.y * 128;

    const int wm = wid & 1;
    const int wn = wid >> 1;

    const uint32_t aRowOff = (lane & 7) + ((lane >> 3) & 1) * 8;
    const uint32_t aSegOff = (lane >> 4) * 16;
    const uint32_t bRowOff = (lane & 7) + (lane >> 4) * 8;
    const uint32_t bSegOff = ((lane >> 3) & 1) * 16;

    float acc[4][4][4] = {};

    mix_load_chunk(sbase + 0*MSTAGE, 0*MIX_KC, tid, b, mBase, nBase);
    mix_load_chunk(sbase + 1*MSTAGE, 1*MIX_KC, tid, b, mBase, nBase);
    mix_load_chunk(sbase + 2*MSTAGE, 2*MIX_KC, tid, b, mBase, nBase);

    int sc = 0;
    for (int c = 0; c < MIX_NCH; c++) {
        if (c + 3 < MIX_NCH) {
            const int ns = (sc + 3) & 3;
            mix_load_chunk(sbase + ns*MSTAGE, (c+3)*MIX_KC, tid, b, mBase, nBase);
            cp_wait<3>();
        } else if (c + 2 < MIX_NCH) {
            cp_wait<2>();
        } else if (c + 1 < MIX_NCH) {
            cp_wait<1>();
        } else {
            cp_wait<0>();
        }
        __syncthreads();

        const uint32_t sA = sbase + sc*MSTAGE;
        const uint32_t sB = sA + MTILE;

        #pragma unroll
        for (int k16 = 0; k16 < 2; k16++) {
            const uint32_t kb = k16*32;
            uint32_t bb[2][4];
            #pragma unroll
            for (int p = 0; p < 2; p++) {
                ldsm_x4(bb[p], sB + (wn*32 + p*16 + bRowOff)*MRS + kb + bSegOff);
            }
            #pragma unroll
            for (int mt = 0; mt < 4; mt++) {
                uint32_t a[4];
                ldsm_x4(a, sA + (wm*64 + mt*16 + aRowOff)*MRS + kb + aSegOff);
                #pragma unroll
                for (int nt = 0; nt < 4; nt++) {
                    mma16816h(acc[mt][nt], a, &bb[nt >> 1][(nt & 1)*2]);
                }
            }
        }
        __syncthreads();
        sc = (sc + 1) & 3;
    }

    // Epilogue
    const int r0 = mBase + wm*64 + (lane >> 2);
    const int c0 = nBase + wn*32 + (lane & 3)*2;
    #pragma unroll
    for (int mt = 0; mt < 4; mt++) {
        #pragma unroll
        for (int half = 0; half < 2; half++) {
            const int n = r0 + mt*16 + half*8;
            if (n < N_) {
                #pragma unroll
                for (int nt = 0; nt < 4; nt++) {
                    const int cc = c0 + nt*8;
                    const int t  = cc >> 6;
                    const int u  = cc & 63;
                    float2 v = make_float2(acc[mt][nt][half*2+0]*0.25f,
                                           acc[mt][nt][half*2+1]*0.25f);
                    *(float2*)&out[(((size_t)b*T_ + t)*N_ + n)*U_ + u] = v;
                }
            }
        }
    }
}

// ---------------------------------------------------------------------------
extern "C" void kernel_launch(void* const* d_in, const int* in_sizes, int n_in,
                              void* d_out, int out_size)
{
    const float* prev = (const float*)d_in[0];   // [8,500,200]
    const float* curr = (const float*)d_in[1];   // [8,32,500,128]
    const float* Wsrc = (const float*)d_in[2];   // [4,200,64]
    const float* Wdst = (const float*)d_in[3];   // [4,200,64]
    const float* aV   = (const float*)d_in[4];   // [4,64,1]
    const float* Wmsg = (const float*)d_in[5];   // [4,128,64]
    float* out = (float*)d_out;                  // [8,32,500,64]

    // W: Wmsg transpose (once per launch; stream-ordered before msg_mma)
    wprep<<<16, 256>>>(Wmsg);

    // A: projections  (M=4000, N=512, K=200)
    proj_gemm<<<dim3(32, 4), 256>>>(prev, Wsrc, Wdst);

    // B: scores + softmax -> single fp16 attn (2-op lrelu decomposition)
    const size_t shB = (size_t)(512*65 + 16*64 + 128 + 16*500 + 512 + 16 + 16) * sizeof(float);
    cudaFuncSetAttribute(score_softmax_kernel,
                         cudaFuncAttributeMaxDynamicSharedMemorySize, (int)shB);
    score_softmax_kernel<<<dim3(32, 32), 256, shB>>>(aV);

    // C: msg GEMM on tensor cores (plain fp16) -> transposed msgT
    cudaFuncSetAttribute(msg_mma,
                         cudaFuncAttributeMaxDynamicSharedMemorySize, QSMEM);
    msg_mma<<<1000, 512, QSMEM>>>(curr);

    // D: mix GEMM on tensor cores (per batch: M=500, N=2048, K=2000), 2 CTAs/SM
    cudaFuncSetAttribute(mix_mma,
                         cudaFuncAttributeMaxDynamicSharedMemorySize, MSM_TOTAL);
    mix_mma<<<dim3(4, 16, 8), 256, MSM_TOTAL>>>(out);
}

// round 16
// speedup vs baseline: 3.0946x; 1.0089x over previous
#include <cuda_runtime.h>
#include <cuda_bf16.h>
#include <cuda_fp16.h>
#include <cstdint>
#include <cstddef>

// Problem constants
#define B_   8
#define T_   32
#define N_   500
#define DP_  200
#define DC_  128
#define H_   4
#define U_   64
#define HM_  2000   // H_*N_  (K dim of mix GEMM)
#define TU_  2048   // T_*U_  (N dim of mix GEMM)

// Scratch (device globals: allocation-free rule)
__device__ float g_S[B_*H_*N_*U_];                    // [b][h][n][u]
__device__ float g_D[B_*H_*N_*U_];                    // [b][h][m][u]
__device__ __half g_attn[(size_t)B_*N_*HM_];          // [b][n][hm] single fp16
__device__ __half g_msgT[(size_t)B_*TU_*HM_];         // [b][tu][hm] single fp16
__device__ __half g_WT[256*128];                      // [(h,u)][d] Wmsg^T fp16

// ---------------------------------------------------------------------------
// Helpers (compute_103-safe: cp.async / ldmatrix / mma.sync)
// ---------------------------------------------------------------------------
__device__ __forceinline__ uint32_t smem_u32(const void* p) {
    uint32_t a;
    asm("{ .reg .u64 t; cvta.to.shared.u64 t, %1; cvt.u32.u64 %0, t; }" : "=r"(a) : "l"(p));
    return a;
}
__device__ __forceinline__ void cp16(uint32_t dst, const void* src, bool ok) {
    int sz = ok ? 16 : 0;   // src-size 0 => zero-fill 16B
    asm volatile("cp.async.cg.shared.global [%0], [%1], 16, %2;" :: "r"(dst), "l"(src), "r"(sz) : "memory");
}
__device__ __forceinline__ void cp_commit() {
    asm volatile("cp.async.commit_group;" ::: "memory");
}
template <int NW>
__device__ __forceinline__ void cp_wait() {
    asm volatile("cp.async.wait_group %0;" :: "n"(NW) : "memory");
}
__device__ __forceinline__ void ldsm_x4(uint32_t* r, uint32_t addr) {
    asm volatile("ldmatrix.sync.aligned.m8n8.x4.shared.b16 {%0,%1,%2,%3}, [%4];"
                 : "=r"(r[0]), "=r"(r[1]), "=r"(r[2]), "=r"(r[3]) : "r"(addr));
}
// fp16 MMA, fp32 accumulate
__device__ __forceinline__ void mma16816h(float* c, const uint32_t* a, const uint32_t* b) {
    asm volatile(
        "mma.sync.aligned.m16n8k16.row.col.f32.f16.f16.f32 "
        "{%0,%1,%2,%3}, {%4,%5,%6,%7}, {%8,%9}, {%0,%1,%2,%3};"
        : "+f"(c[0]), "+f"(c[1]), "+f"(c[2]), "+f"(c[3])
        : "r"(a[0]), "r"(a[1]), "r"(a[2]), "r"(a[3]), "r"(b[0]), "r"(b[1]));
}

// ---------------------------------------------------------------------------
// Kernel W: one-shot Wmsg transpose -> g_WT [(h,u)][d] fp16
// ---------------------------------------------------------------------------
__global__ __launch_bounds__(256)
void wprep(const float* __restrict__ Wmsg)
{
    const int g = blockIdx.x * 256 + threadIdx.x;   // 0..4095
    const int n = g >> 4;          // (h,u) row
    const int s = g & 15;          // 8-d segment
    const int h = n >> 6;
    const int u = n & 63;
    const int d0 = s * 8;
    union { __half x[8]; uint4 v; } ph;
    #pragma unroll
    for (int j = 0; j < 8; j++) {
        const float w = __ldg(Wmsg + h*(DC_*U_) + (d0 + j)*U_ + u);
        ph.x[j] = __float2half_rn(w);
    }
    *(uint4*)&g_WT[n*128 + d0] = ph.v;
}

// ---------------------------------------------------------------------------
// Kernel A: projections.  GEMM M=4000 (b*500+n), K=200, Ncols=512
// ---------------------------------------------------------------------------
__global__ __launch_bounds__(256, 2)
void proj_gemm(const float* __restrict__ prev,
               const float* __restrict__ Wsrc,
               const float* __restrict__ Wdst)
{
    const int rowBase = blockIdx.x * 128;
    const int colBase = blockIdx.y * 128;

    __shared__ float As[2][8][132];
    __shared__ float Bs[2][8][128];

    const int tid  = threadIdx.x;
    const int aRow = tid >> 1;
    const int aK   = (tid & 1) * 4;
    const int bK   = tid >> 5;
    const int bCol = (tid & 31) * 4;
    const int tx   = tid & 15;
    const int ty   = tid >> 4;

    const int gRow  = rowBase + aRow;
    const bool rowOk = gRow < 4000;
    const float* aPtr = prev + (size_t)gRow * DP_ + aK;

    const int cB   = colBase + bCol;
    const int matB = cB >> 8;
    const int hB   = (cB >> 6) & 3;
    const int uB   = cB & 63;
    const float* bPtr = (matB ? Wdst : Wsrc) + hB * (DP_*U_) + bK * U_ + uB;

    const int KSTEPS = DP_ / 8;  // 25

    float4 aReg = rowOk ? *(const float4*)aPtr : make_float4(0,0,0,0);
    float4 bReg = *(const float4*)bPtr;

    As[0][aK+0][aRow] = aReg.x; As[0][aK+1][aRow] = aReg.y;
    As[0][aK+2][aRow] = aReg.z; As[0][aK+3][aRow] = aReg.w;
    *(float4*)&Bs[0][bK][bCol] = bReg;
    __syncthreads();

    float acc[2][2][4][4] = {};

    for (int ks = 0; ks < KSTEPS; ks++) {
        const int cur = ks & 1;
        if (ks + 1 < KSTEPS) {
            aReg = rowOk ? *(const float4*)(aPtr + (ks+1)*8) : make_float4(0,0,0,0);
            bReg = *(const float4*)(bPtr + (ks+1)*8*U_);
        }
        #pragma unroll
        for (int kk = 0; kk < 8; kk++) {
            float ar[2][4], br[2][4];
            *(float4*)ar[0] = *(const float4*)&As[cur][kk][ty*4];
            *(float4*)ar[1] = *(const float4*)&As[cur][kk][ty*4 + 64];
            *(float4*)br[0] = *(const float4*)&Bs[cur][kk][tx*4];
            *(float4*)br[1] = *(const float4*)&Bs[cur][kk][tx*4 + 64];
            #pragma unroll
            for (int rg=0; rg<2; rg++)
              #pragma unroll
              for (int cg=0; cg<2; cg++)
                #pragma unroll
                for (int i=0;i<4;i++)
                  #pragma unroll
                  for (int j=0;j<4;j++)
                    acc[rg][cg][i][j] = fmaf(ar[rg][i], br[cg][j], acc[rg][cg][i][j]);
        }
        if (ks + 1 < KSTEPS) {
            const int nxt = cur ^ 1;
            As[nxt][aK+0][aRow] = aReg.x; As[nxt][aK+1][aRow] = aReg.y;
            As[nxt][aK+2][aRow] = aReg.z; As[nxt][aK+3][aRow] = aReg.w;
            *(float4*)&Bs[nxt][bK][bCol] = bReg;
            __syncthreads();
        }
    }

    #pragma unroll
    for (int rg=0; rg<2; rg++) {
        #pragma unroll
        for (int i=0;i<4;i++) {
            const int r = rowBase + ty*4 + rg*64 + i;
            if (r < 4000) {
                const int b = r / N_;
                const int n = r - b * N_;
                #pragma unroll
                for (int cg=0; cg<2; cg++) {
                    const int c = colBase + tx*4 + cg*64;
                    const int mat = c >> 8;
                    const int h   = (c >> 6) & 3;
                    const int u   = c & 63;
                    float* dst = (mat ? g_D : g_S) + ((size_t)(b*H_ + h)*N_ + n)*U_ + u;
                    float4 v = make_float4(acc[rg][cg][i][0], acc[rg][cg][i][1],
                                           acc[rg][cg][i][2], acc[rg][cg][i][3]);
                    *(float4*)dst = v;
                }
            }
        }
    }
}

// ---------------------------------------------------------------------------
// Kernel B: GATv2 scores + softmax -> single fp16 attn [b][n][hm].
// lrelu(x) = 0.6x + 0.4|x| decomposition (2-op inner loop).
// ---------------------------------------------------------------------------
__global__ __launch_bounds__(256)
void score_softmax_kernel(const float* __restrict__ aVec)
{
    extern __shared__ float sh[];
    float* Dsh = sh;                     // 512*65
    float* Ssh = Dsh + 512*65;           // 16*64
    float* aSh = Ssh + 16*64;            // 64 (+64 pad)
    float* sc  = aSh + 128;              // 16*500
    float* daSh = sc + 16*500;           // 512
    float* saSh = daSh + 512;            // 16

    const int bh = blockIdx.y;           // b*4 + h
    const int b  = bh >> 2;
    const int h  = bh & 3;
    const int nBase = blockIdx.x * 16;
    const int tid = threadIdx.x;

    const float* Dg = g_D + (size_t)bh * N_ * U_;
    const float* Sg = g_S + (size_t)bh * N_ * U_;

    for (int idx = tid; idx < 512*16; idx += 256) {
        const int m = idx >> 4;
        const int u = (idx & 15) * 4;
        float4 v = (m < N_) ? *(const float4*)(Dg + m*U_ + u) : make_float4(0,0,0,0);
        float* dst = &Dsh[m*65 + u];
        dst[0]=v.x; dst[1]=v.y; dst[2]=v.z; dst[3]=v.w;
    }
    for (int idx = tid; idx < 16*16; idx += 256) {
        const int r = idx >> 4;
        const int u = (idx & 15) * 4;
        const int n = nBase + r;
        float4 v = (n < N_) ? *(const float4*)(Sg + n*U_ + u) : make_float4(0,0,0,0);
        float* dst = &Ssh[r*U_ + u];
        dst[0]=v.x; dst[1]=v.y; dst[2]=v.z; dst[3]=v.w;
    }
    if (tid < 64) aSh[tid] = aVec[h*U_ + tid];
    __syncthreads();

    // Rank-1 precomputes
    for (int m = tid; m < 512; m += 256) {
        float s = 0.f;
        #pragma unroll 16
        for (int u = 0; u < U_; u++) s = fmaf(aSh[u], Dsh[m*65 + u], s);
        daSh[m] = s;
    }
    if (tid < 16) {
        float s = 0.f;
        #pragma unroll 16
        for (int u = 0; u < U_; u++) s = fmaf(aSh[u], Ssh[tid*U_ + u], s);
        saSh[tid] = s;
    }
    __syncthreads();

    const int tx  = tid & 63;
    const int tyy = tid >> 6;

    float acc[4][8];
    #pragma unroll
    for (int i=0;i<4;i++)
        #pragma unroll
        for (int k=0;k<8;k++) acc[i][k]=0.f;

    for (int u = 0; u < U_; u++) {
        const float au = aSh[u];
        float s[4];
        #pragma unroll
        for (int i=0;i<4;i++) s[i] = Ssh[(tyy*4+i)*U_ + u];
        #pragma unroll
        for (int k=0;k<8;k++) {
            const float d = Dsh[(tx + 64*k)*65 + u];
            #pragma unroll
            for (int i=0;i<4;i++) {
                acc[i][k] = fmaf(au, fabsf(s[i] + d), acc[i][k]);
            }
        }
    }
    #pragma unroll
    for (int i=0;i<4;i++) {
        const float sa = saSh[tyy*4+i];
        #pragma unroll
        for (int k=0;k<8;k++) {
            const int m = tx + 64*k;
            if (m < N_)
                sc[(tyy*4+i)*N_ + m] = 0.6f*(sa + daSh[m]) + 0.4f*acc[i][k];
        }
    }
    __syncthreads();

    const int warp = tid >> 5, lane = tid & 31;
    #pragma unroll
    for (int rr = 0; rr < 2; rr++) {
        const int r = warp*2 + rr;
        const int n = nBase + r;
        float mx = -1e30f;
        for (int m = lane; m < N_; m += 32) mx = fmaxf(mx, sc[r*N_+m]);
        #pragma unroll
        for (int o=16;o>0;o>>=1) mx = fmaxf(mx, __shfl_xor_sync(0xffffffffu, mx, o));
        float sum = 0.f;
        for (int m = lane; m < N_; m += 32) {
            const float e = __expf(sc[r*N_+m] - mx);
            sc[r*N_+m] = e;
            sum += e;
        }
        #pragma unroll
        for (int o=16;o>0;o>>=1) sum += __shfl_xor_sync(0xffffffffu, sum, o);
        const float inv = 1.f / sum;
        if (n < N_) {
            __half* dH = g_attn + ((size_t)b*N_ + n)*HM_ + (size_t)h*N_;
            for (int m = lane; m < N_; m += 32)
                dH[m] = __float2half_rn(sc[r*N_+m]*inv);
        }
    }
}

// ---------------------------------------------------------------------------
// Kernel C: msg GEMM on tensor cores (plain fp16, K=128 resident).
// (unchanged from R14)
// ---------------------------------------------------------------------------
#define QRS    272                        // smem row stride (17 x 16B, odd units)
#define QAHI   0
#define QWHI   (128*QRS)                  // 34816
#define QSMEM  (QWHI + 256*QRS)           // 104448
#define QCS    257                        // C staging stride (fp32 words, odd)

__global__ __launch_bounds__(512, 1)
void msg_mma(const float* __restrict__ curr)
{
    extern __shared__ __align__(128) char smq[];
    const uint32_t sbase = smem_u32(smq);
    const int tid  = threadIdx.x;
    const int wid  = tid >> 5;
    const int lane = tid & 31;
    const int r0   = blockIdx.x * 128;

    // ---- W: cp.async coalesced from precomputed WT ----
    #pragma unroll
    for (int i = 0; i < 8; i++) {
        const int g = tid + i*512;              // 0..4095
        const int n = g >> 4;
        const int s = g & 15;
        cp16(sbase + QWHI + n*QRS + s*16, g_WT + n*128 + s*8, true);
    }
    cp_commit();

    // ---- A: curr rows -> fp16 smem ----
    #pragma unroll
    for (int i = 0; i < 4; i++) {
        const int g   = tid + i*512;            // 0..2047
        const int row = g >> 4;
        const int s   = g & 15;
        const float* src = curr + (size_t)(r0 + row)*DC_ + s*8;
        float4 v0 = *(const float4*)(src);
        float4 v1 = *(const float4*)(src + 4);
        union { __half x[8]; uint4 v; } ph;
        ph.x[0] = __float2half_rn(v0.x);
        ph.x[1] = __float2half_rn(v0.y);
        ph.x[2] = __float2half_rn(v0.z);
        ph.x[3] = __float2half_rn(v0.w);
        ph.x[4] = __float2half_rn(v1.x);
        ph.x[5] = __float2half_rn(v1.y);
        ph.x[6] = __float2half_rn(v1.z);
        ph.x[7] = __float2half_rn(v1.w);
        *(uint4*)(smq + QAHI + row*QRS + s*16) = ph.v;
    }
    cp_wait<0>();
    __syncthreads();

    // ---- MMA: 16 warps, warp tile 64(m) x 32(n); 8 k16 steps ----
    const int wm = wid & 1;
    const int wn = wid >> 1;
    const uint32_t aRowOff = (lane & 7) + ((lane >> 3) & 1) * 8;
    const uint32_t aSegOff = (lane >> 4) * 16;
    const uint32_t bRowOff = (lane & 7) + (lane >> 4) * 8;
    const uint32_t bSegOff = ((lane >> 3) & 1) * 16;

    float acc[4][4][4] = {};
    const uint32_t sAh = sbase + QAHI;
    const uint32_t sWh = sbase + QWHI;

    #pragma unroll
    for (int k16 = 0; k16 < 8; k16++) {
        const uint32_t kb = k16*32;
        uint32_t bh[2][4];
        #pragma unroll
        for (int p = 0; p < 2; p++) {
            ldsm_x4(bh[p], sWh + (wn*32 + p*16 + bRowOff)*QRS + kb + bSegOff);
        }
        #pragma unroll
        for (int mt = 0; mt < 4; mt++) {
            uint32_t a[4];
            ldsm_x4(a, sAh + (wm*64 + mt*16 + aRowOff)*QRS + kb + aSegOff);
            #pragma unroll
            for (int nt = 0; nt < 4; nt++) {
                mma16816h(acc[mt][nt], a, &bh[nt >> 1][(nt & 1)*2]);
            }
        }
    }

    // ---- Epilogue: two 64-row passes ----
    float* Cs = (float*)smq;
    const int lr0 = (lane >> 2);
    const int cc0 = wn*32 + (lane & 3)*2;

    #pragma unroll
    for (int pass = 0; pass < 2; pass++) {
        __syncthreads();
        if (wm == pass) {
            #pragma unroll
            for (int mt = 0; mt < 4; mt++) {
                #pragma unroll
                for (int half = 0; half < 2; half++) {
                    const int r = lr0 + mt*16 + half*8;
                    #pragma unroll
                    for (int nt = 0; nt < 4; nt++) {
                        Cs[r*QCS + cc0 + nt*8]     = acc[mt][nt][half*2+0];
                        Cs[r*QCS + cc0 + nt*8 + 1] = acc[mt][nt][half*2+1];
                    }
                }
            }
        }
        __syncthreads();

        #pragma unroll
        for (int i = 0; i < 8; i++) {
            const int g  = tid + i*512;
            const int mq = g & 15;
            const int c  = g >> 4;
            const int rloc = mq*4;
            const int rg = r0 + pass*64 + rloc;
            const int bb  = rg / (T_*N_);
            const int rem = rg - bb*(T_*N_);
            const int t   = rem / N_;
            const int m   = rem - t*N_;
            const int h   = c >> 6;
            const int u   = c & 63;
            union { __half x[4]; uint2 v; } p;
            #pragma unroll
            for (int j = 0; j < 4; j++)
                p.x[j] = __float2half_rn(Cs[(rloc + j)*QCS + c]);
            const size_t off = ((size_t)bb*TU_ + t*U_ + u)*HM_ + (size_t)h*N_ + m;
            *(uint2*)&g_msgT[off] = p.v;
        }
    }
}

// ---------------------------------------------------------------------------
// Kernel D: mix GEMM via mma.sync (single fp16 A and B), 2 CTAs/SM.
// KC=64 chunks (4 k16 each) -> half the barriers; 3-stage cp.async pipeline.
// Row stride 144B (9x16B, odd -> conflict-free ldsm).
// ---------------------------------------------------------------------------
#define MIX_KC    64
#define MIX_NCH   32          // ceil(2000/64) -> covers k<2048, zero-filled
#define MRS       144         // smem row stride bytes (128B data + 16B pad)
#define MTILE     18432       // 128 rows * 144B
#define MSTAGE    (2*MTILE)   // A, B = 36864
#define MNSTG     3
#define MSM_TOTAL (MNSTG*MSTAGE)  // 110592

__device__ __forceinline__ void mix_load_chunk(
    uint32_t sstage, int kc, int tid, int b, int mBase, int nBase)
{
    const __half* Am = g_attn + (size_t)b * N_ * HM_;
    const __half* Bm = g_msgT + (size_t)b * TU_ * HM_;
    #pragma unroll
    for (int i = 0; i < 8; i++) {
        const int g    = tid + i*256;       // 0..2047
        const int tile = g >> 10;           // 0:A 1:B
        const int rem  = g & 1023;
        const int row  = rem >> 3;
        const int seg  = rem & 7;
        const int k    = kc + seg*8;
        const uint32_t dst = sstage + tile*MTILE + row*MRS + seg*16;
        if (tile == 0) {
            const int n = mBase + row;
            const bool ok = (n < N_) && (k < HM_);
            cp16(dst, Am + (ok ? ((size_t)n*HM_ + k) : 0), ok);
        } else {
            const bool ok = (k < HM_);
            cp16(dst, Bm + (ok ? ((size_t)(nBase + row)*HM_ + k) : 0), ok);
        }
    }
    cp_commit();
}

__global__ __launch_bounds__(256, 2)
void mix_mma(float* __restrict__ out)
{
    extern __shared__ __align__(128) char smx[];
    const uint32_t sbase = smem_u32(smx);
    const int tid  = threadIdx.x;
    const int wid  = tid >> 5;
    const int lane = tid & 31;
    const int b     = blockIdx.z;
    const int mBase = blockIdx.x * 128;
    const int nBase = blockIdx.y * 128;

    const int wm = wid & 1;
    const int wn = wid >> 1;

    const uint32_t aRowOff = (lane & 7) + ((lane >> 3) & 1) * 8;
    const uint32_t aSegOff = (lane >> 4) * 16;
    const uint32_t bRowOff = (lane & 7) + (lane >> 4) * 8;
    const uint32_t bSegOff = ((lane >> 3) & 1) * 16;

    float acc[4][4][4] = {};

    mix_load_chunk(sbase + 0*MSTAGE, 0*MIX_KC, tid, b, mBase, nBase);
    mix_load_chunk(sbase + 1*MSTAGE, 1*MIX_KC, tid, b, mBase, nBase);

    int sc = 0;
    for (int c = 0; c < MIX_NCH; c++) {
        if (c + 2 < MIX_NCH) {
            const int ns = (sc + 2 >= MNSTG) ? sc + 2 - MNSTG : sc + 2;
            mix_load_chunk(sbase + ns*MSTAGE, (c+2)*MIX_KC, tid, b, mBase, nBase);
            cp_wait<2>();
        } else if (c + 1 < MIX_NCH) {
            cp_wait<1>();
        } else {
            cp_wait<0>();
        }
        __syncthreads();

        const uint32_t sA = sbase + sc*MSTAGE;
        const uint32_t sB = sA + MTILE;

        #pragma unroll
        for (int k16 = 0; k16 < 4; k16++) {
            const uint32_t kb = k16*32;
            uint32_t bb[2][4];
            #pragma unroll
            for (int p = 0; p < 2; p++) {
                ldsm_x4(bb[p], sB + (wn*32 + p*16 + bRowOff)*MRS + kb + bSegOff);
            }
            #pragma unroll
            for (int mt = 0; mt < 4; mt++) {
                uint32_t a[4];
                ldsm_x4(a, sA + (wm*64 + mt*16 + aRowOff)*MRS + kb + aSegOff);
                #pragma unroll
                for (int nt = 0; nt < 4; nt++) {
                    mma16816h(acc[mt][nt], a, &bb[nt >> 1][(nt & 1)*2]);
                }
            }
        }
        __syncthreads();
        sc = (sc + 1 >= MNSTG) ? 0 : sc + 1;
    }

    // Epilogue
    const int r0 = mBase + wm*64 + (lane >> 2);
    const int c0 = nBase + wn*32 + (lane & 3)*2;
    #pragma unroll
    for (int mt = 0; mt < 4; mt++) {
        #pragma unroll
        for (int half = 0; half < 2; half++) {
            const int n = r0 + mt*16 + half*8;
            if (n < N_) {
                #pragma unroll
                for (int nt = 0; nt < 4; nt++) {
                    const int cc = c0 + nt*8;
                    const int t  = cc >> 6;
                    const int u  = cc & 63;
                    float2 v = make_float2(acc[mt][nt][half*2+0]*0.25f,
                                           acc[mt][nt][half*2+1]*0.25f);
                    *(float2*)&out[(((size_t)b*T_ + t)*N_ + n)*U_ + u] = v;
                }
            }
        }
    }
}

// ---------------------------------------------------------------------------
extern "C" void kernel_launch(void* const* d_in, const int* in_sizes, int n_in,
                              void* d_out, int out_size)
{
    const float* prev = (const float*)d_in[0];   // [8,500,200]
    const float* curr = (const float*)d_in[1];   // [8,32,500,128]
    const float* Wsrc = (const float*)d_in[2];   // [4,200,64]
    const float* Wdst = (const float*)d_in[3];   // [4,200,64]
    const float* aV   = (const float*)d_in[4];   // [4,64,1]
    const float* Wmsg = (const float*)d_in[5];   // [4,128,64]
    float* out = (float*)d_out;                  // [8,32,500,64]

    // W: Wmsg transpose (once per launch; stream-ordered before msg_mma)
    wprep<<<16, 256>>>(Wmsg);

    // A: projections  (M=4000, N=512, K=200)
    proj_gemm<<<dim3(32, 4), 256>>>(prev, Wsrc, Wdst);

    // B: scores + softmax -> single fp16 attn (2-op lrelu decomposition)
    const size_t shB = (size_t)(512*65 + 16*64 + 128 + 16*500 + 512 + 16 + 16) * sizeof(float);
    cudaFuncSetAttribute(score_softmax_kernel,
                         cudaFuncAttributeMaxDynamicSharedMemorySize, (int)shB);
    score_softmax_kernel<<<dim3(32, 32), 256, shB>>>(aV);

    // C: msg GEMM on tensor cores (plain fp16) -> transposed msgT
    cudaFuncSetAttribute(msg_mma,
                         cudaFuncAttributeMaxDynamicSharedMemorySize, QSMEM);
    msg_mma<<<1000, 512, QSMEM>>>(curr);

    // D: mix GEMM on tensor cores (per batch: M=500, N=2048, K=2000), 2 CTAs/SM
    cudaFuncSetAttribute(mix_mma,
                         cudaFuncAttributeMaxDynamicSharedMemorySize, MSM_TOTAL);
    mix_mma<<<dim3(4, 16, 8), 256, MSM_TOTAL>>>(out);
}

// round 17
// speedup vs baseline: 3.5766x; 1.1558x over previous
#include <cuda_runtime.h>
#include <cuda_bf16.h>
#include <cuda_fp16.h>
#include <cstdint>
#include <cstddef>

// Problem constants
#define B_   8
#define T_   32
#define N_   500
#define DP_  200
#define DC_  128
#define H_   4
#define U_   64
#define HM_  2000   // H_*N_  (K dim of mix GEMM)
#define TU_  2048   // T_*U_  (N dim of mix GEMM)

// Scratch (device globals: allocation-free rule)
__device__ float g_S[B_*H_*N_*U_];                    // [b][h][n][u]
__device__ float g_D[B_*H_*N_*U_];                    // [b][h][m][u]
__device__ __half g_attn[(size_t)B_*N_*HM_];          // [b][n][hm] single fp16
__device__ __half g_msgT[(size_t)B_*TU_*HM_];         // [b][tu][hm] single fp16
__device__ __half g_WT[256*128];                      // [(h,u)][d] Wmsg^T fp16

// ---------------------------------------------------------------------------
// Helpers (compute_103-safe: cp.async / ldmatrix / mma.sync)
// ---------------------------------------------------------------------------
__device__ __forceinline__ uint32_t smem_u32(const void* p) {
    uint32_t a;
    asm("{ .reg .u64 t; cvta.to.shared.u64 t, %1; cvt.u32.u64 %0, t; }" : "=r"(a) : "l"(p));
    return a;
}
__device__ __forceinline__ void cp16(uint32_t dst, const void* src, bool ok) {
    int sz = ok ? 16 : 0;   // src-size 0 => zero-fill 16B
    asm volatile("cp.async.cg.shared.global [%0], [%1], 16, %2;" :: "r"(dst), "l"(src), "r"(sz) : "memory");
}
__device__ __forceinline__ void cp_commit() {
    asm volatile("cp.async.commit_group;" ::: "memory");
}
template <int NW>
__device__ __forceinline__ void cp_wait() {
    asm volatile("cp.async.wait_group %0;" :: "n"(NW) : "memory");
}
__device__ __forceinline__ void ldsm_x4(uint32_t* r, uint32_t addr) {
    asm volatile("ldmatrix.sync.aligned.m8n8.x4.shared.b16 {%0,%1,%2,%3}, [%4];"
                 : "=r"(r[0]), "=r"(r[1]), "=r"(r[2]), "=r"(r[3]) : "r"(addr));
}
// fp16 MMA, fp32 accumulate
__device__ __forceinline__ void mma16816h(float* c, const uint32_t* a, const uint32_t* b) {
    asm volatile(
        "mma.sync.aligned.m16n8k16.row.col.f32.f16.f16.f32 "
        "{%0,%1,%2,%3}, {%4,%5,%6,%7}, {%8,%9}, {%0,%1,%2,%3};"
        : "+f"(c[0]), "+f"(c[1]), "+f"(c[2]), "+f"(c[3])
        : "r"(a[0]), "r"(a[1]), "r"(a[2]), "r"(a[3]), "r"(b[0]), "r"(b[1]));
}

// ---------------------------------------------------------------------------
// Kernel W: one-shot Wmsg transpose -> g_WT [(h,u)][d] fp16
// ---------------------------------------------------------------------------
__global__ __launch_bounds__(256)
void wprep(const float* __restrict__ Wmsg)
{
    const int g = blockIdx.x * 256 + threadIdx.x;   // 0..4095
    const int n = g >> 4;          // (h,u) row
    const int s = g & 15;          // 8-d segment
    const int h = n >> 6;
    const int u = n & 63;
    const int d0 = s * 8;
    union { __half x[8]; uint4 v; } ph;
    #pragma unroll
    for (int j = 0; j < 8; j++) {
        const float w = __ldg(Wmsg + h*(DC_*U_) + (d0 + j)*U_ + u);
        ph.x[j] = __float2half_rn(w);
    }
    *(uint4*)&g_WT[n*128 + d0] = ph.v;
}

// ---------------------------------------------------------------------------
// Kernel A: projections.  GEMM M=4000 (b*500+n), K=200, Ncols=512
// ---------------------------------------------------------------------------
__global__ __launch_bounds__(256, 2)
void proj_gemm(const float* __restrict__ prev,
               const float* __restrict__ Wsrc,
               const float* __restrict__ Wdst)
{
    const int rowBase = blockIdx.x * 128;
    const int colBase = blockIdx.y * 128;

    __shared__ float As[2][8][132];
    __shared__ float Bs[2][8][128];

    const int tid  = threadIdx.x;
    const int aRow = tid >> 1;
    const int aK   = (tid & 1) * 4;
    const int bK   = tid >> 5;
    const int bCol = (tid & 31) * 4;
    const int tx   = tid & 15;
    const int ty   = tid >> 4;

    const int gRow  = rowBase + aRow;
    const bool rowOk = gRow < 4000;
    const float* aPtr = prev + (size_t)gRow * DP_ + aK;

    const int cB   = colBase + bCol;
    const int matB = cB >> 8;
    const int hB   = (cB >> 6) & 3;
    const int uB   = cB & 63;
    const float* bPtr = (matB ? Wdst : Wsrc) + hB * (DP_*U_) + bK * U_ + uB;

    const int KSTEPS = DP_ / 8;  // 25

    float4 aReg = rowOk ? *(const float4*)aPtr : make_float4(0,0,0,0);
    float4 bReg = *(const float4*)bPtr;

    As[0][aK+0][aRow] = aReg.x; As[0][aK+1][aRow] = aReg.y;
    As[0][aK+2][aRow] = aReg.z; As[0][aK+3][aRow] = aReg.w;
    *(float4*)&Bs[0][bK][bCol] = bReg;
    __syncthreads();

    float acc[2][2][4][4] = {};

    for (int ks = 0; ks < KSTEPS; ks++) {
        const int cur = ks & 1;
        if (ks + 1 < KSTEPS) {
            aReg = rowOk ? *(const float4*)(aPtr + (ks+1)*8) : make_float4(0,0,0,0);
            bReg = *(const float4*)(bPtr + (ks+1)*8*U_);
        }
        #pragma unroll
        for (int kk = 0; kk < 8; kk++) {
            float ar[2][4], br[2][4];
            *(float4*)ar[0] = *(const float4*)&As[cur][kk][ty*4];
            *(float4*)ar[1] = *(const float4*)&As[cur][kk][ty*4 + 64];
            *(float4*)br[0] = *(const float4*)&Bs[cur][kk][tx*4];
            *(float4*)br[1] = *(const float4*)&Bs[cur][kk][tx*4 + 64];
            #pragma unroll
            for (int rg=0; rg<2; rg++)
              #pragma unroll
              for (int cg=0; cg<2; cg++)
                #pragma unroll
                for (int i=0;i<4;i++)
                  #pragma unroll
                  for (int j=0;j<4;j++)
                    acc[rg][cg][i][j] = fmaf(ar[rg][i], br[cg][j], acc[rg][cg][i][j]);
        }
        if (ks + 1 < KSTEPS) {
            const int nxt = cur ^ 1;
            As[nxt][aK+0][aRow] = aReg.x; As[nxt][aK+1][aRow] = aReg.y;
            As[nxt][aK+2][aRow] = aReg.z; As[nxt][aK+3][aRow] = aReg.w;
            *(float4*)&Bs[nxt][bK][bCol] = bReg;
            __syncthreads();
        }
    }

    #pragma unroll
    for (int rg=0; rg<2; rg++) {
        #pragma unroll
        for (int i=0;i<4;i++) {
            const int r = rowBase + ty*4 + rg*64 + i;
            if (r < 4000) {
                const int b = r / N_;
                const int n = r - b * N_;
                #pragma unroll
                for (int cg=0; cg<2; cg++) {
                    const int c = colBase + tx*4 + cg*64;
                    const int mat = c >> 8;
                    const int h   = (c >> 6) & 3;
                    const int u   = c & 63;
                    float* dst = (mat ? g_D : g_S) + ((size_t)(b*H_ + h)*N_ + n)*U_ + u;
                    float4 v = make_float4(acc[rg][cg][i][0], acc[rg][cg][i][1],
                                           acc[rg][cg][i][2], acc[rg][cg][i][3]);
                    *(float4*)dst = v;
                }
            }
        }
    }
}

// ---------------------------------------------------------------------------
// Kernel B: GATv2 scores + softmax -> single fp16 attn [b][n][hm].
// lrelu(x)=0.6x+0.4|x| (2-op inner loop).  D processed in two 256-m passes
// so smem fits 2 CTAs/SM (occupancy doubling on the issue-bound loop).
// ---------------------------------------------------------------------------
#define SMH  256    // m-half tile

__global__ __launch_bounds__(256, 2)
void score_softmax_kernel(const float* __restrict__ aVec)
{
    extern __shared__ float sh[];
    float* Dsh = sh;                     // 256*65      (66.6KB)
    float* Ssh = Dsh + SMH*65;           // 16*64
    float* aSh = Ssh + 16*64;            // 64 (+64 pad)
    float* sc  = aSh + 128;              // 16*500
    float* daSh = sc + 16*500;           // 256
    float* saSh = daSh + SMH;            // 16

    const int bh = blockIdx.y;           // b*4 + h
    const int b  = bh >> 2;
    const int h  = bh & 3;
    const int nBase = blockIdx.x * 16;
    const int tid = threadIdx.x;

    const float* Dg = g_D + (size_t)bh * N_ * U_;
    const float* Sg = g_S + (size_t)bh * N_ * U_;

    // S tile + a (loaded once)
    for (int idx = tid; idx < 16*16; idx += 256) {
        const int r = idx >> 4;
        const int u = (idx & 15) * 4;
        const int n = nBase + r;
        float4 v = (n < N_) ? *(const float4*)(Sg + n*U_ + u) : make_float4(0,0,0,0);
        float* dst = &Ssh[r*U_ + u];
        dst[0]=v.x; dst[1]=v.y; dst[2]=v.z; dst[3]=v.w;
    }
    if (tid < 64) aSh[tid] = aVec[h*U_ + tid];
    __syncthreads();

    // sa precompute (once)
    if (tid < 16) {
        float s = 0.f;
        #pragma unroll 16
        for (int u = 0; u < U_; u++) s = fmaf(aSh[u], Ssh[tid*U_ + u], s);
        saSh[tid] = s;
    }

    const int tx  = tid & 63;
    const int tyy = tid >> 6;

    for (int mh = 0; mh < 2; mh++) {
        const int mOff = mh * SMH;
        __syncthreads();                 // previous Dsh/daSh use complete

        // D half-tile
        for (int idx = tid; idx < SMH*16; idx += 256) {
            const int ml = idx >> 4;
            const int u  = (idx & 15) * 4;
            const int m  = mOff + ml;
            float4 v = (m < N_) ? *(const float4*)(Dg + m*U_ + u) : make_float4(0,0,0,0);
            float* dst = &Dsh[ml*65 + u];
            dst[0]=v.x; dst[1]=v.y; dst[2]=v.z; dst[3]=v.w;
        }
        __syncthreads();

        // da for this half
        for (int ml = tid; ml < SMH; ml += 256) {
            float s = 0.f;
            #pragma unroll 16
            for (int u = 0; u < U_; u++) s = fmaf(aSh[u], Dsh[ml*65 + u], s);
            daSh[ml] = s;
        }
        __syncthreads();

        // scoring for this half: 4 k-cols of 64
        float acc[4][4];
        #pragma unroll
        for (int i=0;i<4;i++)
            #pragma unroll
            for (int k=0;k<4;k++) acc[i][k]=0.f;

        for (int u = 0; u < U_; u++) {
            const float au = aSh[u];
            float s[4];
            #pragma unroll
            for (int i=0;i<4;i++) s[i] = Ssh[(tyy*4+i)*U_ + u];
            #pragma unroll
            for (int k=0;k<4;k++) {
                const float d = Dsh[(tx + 64*k)*65 + u];
                #pragma unroll
                for (int i=0;i<4;i++) {
                    acc[i][k] = fmaf(au, fabsf(s[i] + d), acc[i][k]);
                }
            }
        }
        #pragma unroll
        for (int i=0;i<4;i++) {
            const float sa = saSh[tyy*4+i];
            #pragma unroll
            for (int k=0;k<4;k++) {
                const int ml = tx + 64*k;
                const int m  = mOff + ml;
                if (m < N_)
                    sc[(tyy*4+i)*N_ + m] = 0.6f*(sa + daSh[ml]) + 0.4f*acc[i][k];
            }
        }
    }
    __syncthreads();

    // softmax + fp16 store
    const int warp = tid >> 5, lane = tid & 31;
    #pragma unroll
    for (int rr = 0; rr < 2; rr++) {
        const int r = warp*2 + rr;
        const int n = nBase + r;
        float mx = -1e30f;
        for (int m = lane; m < N_; m += 32) mx = fmaxf(mx, sc[r*N_+m]);
        #pragma unroll
        for (int o=16;o>0;o>>=1) mx = fmaxf(mx, __shfl_xor_sync(0xffffffffu, mx, o));
        float sum = 0.f;
        for (int m = lane; m < N_; m += 32) {
            const float e = __expf(sc[r*N_+m] - mx);
            sc[r*N_+m] = e;
            sum += e;
        }
        #pragma unroll
        for (int o=16;o>0;o>>=1) sum += __shfl_xor_sync(0xffffffffu, sum, o);
        const float inv = 1.f / sum;
        if (n < N_) {
            __half* dH = g_attn + ((size_t)b*N_ + n)*HM_ + (size_t)h*N_;
            for (int m = lane; m < N_; m += 32)
                dH[m] = __float2half_rn(sc[r*N_+m]*inv);
        }
    }
}

// ---------------------------------------------------------------------------
// Kernel C: msg GEMM on tensor cores (plain fp16, K=128 resident).
// (unchanged from R14)
// ---------------------------------------------------------------------------
#define QRS    272                        // smem row stride (17 x 16B, odd units)
#define QAHI   0
#define QWHI   (128*QRS)                  // 34816
#define QSMEM  (QWHI + 256*QRS)           // 104448
#define QCS    257                        // C staging stride (fp32 words, odd)

__global__ __launch_bounds__(512, 1)
void msg_mma(const float* __restrict__ curr)
{
    extern __shared__ __align__(128) char smq[];
    const uint32_t sbase = smem_u32(smq);
    const int tid  = threadIdx.x;
    const int wid  = tid >> 5;
    const int lane = tid & 31;
    const int r0   = blockIdx.x * 128;

    // ---- W: cp.async coalesced from precomputed WT ----
    #pragma unroll
    for (int i = 0; i < 8; i++) {
        const int g = tid + i*512;              // 0..4095
        const int n = g >> 4;
        const int s = g & 15;
        cp16(sbase + QWHI + n*QRS + s*16, g_WT + n*128 + s*8, true);
    }
    cp_commit();

    // ---- A: curr rows -> fp16 smem ----
    #pragma unroll
    for (int i = 0; i < 4; i++) {
        const int g   = tid + i*512;            // 0..2047
        const int row = g >> 4;
        const int s   = g & 15;
        const float* src = curr + (size_t)(r0 + row)*DC_ + s*8;
        float4 v0 = *(const float4*)(src);
        float4 v1 = *(const float4*)(src + 4);
        union { __half x[8]; uint4 v; } ph;
        ph.x[0] = __float2half_rn(v0.x);
        ph.x[1] = __float2half_rn(v0.y);
        ph.x[2] = __float2half_rn(v0.z);
        ph.x[3] = __float2half_rn(v0.w);
        ph.x[4] = __float2half_rn(v1.x);
        ph.x[5] = __float2half_rn(v1.y);
        ph.x[6] = __float2half_rn(v1.z);
        ph.x[7] = __float2half_rn(v1.w);
        *(uint4*)(smq + QAHI + row*QRS + s*16) = ph.v;
    }
    cp_wait<0>();
    __syncthreads();

    // ---- MMA: 16 warps, warp tile 64(m) x 32(n); 8 k16 steps ----
    const int wm = wid & 1;
    const int wn = wid >> 1;
    const uint32_t aRowOff = (lane & 7) + ((lane >> 3) & 1) * 8;
    const uint32_t aSegOff = (lane >> 4) * 16;
    const uint32_t bRowOff = (lane & 7) + (lane >> 4) * 8;
    const uint32_t bSegOff = ((lane >> 3) & 1) * 16;

    float acc[4][4][4] = {};
    const uint32_t sAh = sbase + QAHI;
    const uint32_t sWh = sbase + QWHI;

    #pragma unroll
    for (int k16 = 0; k16 < 8; k16++) {
        const uint32_t kb = k16*32;
        uint32_t bh[2][4];
        #pragma unroll
        for (int p = 0; p < 2; p++) {
            ldsm_x4(bh[p], sWh + (wn*32 + p*16 + bRowOff)*QRS + kb + bSegOff);
        }
        #pragma unroll
        for (int mt = 0; mt < 4; mt++) {
            uint32_t a[4];
            ldsm_x4(a, sAh + (wm*64 + mt*16 + aRowOff)*QRS + kb + aSegOff);
            #pragma unroll
            for (int nt = 0; nt < 4; nt++) {
                mma16816h(acc[mt][nt], a, &bh[nt >> 1][(nt & 1)*2]);
            }
        }
    }

    // ---- Epilogue: two 64-row passes ----
    float* Cs = (float*)smq;
    const int lr0 = (lane >> 2);
    const int cc0 = wn*32 + (lane & 3)*2;

    #pragma unroll
    for (int pass = 0; pass < 2; pass++) {
        __syncthreads();
        if (wm == pass) {
            #pragma unroll
            for (int mt = 0; mt < 4; mt++) {
                #pragma unroll
                for (int half = 0; half < 2; half++) {
                    const int r = lr0 + mt*16 + half*8;
                    #pragma unroll
                    for (int nt = 0; nt < 4; nt++) {
                        Cs[r*QCS + cc0 + nt*8]     = acc[mt][nt][half*2+0];
                        Cs[r*QCS + cc0 + nt*8 + 1] = acc[mt][nt][half*2+1];
                    }
                }
            }
        }
        __syncthreads();

        #pragma unroll
        for (int i = 0; i < 8; i++) {
            const int g  = tid + i*512;
            const int mq = g & 15;
            const int c  = g >> 4;
            const int rloc = mq*4;
            const int rg = r0 + pass*64 + rloc;
            const int bb  = rg / (T_*N_);
            const int rem = rg - bb*(T_*N_);
            const int t   = rem / N_;
            const int m   = rem - t*N_;
            const int h   = c >> 6;
            const int u   = c & 63;
            union { __half x[4]; uint2 v; } p;
            #pragma unroll
            for (int j = 0; j < 4; j++)
                p.x[j] = __float2half_rn(Cs[(rloc + j)*QCS + c]);
            const size_t off = ((size_t)bb*TU_ + t*U_ + u)*HM_ + (size_t)h*N_ + m;
            *(uint2*)&g_msgT[off] = p.v;
        }
    }
}

// ---------------------------------------------------------------------------
// Kernel D: mix GEMM via mma.sync (single fp16 A and B), 2 CTAs/SM.
// KC=64 chunks, 3-stage cp.async pipeline.  (unchanged from R16)
// ---------------------------------------------------------------------------
#define MIX_KC    64
#define MIX_NCH   32          // ceil(2000/64) -> covers k<2048, zero-filled
#define MRS       144         // smem row stride bytes (128B data + 16B pad)
#define MTILE     18432       // 128 rows * 144B
#define MSTAGE    (2*MTILE)   // A, B = 36864
#define MNSTG     3
#define MSM_TOTAL (MNSTG*MSTAGE)  // 110592

__device__ __forceinline__ void mix_load_chunk(
    uint32_t sstage, int kc, int tid, int b, int mBase, int nBase)
{
    const __half* Am = g_attn + (size_t)b * N_ * HM_;
    const __half* Bm = g_msgT + (size_t)b * TU_ * HM_;
    #pragma unroll
    for (int i = 0; i < 8; i++) {
        const int g    = tid + i*256;       // 0..2047
        const int tile = g >> 10;           // 0:A 1:B
        const int rem  = g & 1023;
        const int row  = rem >> 3;
        const int seg  = rem & 7;
        const int k    = kc + seg*8;
        const uint32_t dst = sstage + tile*MTILE + row*MRS + seg*16;
        if (tile == 0) {
            const int n = mBase + row;
            const bool ok = (n < N_) && (k < HM_);
            cp16(dst, Am + (ok ? ((size_t)n*HM_ + k) : 0), ok);
        } else {
            const bool ok = (k < HM_);
            cp16(dst, Bm + (ok ? ((size_t)(nBase + row)*HM_ + k) : 0), ok);
        }
    }
    cp_commit();
}

__global__ __launch_bounds__(256, 2)
void mix_mma(float* __restrict__ out)
{
    extern __shared__ __align__(128) char smx[];
    const uint32_t sbase = smem_u32(smx);
    const int tid  = threadIdx.x;
    const int wid  = tid >> 5;
    const int lane = tid & 31;
    const int b     = blockIdx.z;
    const int mBase = blockIdx.x * 128;
    const int nBase = blockIdx.y * 128;

    const int wm = wid & 1;
    const int wn = wid >> 1;

    const uint32_t aRowOff = (lane & 7) + ((lane >> 3) & 1) * 8;
    const uint32_t aSegOff = (lane >> 4) * 16;
    const uint32_t bRowOff = (lane & 7) + (lane >> 4) * 8;
    const uint32_t bSegOff = ((lane >> 3) & 1) * 16;

    float acc[4][4][4] = {};

    mix_load_chunk(sbase + 0*MSTAGE, 0*MIX_KC, tid, b, mBase, nBase);
    mix_load_chunk(sbase + 1*MSTAGE, 1*MIX_KC, tid, b, mBase, nBase);

    int sc = 0;
    for (int c = 0; c < MIX_NCH; c++) {
        if (c + 2 < MIX_NCH) {
            const int ns = (sc + 2 >= MNSTG) ? sc + 2 - MNSTG : sc + 2;
            mix_load_chunk(sbase + ns*MSTAGE, (c+2)*MIX_KC, tid, b, mBase, nBase);
            cp_wait<2>();
        } else if (c + 1 < MIX_NCH) {
            cp_wait<1>();
        } else {
            cp_wait<0>();
        }
        __syncthreads();

        const uint32_t sA = sbase + sc*MSTAGE;
        const uint32_t sB = sA + MTILE;

        #pragma unroll
        for (int k16 = 0; k16 < 4; k16++) {
            const uint32_t kb = k16*32;
            uint32_t bb[2][4];
            #pragma unroll
            for (int p = 0; p < 2; p++) {
                ldsm_x4(bb[p], sB + (wn*32 + p*16 + bRowOff)*MRS + kb + bSegOff);
            }
            #pragma unroll
            for (int mt = 0; mt < 4; mt++) {
                uint32_t a[4];
                ldsm_x4(a, sA + (wm*64 + mt*16 + aRowOff)*MRS + kb + aSegOff);
                #pragma unroll
                for (int nt = 0; nt < 4; nt++) {
                    mma16816h(acc[mt][nt], a, &bb[nt >> 1][(nt & 1)*2]);
                }
            }
        }
        __syncthreads();
        sc = (sc + 1 >= MNSTG) ? 0 : sc + 1;
    }

    // Epilogue
    const int r0 = mBase + wm*64 + (lane >> 2);
    const int c0 = nBase + wn*32 + (lane & 3)*2;
    #pragma unroll
    for (int mt = 0; mt < 4; mt++) {
        #pragma unroll
        for (int half = 0; half < 2; half++) {
            const int n = r0 + mt*16 + half*8;
            if (n < N_) {
                #pragma unroll
                for (int nt = 0; nt < 4; nt++) {
                    const int cc = c0 + nt*8;
                    const int t  = cc >> 6;
                    const int u  = cc & 63;
                    float2 v = make_float2(acc[mt][nt][half*2+0]*0.25f,
                                           acc[mt][nt][half*2+1]*0.25f);
                    *(float2*)&out[(((size_t)b*T_ + t)*N_ + n)*U_ + u] = v;
                }
            }
        }
    }
}

// ---------------------------------------------------------------------------
extern "C" void kernel_launch(void* const* d_in, const int* in_sizes, int n_in,
                              void* d_out, int out_size)
{
    const float* prev = (const float*)d_in[0];   // [8,500,200]
    const float* curr = (const float*)d_in[1];   // [8,32,500,128]
    const float* Wsrc = (const float*)d_in[2];   // [4,200,64]
    const float* Wdst = (const float*)d_in[3];   // [4,200,64]
    const float* aV   = (const float*)d_in[4];   // [4,64,1]
    const float* Wmsg = (const float*)d_in[5];   // [4,128,64]
    float* out = (float*)d_out;                  // [8,32,500,64]

    // W: Wmsg transpose (once per launch; stream-ordered before msg_mma)
    wprep<<<16, 256>>>(Wmsg);

    // A: projections  (M=4000, N=512, K=200)
    proj_gemm<<<dim3(32, 4), 256>>>(prev, Wsrc, Wdst);

    // B: scores + softmax -> single fp16 attn (two 256-m passes, 2 CTAs/SM)
    const size_t shB = (size_t)(SMH*65 + 16*64 + 128 + 16*500 + SMH + 16 + 16) * sizeof(float);
    cudaFuncSetAttribute(score_softmax_kernel,
                         cudaFuncAttributeMaxDynamicSharedMemorySize, (int)shB);
    score_softmax_kernel<<<dim3(32, 32), 256, shB>>>(aV);

    // C: msg GEMM on tensor cores (plain fp16) -> transposed msgT
    cudaFuncSetAttribute(msg_mma,
                         cudaFuncAttributeMaxDynamicSharedMemorySize, QSMEM);
    msg_mma<<<1000, 512, QSMEM>>>(curr);

    // D: mix GEMM on tensor cores (per batch: M=500, N=2048, K=2000), 2 CTAs/SM
    cudaFuncSetAttribute(mix_mma,
                         cudaFuncAttributeMaxDynamicSharedMemorySize, MSM_TOTAL);
    mix_mma<<<dim3(4, 16, 8), 256, MSM_TOTAL>>>(out);
}